// round 1
// baseline (speedup 1.0000x reference)
#include <cuda_runtime.h>
#include <math.h>

#define Tn 512
#define Dn 2048
#define Hn 32
#define KVn 8
#define DHn 64
#define In 7168
#define En 8
#define QKVn 3072   // (H + 2*KV) * DH

// ---------------- scratch (device globals; no allocation allowed) ----------------
__device__ __align__(16) float g_res1[Tn * Dn];
__device__ __align__(16) float g_x[Tn * Dn];
__device__ __align__(16) float g_qkv[Tn * QKVn];
__device__ __align__(16) float g_scores[Hn * Tn * Tn];
__device__ __align__(16) float g_attn[Tn * Dn];
__device__ __align__(16) float g_x2[Tn * Dn];
__device__ __align__(16) float g_h1[En * Tn * In];
__device__ __align__(16) float g_h3[En * Tn * In];
__device__ __align__(16) float g_eo[Tn * 2 * Dn];
__device__ int   g_tok[En * Tn];
__device__ float g_wgt[En * Tn];
__device__ int   g_slot[En * Tn];
__device__ int   g_cnt[En];

// ---------------- small utility kernels ----------------

__global__ void k_zero_cnt() {
    if (threadIdx.x < En) g_cnt[threadIdx.x] = 0;
}

// res1 = h + r;  x = rmsnorm(res1, w)
__global__ void k_add_rmsnorm(const float* __restrict__ h, const float* __restrict__ r,
                              const float* __restrict__ w) {
    int t = blockIdx.x;
    const float* hr = h + t * Dn;
    const float* rr = r + t * Dn;
    float* resr = g_res1 + t * Dn;
    float* xr = g_x + t * Dn;

    float v[8];
    float local = 0.f;
#pragma unroll
    for (int j = 0; j < 8; j++) {
        int c = threadIdx.x + j * 256;
        float s = hr[c] + rr[c];
        v[j] = s;
        resr[c] = s;
        local += s * s;
    }
#pragma unroll
    for (int o = 16; o > 0; o >>= 1) local += __shfl_xor_sync(0xffffffffu, local, o);
    __shared__ float red[8];
    if ((threadIdx.x & 31) == 0) red[threadIdx.x >> 5] = local;
    __syncthreads();
    __shared__ float inv;
    if (threadIdx.x == 0) {
        float s = 0.f;
#pragma unroll
        for (int i = 0; i < 8; i++) s += red[i];
        inv = rsqrtf(s / (float)Dn + 1e-5f);
    }
    __syncthreads();
    float iv = inv;
#pragma unroll
    for (int j = 0; j < 8; j++) {
        int c = threadIdx.x + j * 256;
        xr[c] = v[j] * iv * w[c];
    }
}

// x2 = rmsnorm(in, w)
__global__ void k_rmsnorm(const float* __restrict__ in, const float* __restrict__ w) {
    int t = blockIdx.x;
    const float* ir = in + t * Dn;
    float* xr = g_x2 + t * Dn;
    float v[8];
    float local = 0.f;
#pragma unroll
    for (int j = 0; j < 8; j++) {
        int c = threadIdx.x + j * 256;
        float s = ir[c];
        v[j] = s;
        local += s * s;
    }
#pragma unroll
    for (int o = 16; o > 0; o >>= 1) local += __shfl_xor_sync(0xffffffffu, local, o);
    __shared__ float red[8];
    if ((threadIdx.x & 31) == 0) red[threadIdx.x >> 5] = local;
    __syncthreads();
    __shared__ float inv;
    if (threadIdx.x == 0) {
        float s = 0.f;
#pragma unroll
        for (int i = 0; i < 8; i++) s += red[i];
        inv = rsqrtf(s / (float)Dn + 1e-5f);
    }
    __syncthreads();
    float iv = inv;
#pragma unroll
    for (int j = 0; j < 8; j++) {
        int c = threadIdx.x + j * 256;
        xr[c] = v[j] * iv * w[c];
    }
}

// ---------------- generic SGEMM: C[M,N] = A[M,K] * B[N,K]^T (+ addend) ----------------
// 128x128 tile, BK=8, 256 threads, 8x8 per thread.
__global__ void k_sgemm_nt(const float* __restrict__ A, const float* __restrict__ B,
                           float* __restrict__ C, const float* __restrict__ addend,
                           int M, int N, int K) {
    __shared__ float As[8][128];
    __shared__ float Bs[8][128];
    const int bm = blockIdx.y * 128;
    const int bn = blockIdx.x * 128;
    const int tid = threadIdx.x;
    const int lr = tid >> 1;
    const int lc = (tid & 1) * 4;
    const int tx = tid & 15;
    const int ty = tid >> 4;

    float acc[8][8];
#pragma unroll
    for (int i = 0; i < 8; i++)
#pragma unroll
        for (int j = 0; j < 8; j++) acc[i][j] = 0.f;

    int arow = bm + lr; if (arow >= M) arow = M - 1;  // safe address (result unused)
    const float* Aptr = A + (size_t)arow * K + lc;
    const float* Bptr = B + (size_t)(bn + lr) * K + lc;

    for (int k0 = 0; k0 < K; k0 += 8) {
        float4 a4 = *(const float4*)(Aptr + k0);
        float4 b4 = *(const float4*)(Bptr + k0);
        As[lc + 0][lr] = a4.x; As[lc + 1][lr] = a4.y; As[lc + 2][lr] = a4.z; As[lc + 3][lr] = a4.w;
        Bs[lc + 0][lr] = b4.x; Bs[lc + 1][lr] = b4.y; Bs[lc + 2][lr] = b4.z; Bs[lc + 3][lr] = b4.w;
        __syncthreads();
#pragma unroll
        for (int kk = 0; kk < 8; kk++) {
            float4 ra0 = *(const float4*)&As[kk][ty * 8];
            float4 ra1 = *(const float4*)&As[kk][ty * 8 + 4];
            float4 rb0 = *(const float4*)&Bs[kk][tx * 8];
            float4 rb1 = *(const float4*)&Bs[kk][tx * 8 + 4];
            float ra[8] = {ra0.x, ra0.y, ra0.z, ra0.w, ra1.x, ra1.y, ra1.z, ra1.w};
            float rb[8] = {rb0.x, rb0.y, rb0.z, rb0.w, rb1.x, rb1.y, rb1.z, rb1.w};
#pragma unroll
            for (int i = 0; i < 8; i++)
#pragma unroll
                for (int j = 0; j < 8; j++) acc[i][j] += ra[i] * rb[j];
        }
        __syncthreads();
    }

#pragma unroll
    for (int i = 0; i < 8; i++) {
        int row = bm + ty * 8 + i;
        if (row >= M) continue;
        float* crow = C + (size_t)row * N + bn + tx * 8;
        float4 v0 = make_float4(acc[i][0], acc[i][1], acc[i][2], acc[i][3]);
        float4 v1 = make_float4(acc[i][4], acc[i][5], acc[i][6], acc[i][7]);
        if (addend) {
            const float* arow2 = addend + (size_t)row * N + bn + tx * 8;
            float4 d0 = *(const float4*)arow2;
            float4 d1 = *(const float4*)(arow2 + 4);
            v0.x += d0.x; v0.y += d0.y; v0.z += d0.z; v0.w += d0.w;
            v1.x += d1.x; v1.y += d1.y; v1.z += d1.z; v1.w += d1.w;
        }
        *(float4*)crow = v0;
        *(float4*)(crow + 4) = v1;
    }
}

// ---------------- RoPE on q (heads 0..31) and k (heads 32..39) ----------------
__global__ void k_rope(const float* __restrict__ cosb, const float* __restrict__ sinb) {
    int idx = blockIdx.x * 256 + threadIdx.x;
    if (idx >= Tn * 40 * 32) return;
    int d = idx & 31;
    int rest = idx >> 5;
    int hh = rest % 40;
    int t = rest / 40;
    float c = cosb[t * 32 + d];
    float s = sinb[t * 32 + d];
    float* base = g_qkv + (size_t)t * QKVn + hh * 64 + d;
    float x1 = base[0];
    float x2 = base[32];
    base[0] = x1 * c - x2 * s;
    base[32] = x2 * c + x1 * s;
}

// ---------------- attention: scores ----------------
__global__ void k_scores() {
    const int kt = blockIdx.x, qt = blockIdx.y, h = blockIdx.z;
    const int tid = threadIdx.x;
    const int tx = tid & 15, ty = tid >> 4;

    if (kt > qt) {
        // fully masked tile
#pragma unroll
        for (int i = 0; i < 4; i++)
#pragma unroll
            for (int j = 0; j < 4; j++) {
                int q = qt * 64 + ty * 4 + i;
                int k = kt * 64 + tx * 4 + j;
                g_scores[((size_t)h * Tn + q) * Tn + k] = -1e30f;
            }
        return;
    }

    __shared__ float Qs[64][65];
    __shared__ float Ks[64][65];
    const int lr = tid >> 2;
    const int lc = (tid & 3) * 16;
    const int kvh = h >> 2;
#pragma unroll
    for (int ch = 0; ch < 4; ch++) {
        float4 qv = *(const float4*)(g_qkv + (size_t)(qt * 64 + lr) * QKVn + h * 64 + lc + ch * 4);
        Qs[lr][lc + ch * 4 + 0] = qv.x; Qs[lr][lc + ch * 4 + 1] = qv.y;
        Qs[lr][lc + ch * 4 + 2] = qv.z; Qs[lr][lc + ch * 4 + 3] = qv.w;
        float4 kv = *(const float4*)(g_qkv + (size_t)(kt * 64 + lr) * QKVn + 2048 + kvh * 64 + lc + ch * 4);
        Ks[lr][lc + ch * 4 + 0] = kv.x; Ks[lr][lc + ch * 4 + 1] = kv.y;
        Ks[lr][lc + ch * 4 + 2] = kv.z; Ks[lr][lc + ch * 4 + 3] = kv.w;
    }
    __syncthreads();

    float acc[4][4];
#pragma unroll
    for (int i = 0; i < 4; i++)
#pragma unroll
        for (int j = 0; j < 4; j++) acc[i][j] = 0.f;

#pragma unroll 8
    for (int kk = 0; kk < 64; kk++) {
        float ra[4], rb[4];
#pragma unroll
        for (int i = 0; i < 4; i++) ra[i] = Qs[ty * 4 + i][kk];
#pragma unroll
        for (int j = 0; j < 4; j++) rb[j] = Ks[tx * 4 + j][kk];
#pragma unroll
        for (int i = 0; i < 4; i++)
#pragma unroll
            for (int j = 0; j < 4; j++) acc[i][j] += ra[i] * rb[j];
    }

    const float scale = 0.125f;  // DH^-0.5
#pragma unroll
    for (int i = 0; i < 4; i++)
#pragma unroll
        for (int j = 0; j < 4; j++) {
            int q = qt * 64 + ty * 4 + i;
            int k = kt * 64 + tx * 4 + j;
            float v = (k <= q) ? acc[i][j] * scale : -1e30f;
            g_scores[((size_t)h * Tn + q) * Tn + k] = v;
        }
}

// ---------------- attention: softmax over k (512) ----------------
__global__ void k_softmax() {
    const int row = blockIdx.x;  // h*Tn + q
    float* p = g_scores + (size_t)row * Tn;
    const int tid = threadIdx.x;  // 128
    float v[4];
    float mx = -3.4e38f;
#pragma unroll
    for (int j = 0; j < 4; j++) {
        v[j] = p[tid + j * 128];
        mx = fmaxf(mx, v[j]);
    }
#pragma unroll
    for (int o = 16; o > 0; o >>= 1) mx = fmaxf(mx, __shfl_xor_sync(0xffffffffu, mx, o));
    __shared__ float rm[4];
    if ((tid & 31) == 0) rm[tid >> 5] = mx;
    __syncthreads();
    mx = fmaxf(fmaxf(rm[0], rm[1]), fmaxf(rm[2], rm[3]));
    float sum = 0.f;
#pragma unroll
    for (int j = 0; j < 4; j++) {
        v[j] = __expf(v[j] - mx);
        sum += v[j];
    }
#pragma unroll
    for (int o = 16; o > 0; o >>= 1) sum += __shfl_xor_sync(0xffffffffu, sum, o);
    __shared__ float rs[4];
    if ((tid & 31) == 0) rs[tid >> 5] = sum;
    __syncthreads();
    sum = rs[0] + rs[1] + rs[2] + rs[3];
    float inv = 1.f / sum;
#pragma unroll
    for (int j = 0; j < 4; j++) p[tid + j * 128] = v[j] * inv;
}

// ---------------- attention: out = probs @ V ----------------
__global__ void k_attnv() {
    const int qt = blockIdx.x, h = blockIdx.y;
    const int tid = threadIdx.x;
    const int tx = tid & 15, ty = tid >> 4;
    const int lr = tid >> 2;
    const int lc = (tid & 3) * 16;
    const int kvh = h >> 2;

    __shared__ float Ps[64][65];
    __shared__ float Vs[64][65];
    float acc[4][4];
#pragma unroll
    for (int i = 0; i < 4; i++)
#pragma unroll
        for (int j = 0; j < 4; j++) acc[i][j] = 0.f;

    for (int kt = 0; kt <= qt; kt++) {
#pragma unroll
        for (int ch = 0; ch < 4; ch++) {
            float4 pv = *(const float4*)(g_scores + ((size_t)h * Tn + qt * 64 + lr) * Tn + kt * 64 + lc + ch * 4);
            Ps[lr][lc + ch * 4 + 0] = pv.x; Ps[lr][lc + ch * 4 + 1] = pv.y;
            Ps[lr][lc + ch * 4 + 2] = pv.z; Ps[lr][lc + ch * 4 + 3] = pv.w;
            float4 vv = *(const float4*)(g_qkv + (size_t)(kt * 64 + lr) * QKVn + 2560 + kvh * 64 + lc + ch * 4);
            Vs[lr][lc + ch * 4 + 0] = vv.x; Vs[lr][lc + ch * 4 + 1] = vv.y;
            Vs[lr][lc + ch * 4 + 2] = vv.z; Vs[lr][lc + ch * 4 + 3] = vv.w;
        }
        __syncthreads();
#pragma unroll 8
        for (int kk = 0; kk < 64; kk++) {
            float ra[4], rb[4];
#pragma unroll
            for (int i = 0; i < 4; i++) ra[i] = Ps[ty * 4 + i][kk];
#pragma unroll
            for (int j = 0; j < 4; j++) rb[j] = Vs[kk][tx * 4 + j];
#pragma unroll
            for (int i = 0; i < 4; i++)
#pragma unroll
                for (int j = 0; j < 4; j++) acc[i][j] += ra[i] * rb[j];
        }
        __syncthreads();
    }

#pragma unroll
    for (int i = 0; i < 4; i++)
#pragma unroll
        for (int j = 0; j < 4; j++) {
            int q = qt * 64 + ty * 4 + i;
            g_attn[(size_t)q * Dn + h * 64 + tx * 4 + j] = acc[i][j];
        }
}

// ---------------- gate: logits -> top-2 -> bucket routing ----------------
__global__ void k_gate(const float* __restrict__ gw) {
    const int t = blockIdx.x;
    const int warp = threadIdx.x >> 5, lane = threadIdx.x & 31;
    const float* xr = g_x2 + (size_t)t * Dn;
    const float* wr = gw + (size_t)warp * Dn;
    float s = 0.f;
    for (int c = lane; c < Dn; c += 32) s += xr[c] * wr[c];
#pragma unroll
    for (int o = 16; o > 0; o >>= 1) s += __shfl_xor_sync(0xffffffffu, s, o);
    __shared__ float lg[En];
    if (lane == 0) lg[warp] = s;
    __syncthreads();
    if (threadIdx.x == 0) {
        int i0 = 0;
        for (int e = 1; e < En; e++) if (lg[e] > lg[i0]) i0 = e;
        int i1 = (i0 == 0) ? 1 : 0;
        for (int e = 0; e < En; e++) if (e != i0 && lg[e] > lg[i1]) i1 = e;
        float w1v = __expf(lg[i1] - lg[i0]);
        float inv = 1.f / (1.f + w1v);
        float w0 = inv, w1n = w1v * inv;
        int p0 = atomicAdd(&g_cnt[i0], 1);
        g_tok[i0 * Tn + p0] = t; g_wgt[i0 * Tn + p0] = w0; g_slot[i0 * Tn + p0] = 0;
        int p1 = atomicAdd(&g_cnt[i1], 1);
        g_tok[i1 * Tn + p1] = t; g_wgt[i1 * Tn + p1] = w1n; g_slot[i1 * Tn + p1] = 1;
    }
}

// ---------------- grouped MoE GEMM1: H[e-bucket rows, I] = x2_gathered @ W[e]^T ----------------
__global__ void k_moe_gemm1(const float* __restrict__ W, float* __restrict__ Hout) {
    const int e = blockIdx.z;
    const int cnt = g_cnt[e];
    const int bm = blockIdx.y * 128;
    if (bm >= cnt) return;
    const int bn = blockIdx.x * 128;
    const int tid = threadIdx.x;
    const int lr = tid >> 1;
    const int lc = (tid & 1) * 4;
    const int tx = tid & 15, ty = tid >> 4;

    int arow = bm + lr;
    int trow = (arow < cnt) ? g_tok[e * Tn + arow] : 0;
    const float* Aptr = g_x2 + (size_t)trow * Dn + lc;
    const float* Bptr = W + (size_t)e * In * Dn + (size_t)(bn + lr) * Dn + lc;

    __shared__ float As[8][128];
    __shared__ float Bs[8][128];
    float acc[8][8];
#pragma unroll
    for (int i = 0; i < 8; i++)
#pragma unroll
        for (int j = 0; j < 8; j++) acc[i][j] = 0.f;

    for (int k0 = 0; k0 < Dn; k0 += 8) {
        float4 a4 = *(const float4*)(Aptr + k0);
        float4 b4 = *(const float4*)(Bptr + k0);
        As[lc + 0][lr] = a4.x; As[lc + 1][lr] = a4.y; As[lc + 2][lr] = a4.z; As[lc + 3][lr] = a4.w;
        Bs[lc + 0][lr] = b4.x; Bs[lc + 1][lr] = b4.y; Bs[lc + 2][lr] = b4.z; Bs[lc + 3][lr] = b4.w;
        __syncthreads();
#pragma unroll
        for (int kk = 0; kk < 8; kk++) {
            float4 ra0 = *(const float4*)&As[kk][ty * 8];
            float4 ra1 = *(const float4*)&As[kk][ty * 8 + 4];
            float4 rb0 = *(const float4*)&Bs[kk][tx * 8];
            float4 rb1 = *(const float4*)&Bs[kk][tx * 8 + 4];
            float ra[8] = {ra0.x, ra0.y, ra0.z, ra0.w, ra1.x, ra1.y, ra1.z, ra1.w};
            float rb[8] = {rb0.x, rb0.y, rb0.z, rb0.w, rb1.x, rb1.y, rb1.z, rb1.w};
#pragma unroll
            for (int i = 0; i < 8; i++)
#pragma unroll
                for (int j = 0; j < 8; j++) acc[i][j] += ra[i] * rb[j];
        }
        __syncthreads();
    }

#pragma unroll
    for (int i = 0; i < 8; i++) {
        int r = bm + ty * 8 + i;
        if (r >= cnt) continue;
        float* crow = Hout + ((size_t)e * Tn + r) * In + bn + tx * 8;
        *(float4*)crow = make_float4(acc[i][0], acc[i][1], acc[i][2], acc[i][3]);
        *(float4*)(crow + 4) = make_float4(acc[i][4], acc[i][5], acc[i][6], acc[i][7]);
    }
}

// ---------------- act: h1 = silu(h1) * h3 ----------------
__global__ void k_act() {
    const int e = blockIdx.y >> 9;
    const int pos = blockIdx.y & 511;
    if (pos >= g_cnt[e]) return;
    const int col = blockIdx.x * 256 + threadIdx.x;
    const size_t idx = (size_t)blockIdx.y * In + col;
    float a = g_h1[idx];
    float b = g_h3[idx];
    g_h1[idx] = (a / (1.f + __expf(-a))) * b;
}

// ---------------- grouped MoE GEMM2: eo[(t,slot)] = wgt * (act @ w2[e]^T) ----------------
__global__ void k_moe_gemm2(const float* __restrict__ W2) {
    const int e = blockIdx.z;
    const int cnt = g_cnt[e];
    const int bm = blockIdx.y * 128;
    if (bm >= cnt) return;
    const int bn = blockIdx.x * 128;
    const int tid = threadIdx.x;
    const int lr = tid >> 1;
    const int lc = (tid & 1) * 4;
    const int tx = tid & 15, ty = tid >> 4;

    const float* Aptr = g_h1 + ((size_t)e * Tn + bm + lr) * In + lc;
    const float* Bptr = W2 + (size_t)e * Dn * In + (size_t)(bn + lr) * In + lc;

    __shared__ float As[8][128];
    __shared__ float Bs[8][128];
    float acc[8][8];
#pragma unroll
    for (int i = 0; i < 8; i++)
#pragma unroll
        for (int j = 0; j < 8; j++) acc[i][j] = 0.f;

    for (int k0 = 0; k0 < In; k0 += 8) {
        float4 a4 = *(const float4*)(Aptr + k0);
        float4 b4 = *(const float4*)(Bptr + k0);
        As[lc + 0][lr] = a4.x; As[lc + 1][lr] = a4.y; As[lc + 2][lr] = a4.z; As[lc + 3][lr] = a4.w;
        Bs[lc + 0][lr] = b4.x; Bs[lc + 1][lr] = b4.y; Bs[lc + 2][lr] = b4.z; Bs[lc + 3][lr] = b4.w;
        __syncthreads();
#pragma unroll
        for (int kk = 0; kk < 8; kk++) {
            float4 ra0 = *(const float4*)&As[kk][ty * 8];
            float4 ra1 = *(const float4*)&As[kk][ty * 8 + 4];
            float4 rb0 = *(const float4*)&Bs[kk][tx * 8];
            float4 rb1 = *(const float4*)&Bs[kk][tx * 8 + 4];
            float ra[8] = {ra0.x, ra0.y, ra0.z, ra0.w, ra1.x, ra1.y, ra1.z, ra1.w};
            float rb[8] = {rb0.x, rb0.y, rb0.z, rb0.w, rb1.x, rb1.y, rb1.z, rb1.w};
#pragma unroll
            for (int i = 0; i < 8; i++)
#pragma unroll
                for (int j = 0; j < 8; j++) acc[i][j] += ra[i] * rb[j];
        }
        __syncthreads();
    }

#pragma unroll
    for (int i = 0; i < 8; i++) {
        int r = bm + ty * 8 + i;
        if (r >= cnt) continue;
        int idx = e * Tn + r;
        int t = g_tok[idx];
        float wg = g_wgt[idx];
        int sl = g_slot[idx];
        float* orow = g_eo + ((size_t)t * 2 + sl) * Dn + bn + tx * 8;
        *(float4*)orow = make_float4(wg * acc[i][0], wg * acc[i][1], wg * acc[i][2], wg * acc[i][3]);
        *(float4*)(orow + 4) = make_float4(wg * acc[i][4], wg * acc[i][5], wg * acc[i][6], wg * acc[i][7]);
    }
}

// ---------------- combine: moe_out = eo[slot0] + eo[slot1] ----------------
__global__ void k_combine(float* __restrict__ out) {
    int i = blockIdx.x * 256 + threadIdx.x;
    if (i >= Tn * Dn) return;
    int t = i / Dn;
    out[i] = g_eo[(size_t)i + (size_t)t * Dn] + g_eo[(size_t)i + (size_t)t * Dn + Dn];
}

// ---------------- launch ----------------
extern "C" void kernel_launch(void* const* d_in, const int* in_sizes, int n_in,
                              void* d_out, int out_size) {
    const float* hs   = (const float*)d_in[0];
    const float* resi = (const float*)d_in[1];
    const float* cosb = (const float*)d_in[2];
    const float* sinb = (const float*)d_in[3];
    const float* ln1  = (const float*)d_in[4];
    const float* ln2  = (const float*)d_in[5];
    const float* wqkv = (const float*)d_in[6];
    const float* wo   = (const float*)d_in[7];
    const float* gw   = (const float*)d_in[8];
    const float* w1   = (const float*)d_in[9];
    const float* w3   = (const float*)d_in[10];
    const float* w2   = (const float*)d_in[11];

    float* out = (float*)d_out;
    float* moe_out = out;
    float* res2 = out + Tn * Dn;

    void *px, *pqkv, *pattn, *pres1, *ph1, *ph3;
    cudaGetSymbolAddress(&px, g_x);
    cudaGetSymbolAddress(&pqkv, g_qkv);
    cudaGetSymbolAddress(&pattn, g_attn);
    cudaGetSymbolAddress(&pres1, g_res1);
    cudaGetSymbolAddress(&ph1, g_h1);
    cudaGetSymbolAddress(&ph3, g_h3);

    k_zero_cnt<<<1, 32>>>();
    k_add_rmsnorm<<<Tn, 256>>>(hs, resi, ln1);

    // qkv = x @ wqkv^T    [512,3072] = [512,2048] x [3072,2048]^T
    k_sgemm_nt<<<dim3(QKVn / 128, Tn / 128), 256>>>((const float*)px, wqkv,
                                                    (float*)pqkv, nullptr, Tn, QKVn, Dn);
    k_rope<<<(Tn * 40 * 32) / 256, 256>>>(cosb, sinb);

    k_scores<<<dim3(Tn / 64, Tn / 64, Hn), 256>>>();
    k_softmax<<<Hn * Tn, 128>>>();
    k_attnv<<<dim3(Tn / 64, Hn), 256>>>();

    // res2 = attn @ wo^T + res1   (written straight into d_out second half)
    k_sgemm_nt<<<dim3(Dn / 128, Tn / 128), 256>>>((const float*)pattn, wo,
                                                  res2, (const float*)pres1, Tn, Dn, Dn);
    k_rmsnorm<<<Tn, 256>>>(res2, ln2);
    k_gate<<<Tn, 256>>>(gw);

    k_moe_gemm1<<<dim3(In / 128, Tn / 128, En), 256>>>(w1, (float*)ph1);
    k_moe_gemm1<<<dim3(In / 128, Tn / 128, En), 256>>>(w3, (float*)ph3);
    k_act<<<dim3(In / 256, En * Tn), 256>>>();
    k_moe_gemm2<<<dim3(Dn / 128, Tn / 128, En), 256>>>(w2);
    k_combine<<<(Tn * Dn) / 256, 256>>>(moe_out);
}

// round 3
// speedup vs baseline: 3.2173x; 3.2173x over previous
#include <cuda_runtime.h>
#include <math.h>
#include <stdint.h>

#define Tn 512
#define Dn 2048
#define Hn 32
#define KVn 8
#define DHn 64
#define In 7168
#define En 8
#define QKVn 3072   // (H + 2*KV) * DH
#define PAD 36      // smem row stride in 32-bit words

// ---------------- scratch (device globals; no allocation allowed) ----------------
__device__ __align__(16) float g_res1[Tn * Dn];
__device__ __align__(16) float g_x[Tn * Dn];
__device__ __align__(16) float g_qkv[Tn * QKVn];
__device__ __align__(16) float g_scores[Hn * Tn * Tn];
__device__ __align__(16) float g_attn[Tn * Dn];
__device__ __align__(16) float g_x2[Tn * Dn];
__device__ __align__(16) float g_h1[En * Tn * In];
__device__ __align__(16) float g_h3[En * Tn * In];
__device__ __align__(16) float g_eo[Tn * 2 * Dn];
__device__ int   g_tok[En * Tn];
__device__ float g_wgt[En * Tn];
__device__ int   g_slot[En * Tn];
__device__ int   g_cnt[En];

// ================= mma.sync tf32 helpers (sm_80+ features only) =================
__device__ __forceinline__ uint32_t tf32_rna(float x) {
    uint32_t r; asm("cvt.rna.tf32.f32 %0, %1;" : "=r"(r) : "f"(x)); return r;
}
__device__ __forceinline__ void mma_tf32(float* c, const uint32_t* a, const uint32_t* b) {
    asm volatile(
        "mma.sync.aligned.m16n8k8.row.col.f32.tf32.tf32.f32 "
        "{%0,%1,%2,%3}, {%4,%5,%6,%7}, {%8,%9}, {%0,%1,%2,%3};"
        : "+f"(c[0]), "+f"(c[1]), "+f"(c[2]), "+f"(c[3])
        : "r"(a[0]), "r"(a[1]), "r"(a[2]), "r"(a[3]), "r"(b[0]), "r"(b[1]));
}

// ================= tf32 tensor-core GEMM: C[M,N] = A[M,K] * B[N,K]^T =================
// MODE 0: plain (+ optional addend). MODE 1: MoE gemm1 (row gather via g_tok).
// MODE 2: MoE gemm2 (weighted scatter to g_eo).
// Tile 128x128, BK=32, 256 threads (2x4 warps of 64x32), double-buffered SMEM.
#define GEMM_SMEM_BYTES (4 * 128 * PAD * 4)

template <int MODE>
__global__ void __launch_bounds__(256, 1) k_gemm_mma(const float* __restrict__ A,
                                                     const float* __restrict__ B,
                                                     float* __restrict__ C,
                                                     const float* __restrict__ ADD,
                                                     int M, int N, int K) {
    const int e = (MODE == 0) ? 0 : blockIdx.z;
    const int cnt = (MODE == 0) ? M : g_cnt[e];
    const int bm = blockIdx.y * 128;
    if (bm >= cnt) return;
    const int bn = blockIdx.x * 128;
    const int tid = threadIdx.x;
    const int wid = tid >> 5, lane = tid & 31;
    const int g = lane >> 2, t4 = lane & 3;
    const int wm = (wid & 1) * 64, wn = (wid >> 1) * 32;

    extern __shared__ uint32_t sm[];
    uint32_t* Ab[2] = { sm,                sm + 2 * 128 * PAD };
    uint32_t* Bb[2] = { sm + 128 * PAD,    sm + 3 * 128 * PAD };

    // staging geometry: 2 threads per row, 16 floats each
    const int r = tid >> 1;
    const int part = tid & 1;

    // A source row pointer
    const float* aRow;
    if (MODE == 0) {
        int arow = bm + r; if (arow >= M) arow = M - 1;
        aRow = A + (size_t)arow * K + part * 16;
    } else if (MODE == 1) {
        int idx = bm + r;
        int tok = (idx < cnt) ? g_tok[e * Tn + idx] : g_tok[e * Tn];
        aRow = A + (size_t)tok * K + part * 16;
    } else {
        int idx = bm + r; if (idx >= Tn) idx = Tn - 1;
        aRow = A + ((size_t)e * Tn + idx) * (size_t)K + part * 16;
    }
    // B source row pointer
    const float* bRow;
    if (MODE == 0) bRow = B + (size_t)(bn + r) * K + part * 16;
    else           bRow = B + (size_t)e * N * K + (size_t)(bn + r) * K + part * 16;

    const int sbase = r * PAD + part * 16;

    float4 aR[4], bR[4];
#define LDG_STAGE(k0)                                                            \
    do {                                                                         \
        _Pragma("unroll")                                                        \
        for (int q = 0; q < 4; q++) {                                            \
            aR[q] = *(const float4*)(aRow + (k0) + q * 4);                       \
            bR[q] = *(const float4*)(bRow + (k0) + q * 4);                       \
        }                                                                        \
    } while (0)
#define STS_STAGE(p)                                                             \
    do {                                                                         \
        _Pragma("unroll")                                                        \
        for (int q = 0; q < 4; q++) {                                            \
            uint4 av = make_uint4(tf32_rna(aR[q].x), tf32_rna(aR[q].y),          \
                                  tf32_rna(aR[q].z), tf32_rna(aR[q].w));         \
            uint4 bv = make_uint4(tf32_rna(bR[q].x), tf32_rna(bR[q].y),          \
                                  tf32_rna(bR[q].z), tf32_rna(bR[q].w));         \
            *(uint4*)&Ab[p][sbase + q * 4] = av;                                 \
            *(uint4*)&Bb[p][sbase + q * 4] = bv;                                 \
        }                                                                        \
    } while (0)

    float acc[4][4][4];
#pragma unroll
    for (int mt = 0; mt < 4; mt++)
#pragma unroll
        for (int nt = 0; nt < 4; nt++)
#pragma unroll
            for (int q = 0; q < 4; q++) acc[mt][nt][q] = 0.f;

    LDG_STAGE(0);
    STS_STAGE(0);
    __syncthreads();

    const int KT = K / 32;
    for (int kt = 0; kt < KT; kt++) {
        const int p = kt & 1;
        if (kt + 1 < KT) LDG_STAGE((kt + 1) * 32);

        const uint32_t* as = Ab[p];
        const uint32_t* bs = Bb[p];
#pragma unroll
        for (int ks = 0; ks < 4; ks++) {
            uint32_t af[4][4], bf[4][2];
#pragma unroll
            for (int mt = 0; mt < 4; mt++) {
                int r0 = (wm + mt * 16 + g) * PAD + ks * 8 + t4;
                af[mt][0] = as[r0];
                af[mt][1] = as[r0 + 8 * PAD];
                af[mt][2] = as[r0 + 4];
                af[mt][3] = as[r0 + 8 * PAD + 4];
            }
#pragma unroll
            for (int nt = 0; nt < 4; nt++) {
                int c0 = (wn + nt * 8 + g) * PAD + ks * 8 + t4;
                bf[nt][0] = bs[c0];
                bf[nt][1] = bs[c0 + 4];
            }
#pragma unroll
            for (int mt = 0; mt < 4; mt++)
#pragma unroll
                for (int nt = 0; nt < 4; nt++)
                    mma_tf32(acc[mt][nt], af[mt], bf[nt]);
        }

        if (kt + 1 < KT) {
            STS_STAGE(p ^ 1);
            __syncthreads();
        }
    }

    // -------- epilogue: registers -> gmem --------
#pragma unroll
    for (int mt = 0; mt < 4; mt++) {
#pragma unroll
        for (int h = 0; h < 2; h++) {
            const int ridx = bm + wm + mt * 16 + g + h * 8;
            bool valid;
            float* dst = nullptr;
            const float* addrow = nullptr;
            float wg = 1.f;
            if (MODE == 0) {
                valid = ridx < M;
                if (valid) {
                    dst = C + (size_t)ridx * N;
                    if (ADD) addrow = ADD + (size_t)ridx * N;
                }
            } else if (MODE == 1) {
                valid = ridx < cnt;
                if (valid) dst = C + ((size_t)e * Tn + ridx) * (size_t)N;
            } else {
                valid = ridx < cnt;
                if (valid) {
                    int idx = e * Tn + ridx;
                    int tok = g_tok[idx];
                    wg = g_wgt[idx];
                    int sl = g_slot[idx];
                    dst = C + ((size_t)tok * 2 + sl) * (size_t)Dn;
                }
            }
            if (!valid) continue;
#pragma unroll
            for (int nt = 0; nt < 4; nt++) {
                const int col = bn + wn + nt * 8 + 2 * t4;
                float2 v = make_float2(acc[mt][nt][h * 2 + 0], acc[mt][nt][h * 2 + 1]);
                if (MODE == 2) { v.x *= wg; v.y *= wg; }
                if (MODE == 0 && addrow) {
                    float2 d = *(const float2*)(addrow + col);
                    v.x += d.x; v.y += d.y;
                }
                *(float2*)(dst + col) = v;
            }
        }
    }
#undef LDG_STAGE
#undef STS_STAGE
}

// ---------------- small utility kernels (unchanged from R1) ----------------

__global__ void k_zero_cnt() {
    if (threadIdx.x < En) g_cnt[threadIdx.x] = 0;
}

__global__ void k_add_rmsnorm(const float* __restrict__ h, const float* __restrict__ r,
                              const float* __restrict__ w) {
    int t = blockIdx.x;
    const float* hr = h + t * Dn;
    const float* rr = r + t * Dn;
    float* resr = g_res1 + t * Dn;
    float* xr = g_x + t * Dn;

    float v[8];
    float local = 0.f;
#pragma unroll
    for (int j = 0; j < 8; j++) {
        int c = threadIdx.x + j * 256;
        float s = hr[c] + rr[c];
        v[j] = s;
        resr[c] = s;
        local += s * s;
    }
#pragma unroll
    for (int o = 16; o > 0; o >>= 1) local += __shfl_xor_sync(0xffffffffu, local, o);
    __shared__ float red[8];
    if ((threadIdx.x & 31) == 0) red[threadIdx.x >> 5] = local;
    __syncthreads();
    __shared__ float inv;
    if (threadIdx.x == 0) {
        float s = 0.f;
#pragma unroll
        for (int i = 0; i < 8; i++) s += red[i];
        inv = rsqrtf(s / (float)Dn + 1e-5f);
    }
    __syncthreads();
    float iv = inv;
#pragma unroll
    for (int j = 0; j < 8; j++) {
        int c = threadIdx.x + j * 256;
        xr[c] = v[j] * iv * w[c];
    }
}

__global__ void k_rmsnorm(const float* __restrict__ in, const float* __restrict__ w) {
    int t = blockIdx.x;
    const float* ir = in + t * Dn;
    float* xr = g_x2 + t * Dn;
    float v[8];
    float local = 0.f;
#pragma unroll
    for (int j = 0; j < 8; j++) {
        int c = threadIdx.x + j * 256;
        float s = ir[c];
        v[j] = s;
        local += s * s;
    }
#pragma unroll
    for (int o = 16; o > 0; o >>= 1) local += __shfl_xor_sync(0xffffffffu, local, o);
    __shared__ float red[8];
    if ((threadIdx.x & 31) == 0) red[threadIdx.x >> 5] = local;
    __syncthreads();
    __shared__ float inv;
    if (threadIdx.x == 0) {
        float s = 0.f;
#pragma unroll
        for (int i = 0; i < 8; i++) s += red[i];
        inv = rsqrtf(s / (float)Dn + 1e-5f);
    }
    __syncthreads();
    float iv = inv;
#pragma unroll
    for (int j = 0; j < 8; j++) {
        int c = threadIdx.x + j * 256;
        xr[c] = v[j] * iv * w[c];
    }
}

__global__ void k_rope(const float* __restrict__ cosb, const float* __restrict__ sinb) {
    int idx = blockIdx.x * 256 + threadIdx.x;
    if (idx >= Tn * 40 * 32) return;
    int d = idx & 31;
    int rest = idx >> 5;
    int hh = rest % 40;
    int t = rest / 40;
    float c = cosb[t * 32 + d];
    float s = sinb[t * 32 + d];
    float* base = g_qkv + (size_t)t * QKVn + hh * 64 + d;
    float x1 = base[0];
    float x2 = base[32];
    base[0] = x1 * c - x2 * s;
    base[32] = x2 * c + x1 * s;
}

__global__ void k_scores() {
    const int kt = blockIdx.x, qt = blockIdx.y, h = blockIdx.z;
    const int tid = threadIdx.x;
    const int tx = tid & 15, ty = tid >> 4;

    if (kt > qt) {
#pragma unroll
        for (int i = 0; i < 4; i++)
#pragma unroll
            for (int j = 0; j < 4; j++) {
                int q = qt * 64 + ty * 4 + i;
                int k = kt * 64 + tx * 4 + j;
                g_scores[((size_t)h * Tn + q) * Tn + k] = -1e30f;
            }
        return;
    }

    __shared__ float Qs[64][65];
    __shared__ float Ks[64][65];
    const int lr = tid >> 2;
    const int lc = (tid & 3) * 16;
    const int kvh = h >> 2;
#pragma unroll
    for (int ch = 0; ch < 4; ch++) {
        float4 qv = *(const float4*)(g_qkv + (size_t)(qt * 64 + lr) * QKVn + h * 64 + lc + ch * 4);
        Qs[lr][lc + ch * 4 + 0] = qv.x; Qs[lr][lc + ch * 4 + 1] = qv.y;
        Qs[lr][lc + ch * 4 + 2] = qv.z; Qs[lr][lc + ch * 4 + 3] = qv.w;
        float4 kv = *(const float4*)(g_qkv + (size_t)(kt * 64 + lr) * QKVn + 2048 + kvh * 64 + lc + ch * 4);
        Ks[lr][lc + ch * 4 + 0] = kv.x; Ks[lr][lc + ch * 4 + 1] = kv.y;
        Ks[lr][lc + ch * 4 + 2] = kv.z; Ks[lr][lc + ch * 4 + 3] = kv.w;
    }
    __syncthreads();

    float acc[4][4];
#pragma unroll
    for (int i = 0; i < 4; i++)
#pragma unroll
        for (int j = 0; j < 4; j++) acc[i][j] = 0.f;

#pragma unroll 8
    for (int kk = 0; kk < 64; kk++) {
        float ra[4], rb[4];
#pragma unroll
        for (int i = 0; i < 4; i++) ra[i] = Qs[ty * 4 + i][kk];
#pragma unroll
        for (int j = 0; j < 4; j++) rb[j] = Ks[tx * 4 + j][kk];
#pragma unroll
        for (int i = 0; i < 4; i++)
#pragma unroll
            for (int j = 0; j < 4; j++) acc[i][j] += ra[i] * rb[j];
    }

    const float scale = 0.125f;
#pragma unroll
    for (int i = 0; i < 4; i++)
#pragma unroll
        for (int j = 0; j < 4; j++) {
            int q = qt * 64 + ty * 4 + i;
            int k = kt * 64 + tx * 4 + j;
            float v = (k <= q) ? acc[i][j] * scale : -1e30f;
            g_scores[((size_t)h * Tn + q) * Tn + k] = v;
        }
}

__global__ void k_softmax() {
    const int row = blockIdx.x;
    float* p = g_scores + (size_t)row * Tn;
    const int tid = threadIdx.x;
    float v[4];
    float mx = -3.4e38f;
#pragma unroll
    for (int j = 0; j < 4; j++) {
        v[j] = p[tid + j * 128];
        mx = fmaxf(mx, v[j]);
    }
#pragma unroll
    for (int o = 16; o > 0; o >>= 1) mx = fmaxf(mx, __shfl_xor_sync(0xffffffffu, mx, o));
    __shared__ float rm[4];
    if ((tid & 31) == 0) rm[tid >> 5] = mx;
    __syncthreads();
    mx = fmaxf(fmaxf(rm[0], rm[1]), fmaxf(rm[2], rm[3]));
    float sum = 0.f;
#pragma unroll
    for (int j = 0; j < 4; j++) {
        v[j] = __expf(v[j] - mx);
        sum += v[j];
    }
#pragma unroll
    for (int o = 16; o > 0; o >>= 1) sum += __shfl_xor_sync(0xffffffffu, sum, o);
    __shared__ float rs[4];
    if ((tid & 31) == 0) rs[tid >> 5] = sum;
    __syncthreads();
    sum = rs[0] + rs[1] + rs[2] + rs[3];
    float inv = 1.f / sum;
#pragma unroll
    for (int j = 0; j < 4; j++) p[tid + j * 128] = v[j] * inv;
}

__global__ void k_attnv() {
    const int qt = blockIdx.x, h = blockIdx.y;
    const int tid = threadIdx.x;
    const int tx = tid & 15, ty = tid >> 4;
    const int lr = tid >> 2;
    const int lc = (tid & 3) * 16;
    const int kvh = h >> 2;

    __shared__ float Ps[64][65];
    __shared__ float Vs[64][65];
    float acc[4][4];
#pragma unroll
    for (int i = 0; i < 4; i++)
#pragma unroll
        for (int j = 0; j < 4; j++) acc[i][j] = 0.f;

    for (int kt = 0; kt <= qt; kt++) {
#pragma unroll
        for (int ch = 0; ch < 4; ch++) {
            float4 pv = *(const float4*)(g_scores + ((size_t)h * Tn + qt * 64 + lr) * Tn + kt * 64 + lc + ch * 4);
            Ps[lr][lc + ch * 4 + 0] = pv.x; Ps[lr][lc + ch * 4 + 1] = pv.y;
            Ps[lr][lc + ch * 4 + 2] = pv.z; Ps[lr][lc + ch * 4 + 3] = pv.w;
            float4 vv = *(const float4*)(g_qkv + (size_t)(kt * 64 + lr) * QKVn + 2560 + kvh * 64 + lc + ch * 4);
            Vs[lr][lc + ch * 4 + 0] = vv.x; Vs[lr][lc + ch * 4 + 1] = vv.y;
            Vs[lr][lc + ch * 4 + 2] = vv.z; Vs[lr][lc + ch * 4 + 3] = vv.w;
        }
        __syncthreads();
#pragma unroll 8
        for (int kk = 0; kk < 64; kk++) {
            float ra[4], rb[4];
#pragma unroll
            for (int i = 0; i < 4; i++) ra[i] = Ps[ty * 4 + i][kk];
#pragma unroll
            for (int j = 0; j < 4; j++) rb[j] = Vs[kk][tx * 4 + j];
#pragma unroll
            for (int i = 0; i < 4; i++)
#pragma unroll
                for (int j = 0; j < 4; j++) acc[i][j] += ra[i] * rb[j];
        }
        __syncthreads();
    }

#pragma unroll
    for (int i = 0; i < 4; i++)
#pragma unroll
        for (int j = 0; j < 4; j++) {
            int q = qt * 64 + ty * 4 + i;
            g_attn[(size_t)q * Dn + h * 64 + tx * 4 + j] = acc[i][j];
        }
}

__global__ void k_gate(const float* __restrict__ gw) {
    const int t = blockIdx.x;
    const int warp = threadIdx.x >> 5, lane = threadIdx.x & 31;
    const float* xr = g_x2 + (size_t)t * Dn;
    const float* wr = gw + (size_t)warp * Dn;
    float s = 0.f;
    for (int c = lane; c < Dn; c += 32) s += xr[c] * wr[c];
#pragma unroll
    for (int o = 16; o > 0; o >>= 1) s += __shfl_xor_sync(0xffffffffu, s, o);
    __shared__ float lg[En];
    if (lane == 0) lg[warp] = s;
    __syncthreads();
    if (threadIdx.x == 0) {
        int i0 = 0;
        for (int e = 1; e < En; e++) if (lg[e] > lg[i0]) i0 = e;
        int i1 = (i0 == 0) ? 1 : 0;
        for (int e = 0; e < En; e++) if (e != i0 && lg[e] > lg[i1]) i1 = e;
        float w1v = __expf(lg[i1] - lg[i0]);
        float inv = 1.f / (1.f + w1v);
        float w0 = inv, w1n = w1v * inv;
        int p0 = atomicAdd(&g_cnt[i0], 1);
        g_tok[i0 * Tn + p0] = t; g_wgt[i0 * Tn + p0] = w0; g_slot[i0 * Tn + p0] = 0;
        int p1 = atomicAdd(&g_cnt[i1], 1);
        g_tok[i1 * Tn + p1] = t; g_wgt[i1 * Tn + p1] = w1n; g_slot[i1 * Tn + p1] = 1;
    }
}

__global__ void k_act() {
    const int e = blockIdx.y >> 9;
    const int pos = blockIdx.y & 511;
    if (pos >= g_cnt[e]) return;
    const int col = blockIdx.x * 256 + threadIdx.x;
    const size_t idx = (size_t)blockIdx.y * In + col;
    float a = g_h1[idx];
    float b = g_h3[idx];
    g_h1[idx] = (a / (1.f + __expf(-a))) * b;
}

__global__ void k_combine(float* __restrict__ out) {
    int i = blockIdx.x * 256 + threadIdx.x;
    if (i >= Tn * Dn) return;
    int t = i / Dn;
    out[i] = g_eo[(size_t)i + (size_t)t * Dn] + g_eo[(size_t)i + (size_t)t * Dn + Dn];
}

// ---------------- launch ----------------
extern "C" void kernel_launch(void* const* d_in, const int* in_sizes, int n_in,
                              void* d_out, int out_size) {
    const float* hs   = (const float*)d_in[0];
    const float* resi = (const float*)d_in[1];
    const float* cosb = (const float*)d_in[2];
    const float* sinb = (const float*)d_in[3];
    const float* ln1  = (const float*)d_in[4];
    const float* ln2  = (const float*)d_in[5];
    const float* wqkv = (const float*)d_in[6];
    const float* wo   = (const float*)d_in[7];
    const float* gw   = (const float*)d_in[8];
    const float* w1   = (const float*)d_in[9];
    const float* w3   = (const float*)d_in[10];
    const float* w2   = (const float*)d_in[11];

    float* out = (float*)d_out;
    float* moe_out = out;
    float* res2 = out + Tn * Dn;

    void *px, *pqkv, *pattn, *pres1, *px2, *ph1, *ph3, *peo;
    cudaGetSymbolAddress(&px, g_x);
    cudaGetSymbolAddress(&pqkv, g_qkv);
    cudaGetSymbolAddress(&pattn, g_attn);
    cudaGetSymbolAddress(&pres1, g_res1);
    cudaGetSymbolAddress(&px2, g_x2);
    cudaGetSymbolAddress(&ph1, g_h1);
    cudaGetSymbolAddress(&ph3, g_h3);
    cudaGetSymbolAddress(&peo, g_eo);

    cudaFuncSetAttribute(k_gemm_mma<0>, cudaFuncAttributeMaxDynamicSharedMemorySize, GEMM_SMEM_BYTES);
    cudaFuncSetAttribute(k_gemm_mma<1>, cudaFuncAttributeMaxDynamicSharedMemorySize, GEMM_SMEM_BYTES);
    cudaFuncSetAttribute(k_gemm_mma<2>, cudaFuncAttributeMaxDynamicSharedMemorySize, GEMM_SMEM_BYTES);

    k_zero_cnt<<<1, 32>>>();
    k_add_rmsnorm<<<Tn, 256>>>(hs, resi, ln1);

    // qkv = x @ wqkv^T
    k_gemm_mma<0><<<dim3(QKVn / 128, Tn / 128), 256, GEMM_SMEM_BYTES>>>(
        (const float*)px, wqkv, (float*)pqkv, nullptr, Tn, QKVn, Dn);
    k_rope<<<(Tn * 40 * 32) / 256, 256>>>(cosb, sinb);

    k_scores<<<dim3(Tn / 64, Tn / 64, Hn), 256>>>();
    k_softmax<<<Hn * Tn, 128>>>();
    k_attnv<<<dim3(Tn / 64, Hn), 256>>>();

    // res2 = attn @ wo^T + res1
    k_gemm_mma<0><<<dim3(Dn / 128, Tn / 128), 256, GEMM_SMEM_BYTES>>>(
        (const float*)pattn, wo, res2, (const float*)pres1, Tn, Dn, Dn);
    k_rmsnorm<<<Tn, 256>>>(res2, ln2);
    k_gate<<<Tn, 256>>>(gw);

    k_gemm_mma<1><<<dim3(In / 128, Tn / 128, En), 256, GEMM_SMEM_BYTES>>>(
        (const float*)px2, w1, (float*)ph1, nullptr, Tn, In, Dn);
    k_gemm_mma<1><<<dim3(In / 128, Tn / 128, En), 256, GEMM_SMEM_BYTES>>>(
        (const float*)px2, w3, (float*)ph3, nullptr, Tn, In, Dn);
    k_act<<<dim3(In / 256, En * Tn), 256>>>();
    k_gemm_mma<2><<<dim3(Dn / 128, Tn / 128, En), 256, GEMM_SMEM_BYTES>>>(
        (const float*)ph1, w2, (float*)peo, nullptr, Tn, Dn, In);
    k_combine<<<(Tn * Dn) / 256, 256>>>(moe_out);
}

// round 4
// speedup vs baseline: 4.8581x; 1.5100x over previous
#include <cuda_runtime.h>
#include <math.h>
#include <stdint.h>

#define Tn 512
#define Dn 2048
#define Hn 32
#define KVn 8
#define DHn 64
#define In 7168
#define En 8
#define QKVn 3072   // (H + 2*KV) * DH
#define PAD 36      // smem row stride in 32-bit words

// GEMM tile: 128 (M) x 256 (N), BK=32, 3-stage cp.async pipeline
#define A_WORDS (128 * PAD)            // 4608 words
#define B_WORDS (256 * PAD)            // 9216 words
#define STAGE_WORDS (A_WORDS + B_WORDS) // 13824 words
#define STAGE_BYTES (STAGE_WORDS * 4)   // 55296 B
#define GEMM_SMEM_BYTES (3 * STAGE_BYTES) // 165888 B

// ---------------- scratch (device globals; no allocation allowed) ----------------
__device__ __align__(16) float g_res1[Tn * Dn];
__device__ __align__(16) float g_x[Tn * Dn];
__device__ __align__(16) float g_qkv[Tn * QKVn];
__device__ __align__(16) float g_scores[Hn * Tn * Tn];
__device__ __align__(16) float g_attn[Tn * Dn];
__device__ __align__(16) float g_x2[Tn * Dn];
__device__ __align__(16) float g_h1[En * Tn * In];
__device__ __align__(16) float g_h3[En * Tn * In];
__device__ __align__(16) float g_eo[Tn * 2 * Dn];
__device__ int   g_tok[En * Tn];
__device__ float g_wgt[En * Tn];
__device__ int   g_slot[En * Tn];
__device__ int   g_cnt[En];

// ================= helpers (sm_80-level features only) =================
__device__ __forceinline__ uint32_t smem_u32(const void* p) {
    uint32_t a;
    asm("{ .reg .u64 t; cvta.to.shared.u64 t, %1; cvt.u32.u64 %0, t; }" : "=r"(a) : "l"(p));
    return a;
}
__device__ __forceinline__ uint32_t tf32_rna(float x) {
    uint32_t r; asm("cvt.rna.tf32.f32 %0, %1;" : "=r"(r) : "f"(x)); return r;
}
__device__ __forceinline__ void mma_tf32(float* c, const uint32_t* a, const uint32_t* b) {
    asm volatile(
        "mma.sync.aligned.m16n8k8.row.col.f32.tf32.tf32.f32 "
        "{%0,%1,%2,%3}, {%4,%5,%6,%7}, {%8,%9}, {%0,%1,%2,%3};"
        : "+f"(c[0]), "+f"(c[1]), "+f"(c[2]), "+f"(c[3])
        : "r"(a[0]), "r"(a[1]), "r"(a[2]), "r"(a[3]), "r"(b[0]), "r"(b[1]));
}
__device__ __forceinline__ void cp_async16(uint32_t saddr, const void* gaddr) {
    asm volatile("cp.async.cg.shared.global [%0], [%1], 16;" :: "r"(saddr), "l"(gaddr));
}
#define CP_COMMIT() asm volatile("cp.async.commit_group;" ::: "memory")
#define CP_WAIT1()  asm volatile("cp.async.wait_group 1;" ::: "memory")

// ================= tf32 tensor-core GEMM: C[M,N] = A[M,K] * B[N,K]^T =================
// MODE 0: plain (+ optional addend). MODE 1: MoE gemm1 (row gather via g_tok).
// MODE 2: MoE gemm2 (weighted scatter to g_eo).
// Tile 128x256, BK=32, 256 threads (2x4 warps, each 64x64), 3-stage cp.async.
template <int MODE>
__global__ void __launch_bounds__(256, 1) k_gemm_mma(const float* __restrict__ A,
                                                     const float* __restrict__ B,
                                                     float* __restrict__ C,
                                                     const float* __restrict__ ADD,
                                                     int M, int N, int K) {
    const int e = (MODE == 0) ? 0 : blockIdx.z;
    const int cnt = (MODE == 0) ? M : g_cnt[e];
    const int bm = blockIdx.y * 128;
    if (bm >= cnt) return;
    const int bn = blockIdx.x * 256;
    const int tid = threadIdx.x;
    const int wid = tid >> 5, lane = tid & 31;
    const int g = lane >> 2, t4 = lane & 3;
    const int wm = (wid & 1) * 64, wn = (wid >> 1) * 64;

    extern __shared__ float sm[];
    const uint32_t smBase = smem_u32(sm);

    // ---- A source pointers (4 chunks of 16B per thread per stage) ----
    const float* aSrc[4];
#pragma unroll
    for (int i = 0; i < 4; i++) {
        int chunk = tid + i * 256;
        int row = chunk >> 3, c = chunk & 7;
        if (MODE == 0) {
            int ridx = bm + row; if (ridx >= M) ridx = M - 1;
            aSrc[i] = A + (size_t)ridx * K + c * 4;
        } else if (MODE == 1) {
            int idx = bm + row;
            int tok = (idx < cnt) ? g_tok[e * Tn + idx] : g_tok[e * Tn];
            aSrc[i] = A + (size_t)tok * K + c * 4;
        } else {
            int idx = bm + row;
            aSrc[i] = A + ((size_t)e * Tn + idx) * (size_t)K + c * 4;
        }
    }
    const float* const bBase = (MODE == 0) ? B : B + (size_t)e * N * K;

#define ISSUE_STAGE(ktn)                                                          \
    do {                                                                          \
        const int k0 = (ktn) * 32;                                                \
        const uint32_t sb = smBase + ((ktn) % 3) * (uint32_t)STAGE_BYTES;         \
        _Pragma("unroll")                                                         \
        for (int i = 0; i < 4; i++) {                                             \
            int chunk = tid + i * 256;                                            \
            int row = chunk >> 3, c = chunk & 7;                                  \
            cp_async16(sb + (uint32_t)(row * PAD + c * 4) * 4u, aSrc[i] + k0);    \
        }                                                                         \
        _Pragma("unroll")                                                         \
        for (int i = 0; i < 8; i++) {                                             \
            int chunk = tid + i * 256;                                            \
            int row = chunk >> 3, c = chunk & 7;                                  \
            const float* gp = bBase + (size_t)(bn + row) * K + c * 4 + k0;        \
            cp_async16(sb + (uint32_t)(A_WORDS + row * PAD + c * 4) * 4u, gp);    \
        }                                                                         \
    } while (0)

    float acc[4][8][4];
#pragma unroll
    for (int mt = 0; mt < 4; mt++)
#pragma unroll
        for (int nt = 0; nt < 8; nt++)
#pragma unroll
            for (int q = 0; q < 4; q++) acc[mt][nt][q] = 0.f;

    ISSUE_STAGE(0); CP_COMMIT();
    ISSUE_STAGE(1); CP_COMMIT();

    const int KT = K / 32;
    for (int kt = 0; kt < KT; kt++) {
        CP_WAIT1();
        __syncthreads();
        if (kt + 2 < KT) ISSUE_STAGE(kt + 2);
        CP_COMMIT();

        const float* as = sm + (kt % 3) * STAGE_WORDS;
        const float* bs = as + A_WORDS;
#pragma unroll
        for (int ks = 0; ks < 4; ks++) {
            const int ko = ks * 8 + t4;
            uint32_t af[4][4], bf[8][2];
#pragma unroll
            for (int mt = 0; mt < 4; mt++) {
                const int r0 = (wm + mt * 16 + g) * PAD + ko;
                af[mt][0] = tf32_rna(as[r0]);
                af[mt][1] = tf32_rna(as[r0 + 8 * PAD]);
                af[mt][2] = tf32_rna(as[r0 + 4]);
                af[mt][3] = tf32_rna(as[r0 + 8 * PAD + 4]);
            }
#pragma unroll
            for (int nt = 0; nt < 8; nt++) {
                const int c0 = (wn + nt * 8 + g) * PAD + ko;
                bf[nt][0] = tf32_rna(bs[c0]);
                bf[nt][1] = tf32_rna(bs[c0 + 4]);
            }
#pragma unroll
            for (int mt = 0; mt < 4; mt++)
#pragma unroll
                for (int nt = 0; nt < 8; nt++)
                    mma_tf32(acc[mt][nt], af[mt], bf[nt]);
        }
        __syncthreads();
    }
#undef ISSUE_STAGE

    // -------- epilogue: registers -> gmem --------
#pragma unroll
    for (int mt = 0; mt < 4; mt++) {
#pragma unroll
        for (int h = 0; h < 2; h++) {
            const int ridx = bm + wm + mt * 16 + g + h * 8;
            bool valid;
            float* dst = nullptr;
            const float* addrow = nullptr;
            float wg = 1.f;
            if (MODE == 0) {
                valid = ridx < M;
                if (valid) {
                    dst = C + (size_t)ridx * N;
                    if (ADD) addrow = ADD + (size_t)ridx * N;
                }
            } else if (MODE == 1) {
                valid = ridx < cnt;
                if (valid) dst = C + ((size_t)e * Tn + ridx) * (size_t)N;
            } else {
                valid = ridx < cnt;
                if (valid) {
                    int idx = e * Tn + ridx;
                    int tok = g_tok[idx];
                    wg = g_wgt[idx];
                    int sl = g_slot[idx];
                    dst = C + ((size_t)tok * 2 + sl) * (size_t)Dn;
                }
            }
            if (!valid) continue;
#pragma unroll
            for (int nt = 0; nt < 8; nt++) {
                const int col = bn + wn + nt * 8 + 2 * t4;
                float2 v = make_float2(acc[mt][nt][h * 2 + 0], acc[mt][nt][h * 2 + 1]);
                if (MODE == 2) { v.x *= wg; v.y *= wg; }
                if (MODE == 0 && addrow) {
                    float2 d = *(const float2*)(addrow + col);
                    v.x += d.x; v.y += d.y;
                }
                *(float2*)(dst + col) = v;
            }
        }
    }
}

// ---------------- small utility kernels ----------------

__global__ void k_zero_cnt() {
    if (threadIdx.x < En) g_cnt[threadIdx.x] = 0;
}

__global__ void k_add_rmsnorm(const float* __restrict__ h, const float* __restrict__ r,
                              const float* __restrict__ w) {
    int t = blockIdx.x;
    const float* hr = h + t * Dn;
    const float* rr = r + t * Dn;
    float* resr = g_res1 + t * Dn;
    float* xr = g_x + t * Dn;

    float v[8];
    float local = 0.f;
#pragma unroll
    for (int j = 0; j < 8; j++) {
        int c = threadIdx.x + j * 256;
        float s = hr[c] + rr[c];
        v[j] = s;
        resr[c] = s;
        local += s * s;
    }
#pragma unroll
    for (int o = 16; o > 0; o >>= 1) local += __shfl_xor_sync(0xffffffffu, local, o);
    __shared__ float red[8];
    if ((threadIdx.x & 31) == 0) red[threadIdx.x >> 5] = local;
    __syncthreads();
    __shared__ float inv;
    if (threadIdx.x == 0) {
        float s = 0.f;
#pragma unroll
        for (int i = 0; i < 8; i++) s += red[i];
        inv = rsqrtf(s / (float)Dn + 1e-5f);
    }
    __syncthreads();
    float iv = inv;
#pragma unroll
    for (int j = 0; j < 8; j++) {
        int c = threadIdx.x + j * 256;
        xr[c] = v[j] * iv * w[c];
    }
}

__global__ void k_rmsnorm(const float* __restrict__ in, const float* __restrict__ w) {
    int t = blockIdx.x;
    const float* ir = in + t * Dn;
    float* xr = g_x2 + t * Dn;
    float v[8];
    float local = 0.f;
#pragma unroll
    for (int j = 0; j < 8; j++) {
        int c = threadIdx.x + j * 256;
        float s = ir[c];
        v[j] = s;
        local += s * s;
    }
#pragma unroll
    for (int o = 16; o > 0; o >>= 1) local += __shfl_xor_sync(0xffffffffu, local, o);
    __shared__ float red[8];
    if ((threadIdx.x & 31) == 0) red[threadIdx.x >> 5] = local;
    __syncthreads();
    __shared__ float inv;
    if (threadIdx.x == 0) {
        float s = 0.f;
#pragma unroll
        for (int i = 0; i < 8; i++) s += red[i];
        inv = rsqrtf(s / (float)Dn + 1e-5f);
    }
    __syncthreads();
    float iv = inv;
#pragma unroll
    for (int j = 0; j < 8; j++) {
        int c = threadIdx.x + j * 256;
        xr[c] = v[j] * iv * w[c];
    }
}

__global__ void k_rope(const float* __restrict__ cosb, const float* __restrict__ sinb) {
    int idx = blockIdx.x * 256 + threadIdx.x;
    if (idx >= Tn * 40 * 32) return;
    int d = idx & 31;
    int rest = idx >> 5;
    int hh = rest % 40;
    int t = rest / 40;
    float c = cosb[t * 32 + d];
    float s = sinb[t * 32 + d];
    float* base = g_qkv + (size_t)t * QKVn + hh * 64 + d;
    float x1 = base[0];
    float x2 = base[32];
    base[0] = x1 * c - x2 * s;
    base[32] = x2 * c + x1 * s;
}

__global__ void k_scores() {
    const int kt = blockIdx.x, qt = blockIdx.y, h = blockIdx.z;
    const int tid = threadIdx.x;
    const int tx = tid & 15, ty = tid >> 4;

    if (kt > qt) {
#pragma unroll
        for (int i = 0; i < 4; i++)
#pragma unroll
            for (int j = 0; j < 4; j++) {
                int q = qt * 64 + ty * 4 + i;
                int k = kt * 64 + tx * 4 + j;
                g_scores[((size_t)h * Tn + q) * Tn + k] = -1e30f;
            }
        return;
    }

    __shared__ float Qs[64][65];
    __shared__ float Ks[64][65];
    const int lr = tid >> 2;
    const int lc = (tid & 3) * 16;
    const int kvh = h >> 2;
#pragma unroll
    for (int ch = 0; ch < 4; ch++) {
        float4 qv = *(const float4*)(g_qkv + (size_t)(qt * 64 + lr) * QKVn + h * 64 + lc + ch * 4);
        Qs[lr][lc + ch * 4 + 0] = qv.x; Qs[lr][lc + ch * 4 + 1] = qv.y;
        Qs[lr][lc + ch * 4 + 2] = qv.z; Qs[lr][lc + ch * 4 + 3] = qv.w;
        float4 kv = *(const float4*)(g_qkv + (size_t)(kt * 64 + lr) * QKVn + 2048 + kvh * 64 + lc + ch * 4);
        Ks[lr][lc + ch * 4 + 0] = kv.x; Ks[lr][lc + ch * 4 + 1] = kv.y;
        Ks[lr][lc + ch * 4 + 2] = kv.z; Ks[lr][lc + ch * 4 + 3] = kv.w;
    }
    __syncthreads();

    float acc[4][4];
#pragma unroll
    for (int i = 0; i < 4; i++)
#pragma unroll
        for (int j = 0; j < 4; j++) acc[i][j] = 0.f;

#pragma unroll 8
    for (int kk = 0; kk < 64; kk++) {
        float ra[4], rb[4];
#pragma unroll
        for (int i = 0; i < 4; i++) ra[i] = Qs[ty * 4 + i][kk];
#pragma unroll
        for (int j = 0; j < 4; j++) rb[j] = Ks[tx * 4 + j][kk];
#pragma unroll
        for (int i = 0; i < 4; i++)
#pragma unroll
            for (int j = 0; j < 4; j++) acc[i][j] += ra[i] * rb[j];
    }

    const float scale = 0.125f;
#pragma unroll
    for (int i = 0; i < 4; i++)
#pragma unroll
        for (int j = 0; j < 4; j++) {
            int q = qt * 64 + ty * 4 + i;
            int k = kt * 64 + tx * 4 + j;
            float v = (k <= q) ? acc[i][j] * scale : -1e30f;
            g_scores[((size_t)h * Tn + q) * Tn + k] = v;
        }
}

__global__ void k_softmax() {
    const int row = blockIdx.x;
    float* p = g_scores + (size_t)row * Tn;
    const int tid = threadIdx.x;
    float v[4];
    float mx = -3.4e38f;
#pragma unroll
    for (int j = 0; j < 4; j++) {
        v[j] = p[tid + j * 128];
        mx = fmaxf(mx, v[j]);
    }
#pragma unroll
    for (int o = 16; o > 0; o >>= 1) mx = fmaxf(mx, __shfl_xor_sync(0xffffffffu, mx, o));
    __shared__ float rm[4];
    if ((tid & 31) == 0) rm[tid >> 5] = mx;
    __syncthreads();
    mx = fmaxf(fmaxf(rm[0], rm[1]), fmaxf(rm[2], rm[3]));
    float sum = 0.f;
#pragma unroll
    for (int j = 0; j < 4; j++) {
        v[j] = __expf(v[j] - mx);
        sum += v[j];
    }
#pragma unroll
    for (int o = 16; o > 0; o >>= 1) sum += __shfl_xor_sync(0xffffffffu, sum, o);
    __shared__ float rs[4];
    if ((tid & 31) == 0) rs[tid >> 5] = sum;
    __syncthreads();
    sum = rs[0] + rs[1] + rs[2] + rs[3];
    float inv = 1.f / sum;
#pragma unroll
    for (int j = 0; j < 4; j++) p[tid + j * 128] = v[j] * inv;
}

__global__ void k_attnv() {
    const int qt = blockIdx.x, h = blockIdx.y;
    const int tid = threadIdx.x;
    const int tx = tid & 15, ty = tid >> 4;
    const int lr = tid >> 2;
    const int lc = (tid & 3) * 16;
    const int kvh = h >> 2;

    __shared__ float Ps[64][65];
    __shared__ float Vs[64][65];
    float acc[4][4];
#pragma unroll
    for (int i = 0; i < 4; i++)
#pragma unroll
        for (int j = 0; j < 4; j++) acc[i][j] = 0.f;

    for (int kt = 0; kt <= qt; kt++) {
#pragma unroll
        for (int ch = 0; ch < 4; ch++) {
            float4 pv = *(const float4*)(g_scores + ((size_t)h * Tn + qt * 64 + lr) * Tn + kt * 64 + lc + ch * 4);
            Ps[lr][lc + ch * 4 + 0] = pv.x; Ps[lr][lc + ch * 4 + 1] = pv.y;
            Ps[lr][lc + ch * 4 + 2] = pv.z; Ps[lr][lc + ch * 4 + 3] = pv.w;
            float4 vv = *(const float4*)(g_qkv + (size_t)(kt * 64 + lr) * QKVn + 2560 + kvh * 64 + lc + ch * 4);
            Vs[lr][lc + ch * 4 + 0] = vv.x; Vs[lr][lc + ch * 4 + 1] = vv.y;
            Vs[lr][lc + ch * 4 + 2] = vv.z; Vs[lr][lc + ch * 4 + 3] = vv.w;
        }
        __syncthreads();
#pragma unroll 8
        for (int kk = 0; kk < 64; kk++) {
            float ra[4], rb[4];
#pragma unroll
            for (int i = 0; i < 4; i++) ra[i] = Ps[ty * 4 + i][kk];
#pragma unroll
            for (int j = 0; j < 4; j++) rb[j] = Vs[kk][tx * 4 + j];
#pragma unroll
            for (int i = 0; i < 4; i++)
#pragma unroll
                for (int j = 0; j < 4; j++) acc[i][j] += ra[i] * rb[j];
        }
        __syncthreads();
    }

#pragma unroll
    for (int i = 0; i < 4; i++)
#pragma unroll
        for (int j = 0; j < 4; j++) {
            int q = qt * 64 + ty * 4 + i;
            g_attn[(size_t)q * Dn + h * 64 + tx * 4 + j] = acc[i][j];
        }
}

__global__ void k_gate(const float* __restrict__ gw) {
    const int t = blockIdx.x;
    const int warp = threadIdx.x >> 5, lane = threadIdx.x & 31;
    const float* xr = g_x2 + (size_t)t * Dn;
    const float* wr = gw + (size_t)warp * Dn;
    float s = 0.f;
    for (int c = lane; c < Dn; c += 32) s += xr[c] * wr[c];
#pragma unroll
    for (int o = 16; o > 0; o >>= 1) s += __shfl_xor_sync(0xffffffffu, s, o);
    __shared__ float lg[En];
    if (lane == 0) lg[warp] = s;
    __syncthreads();
    if (threadIdx.x == 0) {
        int i0 = 0;
        for (int e = 1; e < En; e++) if (lg[e] > lg[i0]) i0 = e;
        int i1 = (i0 == 0) ? 1 : 0;
        for (int e = 0; e < En; e++) if (e != i0 && lg[e] > lg[i1]) i1 = e;
        float w1v = __expf(lg[i1] - lg[i0]);
        float inv = 1.f / (1.f + w1v);
        float w0 = inv, w1n = w1v * inv;
        int p0 = atomicAdd(&g_cnt[i0], 1);
        g_tok[i0 * Tn + p0] = t; g_wgt[i0 * Tn + p0] = w0; g_slot[i0 * Tn + p0] = 0;
        int p1 = atomicAdd(&g_cnt[i1], 1);
        g_tok[i1 * Tn + p1] = t; g_wgt[i1 * Tn + p1] = w1n; g_slot[i1 * Tn + p1] = 1;
    }
}

__global__ void k_act() {
    const int e = blockIdx.y >> 9;
    const int pos = blockIdx.y & 511;
    if (pos >= g_cnt[e]) return;
    const int col = blockIdx.x * 256 + threadIdx.x;
    const size_t idx = (size_t)blockIdx.y * In + col;
    float a = g_h1[idx];
    float b = g_h3[idx];
    g_h1[idx] = (a / (1.f + __expf(-a))) * b;
}

__global__ void k_combine(float* __restrict__ out) {
    int i = blockIdx.x * 256 + threadIdx.x;
    if (i >= Tn * Dn) return;
    int t = i / Dn;
    out[i] = g_eo[(size_t)i + (size_t)t * Dn] + g_eo[(size_t)i + (size_t)t * Dn + Dn];
}

// ---------------- launch ----------------
extern "C" void kernel_launch(void* const* d_in, const int* in_sizes, int n_in,
                              void* d_out, int out_size) {
    const float* hs   = (const float*)d_in[0];
    const float* resi = (const float*)d_in[1];
    const float* cosb = (const float*)d_in[2];
    const float* sinb = (const float*)d_in[3];
    const float* ln1  = (const float*)d_in[4];
    const float* ln2  = (const float*)d_in[5];
    const float* wqkv = (const float*)d_in[6];
    const float* wo   = (const float*)d_in[7];
    const float* gw   = (const float*)d_in[8];
    const float* w1   = (const float*)d_in[9];
    const float* w3   = (const float*)d_in[10];
    const float* w2   = (const float*)d_in[11];

    float* out = (float*)d_out;
    float* moe_out = out;
    float* res2 = out + Tn * Dn;

    void *px, *pqkv, *pattn, *pres1, *px2, *ph1, *ph3, *peo;
    cudaGetSymbolAddress(&px, g_x);
    cudaGetSymbolAddress(&pqkv, g_qkv);
    cudaGetSymbolAddress(&pattn, g_attn);
    cudaGetSymbolAddress(&pres1, g_res1);
    cudaGetSymbolAddress(&px2, g_x2);
    cudaGetSymbolAddress(&ph1, g_h1);
    cudaGetSymbolAddress(&ph3, g_h3);
    cudaGetSymbolAddress(&peo, g_eo);

    cudaFuncSetAttribute(k_gemm_mma<0>, cudaFuncAttributeMaxDynamicSharedMemorySize, GEMM_SMEM_BYTES);
    cudaFuncSetAttribute(k_gemm_mma<1>, cudaFuncAttributeMaxDynamicSharedMemorySize, GEMM_SMEM_BYTES);
    cudaFuncSetAttribute(k_gemm_mma<2>, cudaFuncAttributeMaxDynamicSharedMemorySize, GEMM_SMEM_BYTES);

    k_zero_cnt<<<1, 32>>>();
    k_add_rmsnorm<<<Tn, 256>>>(hs, resi, ln1);

    // qkv = x @ wqkv^T
    k_gemm_mma<0><<<dim3(QKVn / 256, Tn / 128), 256, GEMM_SMEM_BYTES>>>(
        (const float*)px, wqkv, (float*)pqkv, nullptr, Tn, QKVn, Dn);
    k_rope<<<(Tn * 40 * 32) / 256, 256>>>(cosb, sinb);

    k_scores<<<dim3(Tn / 64, Tn / 64, Hn), 256>>>();
    k_softmax<<<Hn * Tn, 128>>>();
    k_attnv<<<dim3(Tn / 64, Hn), 256>>>();

    // res2 = attn @ wo^T + res1
    k_gemm_mma<0><<<dim3(Dn / 256, Tn / 128), 256, GEMM_SMEM_BYTES>>>(
        (const float*)pattn, wo, res2, (const float*)pres1, Tn, Dn, Dn);
    k_rmsnorm<<<Tn, 256>>>(res2, ln2);
    k_gate<<<Tn, 256>>>(gw);

    k_gemm_mma<1><<<dim3(In / 256, Tn / 128, En), 256, GEMM_SMEM_BYTES>>>(
        (const float*)px2, w1, (float*)ph1, nullptr, Tn, In, Dn);
    k_gemm_mma<1><<<dim3(In / 256, Tn / 128, En), 256, GEMM_SMEM_BYTES>>>(
        (const float*)px2, w3, (float*)ph3, nullptr, Tn, In, Dn);
    k_act<<<dim3(In / 256, En * Tn), 256>>>();
    k_gemm_mma<2><<<dim3(Dn / 256, Tn / 128, En), 256, GEMM_SMEM_BYTES>>>(
        (const float*)ph1, w2, (float*)peo, nullptr, Tn, Dn, In);
    k_combine<<<(Tn * Dn) / 256, 256>>>(moe_out);
}

// round 5
// speedup vs baseline: 4.8798x; 1.0045x over previous
#include <cuda_runtime.h>
#include <math.h>
#include <stdint.h>

#define Tn 512
#define Dn 2048
#define Hn 32
#define KVn 8
#define DHn 64
#define In 7168
#define En 8
#define QKVn 3072   // (H + 2*KV) * DH
#define PAD 36      // smem row stride in 32-bit words

// ---------------- scratch (device globals; no allocation allowed) ----------------
__device__ __align__(16) float g_res1[Tn * Dn];
__device__ __align__(16) float g_x[Tn * Dn];
__device__ __align__(16) float g_qkv[Tn * QKVn];
__device__ __align__(16) float g_scores[Hn * Tn * Tn];
__device__ __align__(16) float g_attn[Tn * Dn];
__device__ __align__(16) float g_x2[Tn * Dn];
__device__ __align__(16) float g_h1[En * Tn * In];
__device__ __align__(16) float g_h3[En * Tn * In];
__device__ __align__(16) float g_eo[Tn * 4 * Dn];   // partial/scatter scratch (16 MB)
__device__ int   g_tok[En * Tn];
__device__ float g_wgt[En * Tn];
__device__ int   g_slot[En * Tn];
__device__ int   g_cnt[En];

// ================= helpers (sm_80-level features only) =================
__device__ __forceinline__ uint32_t smem_u32(const void* p) {
    uint32_t a;
    asm("{ .reg .u64 t; cvta.to.shared.u64 t, %1; cvt.u32.u64 %0, t; }" : "=r"(a) : "l"(p));
    return a;
}
__device__ __forceinline__ uint32_t tf32_rna(float x) {
    uint32_t r; asm("cvt.rna.tf32.f32 %0, %1;" : "=r"(r) : "f"(x)); return r;
}
__device__ __forceinline__ void mma_tf32(float* c, const uint32_t* a, const uint32_t* b) {
    asm volatile(
        "mma.sync.aligned.m16n8k8.row.col.f32.tf32.tf32.f32 "
        "{%0,%1,%2,%3}, {%4,%5,%6,%7}, {%8,%9}, {%0,%1,%2,%3};"
        : "+f"(c[0]), "+f"(c[1]), "+f"(c[2]), "+f"(c[3])
        : "r"(a[0]), "r"(a[1]), "r"(a[2]), "r"(a[3]), "r"(b[0]), "r"(b[1]));
}
__device__ __forceinline__ void cp_async16(uint32_t saddr, const void* gaddr) {
    asm volatile("cp.async.cg.shared.global [%0], [%1], 16;" :: "r"(saddr), "l"(gaddr));
}
#define CP_COMMIT() asm volatile("cp.async.commit_group;" ::: "memory")
#define CP_WAIT1()  asm volatile("cp.async.wait_group 1;" ::: "memory")

// ================= tf32 tensor-core GEMM: C[M,N] = A[M,K] * B[N,K]^T =================
// MODE 0: plain, split-K via blockIdx.z, C partials [kh][M][N].
// MODE 1: MoE gemm1 fused w1/w3 (row gather via g_tok), z = expert.
// MODE 2: MoE gemm2, split-K2, z = e*2+kh, weighted scatter to g_eo 4-slot.
// Tile 128 x NT, BK=32, 256 threads (8 warps of 64 x NT/4), 3-stage cp.async.
// Row-granular M masking: warps skip 16-row MMA groups beyond cnt.
template <int MODE, int NT, int KSPLIT>
__global__ void __launch_bounds__(256, 1) k_gemm(const float* __restrict__ A,
                                                 const float* __restrict__ B,
                                                 const float* __restrict__ B2,
                                                 float* __restrict__ C,
                                                 float* __restrict__ C2,
                                                 int M, int N, int Kstride) {
    constexpr int BNT = NT / 32;              // B n-subtiles per warp
    constexpr int A_WORDS = 128 * PAD;
    constexpr int B_WORDS = NT * PAD;
    constexpr int STAGE_WORDS = A_WORDS + B_WORDS;
    constexpr int BCH = NT / 32;              // B chunks per thread per stage

    const int kh = (MODE == 2) ? (int)(blockIdx.z & 1) : ((MODE == 0) ? (int)blockIdx.z : 0);
    const int e  = (MODE == 0) ? 0 : ((MODE == 2) ? (int)(blockIdx.z >> 1) : (int)blockIdx.z);
    const int cnt = (MODE == 0) ? M : g_cnt[e];
    const int bm = blockIdx.y * 128;
    if (bm >= cnt) return;
    int bn = blockIdx.x * NT;

    const float* Bp = B;
    float* Cp = C;
    if (MODE == 1 && bn >= N) { Bp = B2; Cp = C2; bn -= N; }
    if (MODE != 0) Bp += (size_t)e * N * Kstride;

    const int Klen = Kstride / KSPLIT;
    const int koff = kh * Klen;

    const int tid = threadIdx.x;
    const int wid = tid >> 5, lane = tid & 31;
    const int g = lane >> 2, t4 = lane & 3;
    const int wm = (wid & 1) * 64, wn = (wid >> 1) * (NT / 4);

    // rows this warp actually needs, in 16-row MMA groups
    const int rows_avail = cnt - bm - wm;
    const int mtact = (rows_avail >= 64) ? 4 : ((rows_avail <= 0) ? 0 : ((rows_avail + 15) >> 4));

    extern __shared__ float sm[];
    const uint32_t smBase = smem_u32(sm);

    // ---- A source pointers (4 chunks of 16B per thread per stage) ----
    const float* aSrc[4];
#pragma unroll
    for (int i = 0; i < 4; i++) {
        int chunk = tid + i * 256;
        int row = chunk >> 3, c = chunk & 7;
        if (MODE == 0) {
            int ridx = bm + row; if (ridx >= M) ridx = M - 1;
            aSrc[i] = A + (size_t)ridx * Kstride + c * 4 + koff;
        } else if (MODE == 1) {
            int idx = bm + row;
            int tok = (idx < cnt) ? g_tok[e * Tn + idx] : g_tok[e * Tn];
            aSrc[i] = A + (size_t)tok * Kstride + c * 4 + koff;
        } else {
            int idx = bm + row;
            aSrc[i] = A + ((size_t)e * Tn + idx) * (size_t)Kstride + c * 4 + koff;
        }
    }

#define ISSUE_STAGE(ktn)                                                            \
    do {                                                                            \
        const int k0 = (ktn) * 32;                                                  \
        const uint32_t sb = smBase + ((ktn) % 3) * (uint32_t)(STAGE_WORDS * 4);     \
        _Pragma("unroll")                                                           \
        for (int i = 0; i < 4; i++) {                                               \
            int chunk = tid + i * 256;                                              \
            int row = chunk >> 3, c = chunk & 7;                                    \
            cp_async16(sb + (uint32_t)(row * PAD + c * 4) * 4u, aSrc[i] + k0);      \
        }                                                                           \
        _Pragma("unroll")                                                           \
        for (int i = 0; i < BCH; i++) {                                             \
            int chunk = tid + i * 256;                                              \
            int row = chunk >> 3, c = chunk & 7;                                    \
            const float* gp = Bp + (size_t)(bn + row) * Kstride + c * 4 + koff + k0;\
            cp_async16(sb + (uint32_t)(A_WORDS + row * PAD + c * 4) * 4u, gp);      \
        }                                                                           \
    } while (0)

    float acc[4][BNT][4];
#pragma unroll
    for (int mt = 0; mt < 4; mt++)
#pragma unroll
        for (int nt = 0; nt < BNT; nt++)
#pragma unroll
            for (int q = 0; q < 4; q++) acc[mt][nt][q] = 0.f;

    ISSUE_STAGE(0); CP_COMMIT();
    ISSUE_STAGE(1); CP_COMMIT();

    const int KT = Klen / 32;
    for (int kt = 0; kt < KT; kt++) {
        CP_WAIT1();
        __syncthreads();
        if (kt + 2 < KT) ISSUE_STAGE(kt + 2);
        CP_COMMIT();

        const float* as = sm + (kt % 3) * STAGE_WORDS;
        const float* bs = as + A_WORDS;
#pragma unroll
        for (int ks = 0; ks < 4; ks++) {
            const int ko = ks * 8 + t4;
            uint32_t af[4][4], bf[BNT][2];
#pragma unroll
            for (int mt = 0; mt < 4; mt++) {
                if (mt < mtact) {
                    const int r0 = (wm + mt * 16 + g) * PAD + ko;
                    af[mt][0] = tf32_rna(as[r0]);
                    af[mt][1] = tf32_rna(as[r0 + 8 * PAD]);
                    af[mt][2] = tf32_rna(as[r0 + 4]);
                    af[mt][3] = tf32_rna(as[r0 + 8 * PAD + 4]);
                }
            }
            if (mtact > 0) {
#pragma unroll
                for (int nt = 0; nt < BNT; nt++) {
                    const int c0 = (wn + nt * 8 + g) * PAD + ko;
                    bf[nt][0] = tf32_rna(bs[c0]);
                    bf[nt][1] = tf32_rna(bs[c0 + 4]);
                }
#pragma unroll
                for (int mt = 0; mt < 4; mt++) {
                    if (mt < mtact) {
#pragma unroll
                        for (int nt = 0; nt < BNT; nt++)
                            mma_tf32(acc[mt][nt], af[mt], bf[nt]);
                    }
                }
            }
        }
        __syncthreads();
    }
#undef ISSUE_STAGE

    // -------- epilogue: registers -> gmem --------
#pragma unroll
    for (int mt = 0; mt < 4; mt++) {
        if (mt >= mtact) continue;
#pragma unroll
        for (int h = 0; h < 2; h++) {
            const int ridx = bm + wm + mt * 16 + g + h * 8;
            bool valid;
            float* dst = nullptr;
            float wg = 1.f;
            if (MODE == 0) {
                valid = ridx < M;
                if (valid) dst = Cp + (size_t)kh * M * N + (size_t)ridx * N;
            } else if (MODE == 1) {
                valid = ridx < cnt;
                if (valid) dst = Cp + ((size_t)e * Tn + ridx) * (size_t)N;
            } else {
                valid = ridx < cnt;
                if (valid) {
                    int idx = e * Tn + ridx;
                    int tok = g_tok[idx];
                    wg = g_wgt[idx];
                    int sl = g_slot[idx];
                    dst = Cp + ((size_t)tok * 4 + sl * 2 + kh) * (size_t)Dn;
                }
            }
            if (!valid) continue;
#pragma unroll
            for (int nt = 0; nt < BNT; nt++) {
                const int col = bn + wn + nt * 8 + 2 * t4;
                float2 v = make_float2(acc[mt][nt][h * 2 + 0], acc[mt][nt][h * 2 + 1]);
                if (MODE == 2) { v.x *= wg; v.y *= wg; }
                *(float2*)(dst + col) = v;
            }
        }
    }
}

// ---------------- small utility kernels ----------------

__global__ void k_zero_cnt() {
    if (threadIdx.x < En) g_cnt[threadIdx.x] = 0;
}

// res1 = h + r;  x = rmsnorm(res1, w)
__global__ void k_add_rmsnorm(const float* __restrict__ h, const float* __restrict__ r,
                              const float* __restrict__ w) {
    int t = blockIdx.x;
    const float* hr = h + t * Dn;
    const float* rr = r + t * Dn;
    float* resr = g_res1 + t * Dn;
    float* xr = g_x + t * Dn;

    float v[8];
    float local = 0.f;
#pragma unroll
    for (int j = 0; j < 8; j++) {
        int c = threadIdx.x + j * 256;
        float s = hr[c] + rr[c];
        v[j] = s;
        resr[c] = s;
        local += s * s;
    }
#pragma unroll
    for (int o = 16; o > 0; o >>= 1) local += __shfl_xor_sync(0xffffffffu, local, o);
    __shared__ float red[8];
    if ((threadIdx.x & 31) == 0) red[threadIdx.x >> 5] = local;
    __syncthreads();
    __shared__ float inv;
    if (threadIdx.x == 0) {
        float s = 0.f;
#pragma unroll
        for (int i = 0; i < 8; i++) s += red[i];
        inv = rsqrtf(s / (float)Dn + 1e-5f);
    }
    __syncthreads();
    float iv = inv;
#pragma unroll
    for (int j = 0; j < 8; j++) {
        int c = threadIdx.x + j * 256;
        xr[c] = v[j] * iv * w[c];
    }
}

// res2 = p0 + p1 + res1 (written to out); x2 = rmsnorm(res2, w)
__global__ void k_add2_rmsnorm(const float* __restrict__ p0, const float* __restrict__ p1,
                               const float* __restrict__ w, float* __restrict__ res2out) {
    int t = blockIdx.x;
    const float* a0 = p0 + t * Dn;
    const float* a1 = p1 + t * Dn;
    const float* rr = g_res1 + t * Dn;
    float* ro = res2out + t * Dn;
    float* xr = g_x2 + t * Dn;
    float v[8];
    float local = 0.f;
#pragma unroll
    for (int j = 0; j < 8; j++) {
        int c = threadIdx.x + j * 256;
        float s = a0[c] + a1[c] + rr[c];
        v[j] = s;
        ro[c] = s;
        local += s * s;
    }
#pragma unroll
    for (int o = 16; o > 0; o >>= 1) local += __shfl_xor_sync(0xffffffffu, local, o);
    __shared__ float red[8];
    if ((threadIdx.x & 31) == 0) red[threadIdx.x >> 5] = local;
    __syncthreads();
    __shared__ float inv;
    if (threadIdx.x == 0) {
        float s = 0.f;
#pragma unroll
        for (int i = 0; i < 8; i++) s += red[i];
        inv = rsqrtf(s / (float)Dn + 1e-5f);
    }
    __syncthreads();
    float iv = inv;
#pragma unroll
    for (int j = 0; j < 8; j++) {
        int c = threadIdx.x + j * 256;
        xr[c] = v[j] * iv * w[c];
    }
}

// qkv = p0 + p1 (split-K partial sum)
__global__ void k_addqkv(const float* __restrict__ p) {
    int i = blockIdx.x * 256 + threadIdx.x;
    if (i >= Tn * QKVn) return;
    g_qkv[i] = p[i] + p[i + Tn * QKVn];
}

__global__ void k_rope(const float* __restrict__ cosb, const float* __restrict__ sinb) {
    int idx = blockIdx.x * 256 + threadIdx.x;
    if (idx >= Tn * 40 * 32) return;
    int d = idx & 31;
    int rest = idx >> 5;
    int hh = rest % 40;
    int t = rest / 40;
    float c = cosb[t * 32 + d];
    float s = sinb[t * 32 + d];
    float* base = g_qkv + (size_t)t * QKVn + hh * 64 + d;
    float x1 = base[0];
    float x2 = base[32];
    base[0] = x1 * c - x2 * s;
    base[32] = x2 * c + x1 * s;
}

__global__ void k_scores() {
    const int kt = blockIdx.x, qt = blockIdx.y, h = blockIdx.z;
    const int tid = threadIdx.x;
    const int tx = tid & 15, ty = tid >> 4;

    if (kt > qt) {
#pragma unroll
        for (int i = 0; i < 4; i++)
#pragma unroll
            for (int j = 0; j < 4; j++) {
                int q = qt * 64 + ty * 4 + i;
                int k = kt * 64 + tx * 4 + j;
                g_scores[((size_t)h * Tn + q) * Tn + k] = -1e30f;
            }
        return;
    }

    __shared__ float Qs[64][65];
    __shared__ float Ks[64][65];
    const int lr = tid >> 2;
    const int lc = (tid & 3) * 16;
    const int kvh = h >> 2;
#pragma unroll
    for (int ch = 0; ch < 4; ch++) {
        float4 qv = *(const float4*)(g_qkv + (size_t)(qt * 64 + lr) * QKVn + h * 64 + lc + ch * 4);
        Qs[lr][lc + ch * 4 + 0] = qv.x; Qs[lr][lc + ch * 4 + 1] = qv.y;
        Qs[lr][lc + ch * 4 + 2] = qv.z; Qs[lr][lc + ch * 4 + 3] = qv.w;
        float4 kv = *(const float4*)(g_qkv + (size_t)(kt * 64 + lr) * QKVn + 2048 + kvh * 64 + lc + ch * 4);
        Ks[lr][lc + ch * 4 + 0] = kv.x; Ks[lr][lc + ch * 4 + 1] = kv.y;
        Ks[lr][lc + ch * 4 + 2] = kv.z; Ks[lr][lc + ch * 4 + 3] = kv.w;
    }
    __syncthreads();

    float acc[4][4];
#pragma unroll
    for (int i = 0; i < 4; i++)
#pragma unroll
        for (int j = 0; j < 4; j++) acc[i][j] = 0.f;

#pragma unroll 8
    for (int kk = 0; kk < 64; kk++) {
        float ra[4], rb[4];
#pragma unroll
        for (int i = 0; i < 4; i++) ra[i] = Qs[ty * 4 + i][kk];
#pragma unroll
        for (int j = 0; j < 4; j++) rb[j] = Ks[tx * 4 + j][kk];
#pragma unroll
        for (int i = 0; i < 4; i++)
#pragma unroll
            for (int j = 0; j < 4; j++) acc[i][j] += ra[i] * rb[j];
    }

    const float scale = 0.125f;
#pragma unroll
    for (int i = 0; i < 4; i++)
#pragma unroll
        for (int j = 0; j < 4; j++) {
            int q = qt * 64 + ty * 4 + i;
            int k = kt * 64 + tx * 4 + j;
            float v = (k <= q) ? acc[i][j] * scale : -1e30f;
            g_scores[((size_t)h * Tn + q) * Tn + k] = v;
        }
}

__global__ void k_softmax() {
    const int row = blockIdx.x;
    float* p = g_scores + (size_t)row * Tn;
    const int tid = threadIdx.x;
    float v[4];
    float mx = -3.4e38f;
#pragma unroll
    for (int j = 0; j < 4; j++) {
        v[j] = p[tid + j * 128];
        mx = fmaxf(mx, v[j]);
    }
#pragma unroll
    for (int o = 16; o > 0; o >>= 1) mx = fmaxf(mx, __shfl_xor_sync(0xffffffffu, mx, o));
    __shared__ float rm[4];
    if ((tid & 31) == 0) rm[tid >> 5] = mx;
    __syncthreads();
    mx = fmaxf(fmaxf(rm[0], rm[1]), fmaxf(rm[2], rm[3]));
    float sum = 0.f;
#pragma unroll
    for (int j = 0; j < 4; j++) {
        v[j] = __expf(v[j] - mx);
        sum += v[j];
    }
#pragma unroll
    for (int o = 16; o > 0; o >>= 1) sum += __shfl_xor_sync(0xffffffffu, sum, o);
    __shared__ float rs[4];
    if ((tid & 31) == 0) rs[tid >> 5] = sum;
    __syncthreads();
    sum = rs[0] + rs[1] + rs[2] + rs[3];
    float inv = 1.f / sum;
#pragma unroll
    for (int j = 0; j < 4; j++) p[tid + j * 128] = v[j] * inv;
}

__global__ void k_attnv() {
    const int qt = blockIdx.x, h = blockIdx.y;
    const int tid = threadIdx.x;
    const int tx = tid & 15, ty = tid >> 4;
    const int lr = tid >> 2;
    const int lc = (tid & 3) * 16;
    const int kvh = h >> 2;

    __shared__ float Ps[64][65];
    __shared__ float Vs[64][65];
    float acc[4][4];
#pragma unroll
    for (int i = 0; i < 4; i++)
#pragma unroll
        for (int j = 0; j < 4; j++) acc[i][j] = 0.f;

    for (int kt = 0; kt <= qt; kt++) {
#pragma unroll
        for (int ch = 0; ch < 4; ch++) {
            float4 pv = *(const float4*)(g_scores + ((size_t)h * Tn + qt * 64 + lr) * Tn + kt * 64 + lc + ch * 4);
            Ps[lr][lc + ch * 4 + 0] = pv.x; Ps[lr][lc + ch * 4 + 1] = pv.y;
            Ps[lr][lc + ch * 4 + 2] = pv.z; Ps[lr][lc + ch * 4 + 3] = pv.w;
            float4 vv = *(const float4*)(g_qkv + (size_t)(kt * 64 + lr) * QKVn + 2560 + kvh * 64 + lc + ch * 4);
            Vs[lr][lc + ch * 4 + 0] = vv.x; Vs[lr][lc + ch * 4 + 1] = vv.y;
            Vs[lr][lc + ch * 4 + 2] = vv.z; Vs[lr][lc + ch * 4 + 3] = vv.w;
        }
        __syncthreads();
#pragma unroll 8
        for (int kk = 0; kk < 64; kk++) {
            float ra[4], rb[4];
#pragma unroll
            for (int i = 0; i < 4; i++) ra[i] = Ps[ty * 4 + i][kk];
#pragma unroll
            for (int j = 0; j < 4; j++) rb[j] = Vs[kk][tx * 4 + j];
#pragma unroll
            for (int i = 0; i < 4; i++)
#pragma unroll
                for (int j = 0; j < 4; j++) acc[i][j] += ra[i] * rb[j];
        }
        __syncthreads();
    }

#pragma unroll
    for (int i = 0; i < 4; i++)
#pragma unroll
        for (int j = 0; j < 4; j++) {
            int q = qt * 64 + ty * 4 + i;
            g_attn[(size_t)q * Dn + h * 64 + tx * 4 + j] = acc[i][j];
        }
}

__global__ void k_gate(const float* __restrict__ gw) {
    const int t = blockIdx.x;
    const int warp = threadIdx.x >> 5, lane = threadIdx.x & 31;
    const float* xr = g_x2 + (size_t)t * Dn;
    const float* wr = gw + (size_t)warp * Dn;
    float s = 0.f;
    for (int c = lane; c < Dn; c += 32) s += xr[c] * wr[c];
#pragma unroll
    for (int o = 16; o > 0; o >>= 1) s += __shfl_xor_sync(0xffffffffu, s, o);
    __shared__ float lg[En];
    if (lane == 0) lg[warp] = s;
    __syncthreads();
    if (threadIdx.x == 0) {
        int i0 = 0;
        for (int e = 1; e < En; e++) if (lg[e] > lg[i0]) i0 = e;
        int i1 = (i0 == 0) ? 1 : 0;
        for (int e = 0; e < En; e++) if (e != i0 && lg[e] > lg[i1]) i1 = e;
        float w1v = __expf(lg[i1] - lg[i0]);
        float inv = 1.f / (1.f + w1v);
        float w0 = inv, w1n = w1v * inv;
        int p0 = atomicAdd(&g_cnt[i0], 1);
        g_tok[i0 * Tn + p0] = t; g_wgt[i0 * Tn + p0] = w0; g_slot[i0 * Tn + p0] = 0;
        int p1 = atomicAdd(&g_cnt[i1], 1);
        g_tok[i1 * Tn + p1] = t; g_wgt[i1 * Tn + p1] = w1n; g_slot[i1 * Tn + p1] = 1;
    }
}

__global__ void k_act() {
    const int e = blockIdx.y >> 9;
    const int pos = blockIdx.y & 511;
    if (pos >= g_cnt[e]) return;
    const int col = blockIdx.x * 256 + threadIdx.x;
    const size_t idx = (size_t)blockIdx.y * In + col;
    float a = g_h1[idx];
    float b = g_h3[idx];
    g_h1[idx] = (a / (1.f + __expf(-a))) * b;
}

// moe_out = sum of 4 eo slots (2 experts x 2 K-halves)
__global__ void k_combine(float* __restrict__ out) {
    int i = blockIdx.x * 256 + threadIdx.x;
    if (i >= Tn * Dn) return;
    int t = i / Dn;
    int d = i - t * Dn;
    const float* base = g_eo + (size_t)t * 4 * Dn + d;
    out[i] = base[0] + base[Dn] + base[2 * Dn] + base[3 * Dn];
}

// ---------------- launch ----------------
extern "C" void kernel_launch(void* const* d_in, const int* in_sizes, int n_in,
                              void* d_out, int out_size) {
    const float* hs   = (const float*)d_in[0];
    const float* resi = (const float*)d_in[1];
    const float* cosb = (const float*)d_in[2];
    const float* sinb = (const float*)d_in[3];
    const float* ln1  = (const float*)d_in[4];
    const float* ln2  = (const float*)d_in[5];
    const float* wqkv = (const float*)d_in[6];
    const float* wo   = (const float*)d_in[7];
    const float* gw   = (const float*)d_in[8];
    const float* w1   = (const float*)d_in[9];
    const float* w3   = (const float*)d_in[10];
    const float* w2   = (const float*)d_in[11];

    float* out = (float*)d_out;
    float* moe_out = out;
    float* res2 = out + Tn * Dn;

    void *px, *pattn, *px2, *ph1, *ph3, *peo;
    cudaGetSymbolAddress(&px, g_x);
    cudaGetSymbolAddress(&pattn, g_attn);
    cudaGetSymbolAddress(&px2, g_x2);
    cudaGetSymbolAddress(&ph1, g_h1);
    cudaGetSymbolAddress(&ph3, g_h3);
    cudaGetSymbolAddress(&peo, g_eo);

    constexpr int SMEM128 = 3 * (128 * PAD + 128 * PAD) * 4;  // 110592
    constexpr int SMEM256 = 3 * (128 * PAD + 256 * PAD) * 4;  // 165888
    cudaFuncSetAttribute(k_gemm<0, 128, 2>, cudaFuncAttributeMaxDynamicSharedMemorySize, SMEM128);
    cudaFuncSetAttribute(k_gemm<1, 256, 1>, cudaFuncAttributeMaxDynamicSharedMemorySize, SMEM256);
    cudaFuncSetAttribute(k_gemm<2, 256, 2>, cudaFuncAttributeMaxDynamicSharedMemorySize, SMEM256);

    k_zero_cnt<<<1, 32>>>();
    k_add_rmsnorm<<<Tn, 256>>>(hs, resi, ln1);

    // qkv partials: [2][512][3072] into g_eo, then sum + rope
    k_gemm<0, 128, 2><<<dim3(QKVn / 128, Tn / 128, 2), 256, SMEM128>>>(
        (const float*)px, wqkv, nullptr, (float*)peo, nullptr, Tn, QKVn, Dn);
    k_addqkv<<<(Tn * QKVn) / 256, 256>>>((const float*)peo);
    k_rope<<<(Tn * 40 * 32) / 256, 256>>>(cosb, sinb);

    k_scores<<<dim3(Tn / 64, Tn / 64, Hn), 256>>>();
    k_softmax<<<Hn * Tn, 128>>>();
    k_attnv<<<dim3(Tn / 64, Hn), 256>>>();

    // attn @ wo^T partials: [2][512][2048] into g_eo; fused add + rmsnorm
    k_gemm<0, 128, 2><<<dim3(Dn / 128, Tn / 128, 2), 256, SMEM128>>>(
        (const float*)pattn, wo, nullptr, (float*)peo, nullptr, Tn, Dn, Dn);
    k_add2_rmsnorm<<<Tn, 256>>>((const float*)peo, (const float*)peo + Tn * Dn, ln2, res2);
    k_gate<<<Tn, 256>>>(gw);

    // fused w1/w3 grouped GEMM: x grid covers [w1 | w3]
    k_gemm<1, 256, 1><<<dim3(2 * In / 256, Tn / 128, En), 256, SMEM256>>>(
        (const float*)px2, w1, w3, (float*)ph1, (float*)ph3, Tn, In, Dn);
    k_act<<<dim3(In / 256, En * Tn), 256>>>();
    // w2 grouped GEMM, split-K2, scatter into 4-slot eo
    k_gemm<2, 256, 2><<<dim3(Dn / 256, Tn / 128, En * 2), 256, SMEM256>>>(
        (const float*)ph1, w2, nullptr, (float*)peo, nullptr, Tn, Dn, In);
    k_combine<<<(Tn * Dn) / 256, 256>>>(moe_out);
}

// round 6
// speedup vs baseline: 4.9756x; 1.0196x over previous
#include <cuda_runtime.h>
#include <math.h>
#include <stdint.h>

#define Tn 512
#define Dn 2048
#define Hn 32
#define KVn 8
#define DHn 64
#define In 7168
#define En 8
#define QKVn 3072   // (H + 2*KV) * DH
#define PAD 36      // smem row stride in 32-bit words

// ---------------- scratch (device globals; no allocation allowed) ----------------
__device__ __align__(16) float g_res1[Tn * Dn];
__device__ __align__(16) float g_x[Tn * Dn];
__device__ __align__(16) float g_qkv[Tn * QKVn];
__device__ __align__(16) float g_scores[Hn * Tn * Tn];
__device__ __align__(16) float g_attn[Tn * Dn];
__device__ __align__(16) float g_x2[Tn * Dn];
__device__ __align__(16) float g_h1[En * Tn * In];
__device__ __align__(16) float g_h3[En * Tn * In];
__device__ __align__(16) float g_eo[Tn * 4 * Dn];   // partial/scatter scratch (16 MB)
__device__ int   g_tok[En * Tn];
__device__ float g_wgt[En * Tn];
__device__ int   g_slot[En * Tn];
__device__ int   g_cnt[En];

// ================= helpers (sm_80-level features only) =================
__device__ __forceinline__ uint32_t smem_u32(const void* p) {
    uint32_t a;
    asm("{ .reg .u64 t; cvta.to.shared.u64 t, %1; cvt.u32.u64 %0, t; }" : "=r"(a) : "l"(p));
    return a;
}
__device__ __forceinline__ uint32_t tf32_rna(float x) {
    uint32_t r; asm("cvt.rna.tf32.f32 %0, %1;" : "=r"(r) : "f"(x)); return r;
}
__device__ __forceinline__ void mma_tf32(float* c, const uint32_t* a, const uint32_t* b) {
    asm volatile(
        "mma.sync.aligned.m16n8k8.row.col.f32.tf32.tf32.f32 "
        "{%0,%1,%2,%3}, {%4,%5,%6,%7}, {%8,%9}, {%0,%1,%2,%3};"
        : "+f"(c[0]), "+f"(c[1]), "+f"(c[2]), "+f"(c[3])
        : "r"(a[0]), "r"(a[1]), "r"(a[2]), "r"(a[3]), "r"(b[0]), "r"(b[1]));
}
__device__ __forceinline__ void cp_async16(uint32_t saddr, const void* gaddr) {
    asm volatile("cp.async.cg.shared.global [%0], [%1], 16;" :: "r"(saddr), "l"(gaddr));
}
#define CP_COMMIT() asm volatile("cp.async.commit_group;" ::: "memory")
#define CP_WAIT1()  asm volatile("cp.async.wait_group 1;" ::: "memory")

// ================= tf32 tensor-core GEMM: C[M,N] = A[M,K] * B[N,K]^T =================
// MODE 0: plain, split-K via blockIdx.z, C partials [kh][M][N].
// MODE 1: MoE gemm1 fused w1/w3 (row gather via g_tok), z = expert.
// MODE 2: MoE gemm2, split-K2, z = e*2+kh, weighted scatter to g_eo 4-slot.
// Tile 128 x NT, BK=32, 512 threads (16 warps of 32 x NT/4), 3-stage cp.async.
// Fragment loads use contiguous k-pairs (2*t4, 2*t4+1) for both A and B ->
// LDS.64; MMA sums over a permuted k order, result identical.
template <int MODE, int NT, int KSPLIT>
__global__ void __launch_bounds__(512, 1) k_gemm(const float* __restrict__ A,
                                                 const float* __restrict__ B,
                                                 const float* __restrict__ B2,
                                                 float* __restrict__ C,
                                                 float* __restrict__ C2,
                                                 int M, int N, int Kstride) {
    constexpr int BNT = NT / 32;                 // warp n-subtiles (8 cols each)
    constexpr int WN = NT / 4;                   // warp n extent
    constexpr int A_WORDS = 128 * PAD;
    constexpr int B_WORDS = NT * PAD;
    constexpr int STAGE_WORDS = A_WORDS + B_WORDS;
    constexpr int BCH = NT / 64;                 // B 16B-chunks per thread per stage

    const int kh = (MODE == 2) ? (int)(blockIdx.z & 1) : ((MODE == 0) ? (int)blockIdx.z : 0);
    const int e  = (MODE == 0) ? 0 : ((MODE == 2) ? (int)(blockIdx.z >> 1) : (int)blockIdx.z);
    const int cnt = (MODE == 0) ? M : g_cnt[e];
    const int bm = blockIdx.y * 128;
    if (bm >= cnt) return;
    int bn = blockIdx.x * NT;

    const float* Bp = B;
    float* Cp = C;
    if (MODE == 1 && bn >= N) { Bp = B2; Cp = C2; bn -= N; }
    if (MODE != 0) Bp += (size_t)e * N * Kstride;

    const int Klen = Kstride / KSPLIT;
    const int koff = kh * Klen;

    const int tid = threadIdx.x;
    const int wid = tid >> 5, lane = tid & 31;
    const int g = lane >> 2, t4 = lane & 3;
    const int wm = (wid & 3) * 32, wn = (wid >> 2) * WN;

    // rows this warp actually needs, in 16-row MMA groups (max 2)
    const int rows_avail = cnt - bm - wm;
    const int mtact = (rows_avail >= 32) ? 2 : ((rows_avail <= 0) ? 0 : ((rows_avail + 15) >> 4));

    extern __shared__ float sm[];
    const uint32_t smBase = smem_u32(sm);

    // ---- A source pointers (2 chunks of 16B per thread per stage) ----
    const float* aSrc[2];
#pragma unroll
    for (int i = 0; i < 2; i++) {
        int chunk = tid + i * 512;
        int row = chunk >> 3, c = chunk & 7;
        if (MODE == 0) {
            int ridx = bm + row; if (ridx >= M) ridx = M - 1;
            aSrc[i] = A + (size_t)ridx * Kstride + c * 4 + koff;
        } else if (MODE == 1) {
            int idx = bm + row;
            int tok = (idx < cnt) ? g_tok[e * Tn + idx] : g_tok[e * Tn];
            aSrc[i] = A + (size_t)tok * Kstride + c * 4 + koff;
        } else {
            int idx = bm + row;
            aSrc[i] = A + ((size_t)e * Tn + idx) * (size_t)Kstride + c * 4 + koff;
        }
    }

#define ISSUE_STAGE(ktn)                                                            \
    do {                                                                            \
        const int k0 = (ktn) * 32;                                                  \
        const uint32_t sb = smBase + ((ktn) % 3) * (uint32_t)(STAGE_WORDS * 4);     \
        _Pragma("unroll")                                                           \
        for (int i = 0; i < 2; i++) {                                               \
            int chunk = tid + i * 512;                                              \
            int row = chunk >> 3, c = chunk & 7;                                    \
            cp_async16(sb + (uint32_t)(row * PAD + c * 4) * 4u, aSrc[i] + k0);      \
        }                                                                           \
        _Pragma("unroll")                                                           \
        for (int i = 0; i < BCH; i++) {                                             \
            int chunk = tid + i * 512;                                              \
            int row = chunk >> 3, c = chunk & 7;                                    \
            const float* gp = Bp + (size_t)(bn + row) * Kstride + c * 4 + koff + k0;\
            cp_async16(sb + (uint32_t)(A_WORDS + row * PAD + c * 4) * 4u, gp);      \
        }                                                                           \
    } while (0)

    float acc[2][BNT][4];
#pragma unroll
    for (int mt = 0; mt < 2; mt++)
#pragma unroll
        for (int nt = 0; nt < BNT; nt++)
#pragma unroll
            for (int q = 0; q < 4; q++) acc[mt][nt][q] = 0.f;

    ISSUE_STAGE(0); CP_COMMIT();
    ISSUE_STAGE(1); CP_COMMIT();

    const int KT = Klen / 32;
    for (int kt = 0; kt < KT; kt++) {
        CP_WAIT1();
        __syncthreads();
        if (kt + 2 < KT) ISSUE_STAGE(kt + 2);
        CP_COMMIT();

        const float* as = sm + (kt % 3) * STAGE_WORDS;
        const float* bs = as + A_WORDS;
#pragma unroll
        for (int ks = 0; ks < 4; ks++) {
            const int ko2 = ks * 8 + 2 * t4;     // contiguous k-pair offset
            uint32_t af[2][4], bf[BNT][2];
#pragma unroll
            for (int mt = 0; mt < 2; mt++) {
                if (mt < mtact) {
                    const int r0 = (wm + mt * 16 + g) * PAD + ko2;
                    float2 lo = *(const float2*)&as[r0];
                    float2 hi = *(const float2*)&as[r0 + 8 * PAD];
                    af[mt][0] = tf32_rna(lo.x);
                    af[mt][1] = tf32_rna(hi.x);
                    af[mt][2] = tf32_rna(lo.y);
                    af[mt][3] = tf32_rna(hi.y);
                }
            }
            if (mtact > 0) {
#pragma unroll
                for (int nt = 0; nt < BNT; nt++) {
                    const int c0 = (wn + nt * 8 + g) * PAD + ko2;
                    float2 b2 = *(const float2*)&bs[c0];
                    bf[nt][0] = tf32_rna(b2.x);
                    bf[nt][1] = tf32_rna(b2.y);
                }
#pragma unroll
                for (int mt = 0; mt < 2; mt++) {
                    if (mt < mtact) {
#pragma unroll
                        for (int nt = 0; nt < BNT; nt++)
                            mma_tf32(acc[mt][nt], af[mt], bf[nt]);
                    }
                }
            }
        }
        __syncthreads();
    }
#undef ISSUE_STAGE

    // -------- epilogue: registers -> gmem --------
#pragma unroll
    for (int mt = 0; mt < 2; mt++) {
        if (mt >= mtact) continue;
#pragma unroll
        for (int h = 0; h < 2; h++) {
            const int ridx = bm + wm + mt * 16 + g + h * 8;
            bool valid;
            float* dst = nullptr;
            float wg = 1.f;
            if (MODE == 0) {
                valid = ridx < M;
                if (valid) dst = Cp + (size_t)kh * M * N + (size_t)ridx * N;
            } else if (MODE == 1) {
                valid = ridx < cnt;
                if (valid) dst = Cp + ((size_t)e * Tn + ridx) * (size_t)N;
            } else {
                valid = ridx < cnt;
                if (valid) {
                    int idx = e * Tn + ridx;
                    int tok = g_tok[idx];
                    wg = g_wgt[idx];
                    int sl = g_slot[idx];
                    dst = Cp + ((size_t)tok * 4 + sl * 2 + kh) * (size_t)Dn;
                }
            }
            if (!valid) continue;
#pragma unroll
            for (int nt = 0; nt < BNT; nt++) {
                const int col = bn + wn + nt * 8 + 2 * t4;
                float2 v = make_float2(acc[mt][nt][h * 2 + 0], acc[mt][nt][h * 2 + 1]);
                if (MODE == 2) { v.x *= wg; v.y *= wg; }
                *(float2*)(dst + col) = v;
            }
        }
    }
}

// ---------------- small utility kernels ----------------

__global__ void k_zero_cnt() {
    if (threadIdx.x < En) g_cnt[threadIdx.x] = 0;
}

// res1 = h + r;  x = rmsnorm(res1, w)
__global__ void k_add_rmsnorm(const float* __restrict__ h, const float* __restrict__ r,
                              const float* __restrict__ w) {
    int t = blockIdx.x;
    const float* hr = h + t * Dn;
    const float* rr = r + t * Dn;
    float* resr = g_res1 + t * Dn;
    float* xr = g_x + t * Dn;

    float v[8];
    float local = 0.f;
#pragma unroll
    for (int j = 0; j < 8; j++) {
        int c = threadIdx.x + j * 256;
        float s = hr[c] + rr[c];
        v[j] = s;
        resr[c] = s;
        local += s * s;
    }
#pragma unroll
    for (int o = 16; o > 0; o >>= 1) local += __shfl_xor_sync(0xffffffffu, local, o);
    __shared__ float red[8];
    if ((threadIdx.x & 31) == 0) red[threadIdx.x >> 5] = local;
    __syncthreads();
    __shared__ float inv;
    if (threadIdx.x == 0) {
        float s = 0.f;
#pragma unroll
        for (int i = 0; i < 8; i++) s += red[i];
        inv = rsqrtf(s / (float)Dn + 1e-5f);
    }
    __syncthreads();
    float iv = inv;
#pragma unroll
    for (int j = 0; j < 8; j++) {
        int c = threadIdx.x + j * 256;
        xr[c] = v[j] * iv * w[c];
    }
}

// res2 = p0 + p1 + res1 (written to out); x2 = rmsnorm(res2, w)
__global__ void k_add2_rmsnorm(const float* __restrict__ p0, const float* __restrict__ p1,
                               const float* __restrict__ w, float* __restrict__ res2out) {
    int t = blockIdx.x;
    const float* a0 = p0 + t * Dn;
    const float* a1 = p1 + t * Dn;
    const float* rr = g_res1 + t * Dn;
    float* ro = res2out + t * Dn;
    float* xr = g_x2 + t * Dn;
    float v[8];
    float local = 0.f;
#pragma unroll
    for (int j = 0; j < 8; j++) {
        int c = threadIdx.x + j * 256;
        float s = a0[c] + a1[c] + rr[c];
        v[j] = s;
        ro[c] = s;
        local += s * s;
    }
#pragma unroll
    for (int o = 16; o > 0; o >>= 1) local += __shfl_xor_sync(0xffffffffu, local, o);
    __shared__ float red[8];
    if ((threadIdx.x & 31) == 0) red[threadIdx.x >> 5] = local;
    __syncthreads();
    __shared__ float inv;
    if (threadIdx.x == 0) {
        float s = 0.f;
#pragma unroll
        for (int i = 0; i < 8; i++) s += red[i];
        inv = rsqrtf(s / (float)Dn + 1e-5f);
    }
    __syncthreads();
    float iv = inv;
#pragma unroll
    for (int j = 0; j < 8; j++) {
        int c = threadIdx.x + j * 256;
        xr[c] = v[j] * iv * w[c];
    }
}

// qkv = p0 + p1 (split-K partial sum)
__global__ void k_addqkv(const float* __restrict__ p) {
    int i = blockIdx.x * 256 + threadIdx.x;
    if (i >= Tn * QKVn) return;
    g_qkv[i] = p[i] + p[i + Tn * QKVn];
}

__global__ void k_rope(const float* __restrict__ cosb, const float* __restrict__ sinb) {
    int idx = blockIdx.x * 256 + threadIdx.x;
    if (idx >= Tn * 40 * 32) return;
    int d = idx & 31;
    int rest = idx >> 5;
    int hh = rest % 40;
    int t = rest / 40;
    float c = cosb[t * 32 + d];
    float s = sinb[t * 32 + d];
    float* base = g_qkv + (size_t)t * QKVn + hh * 64 + d;
    float x1 = base[0];
    float x2 = base[32];
    base[0] = x1 * c - x2 * s;
    base[32] = x2 * c + x1 * s;
}

__global__ void k_scores() {
    const int kt = blockIdx.x, qt = blockIdx.y, h = blockIdx.z;
    const int tid = threadIdx.x;
    const int tx = tid & 15, ty = tid >> 4;

    if (kt > qt) {
#pragma unroll
        for (int i = 0; i < 4; i++)
#pragma unroll
            for (int j = 0; j < 4; j++) {
                int q = qt * 64 + ty * 4 + i;
                int k = kt * 64 + tx * 4 + j;
                g_scores[((size_t)h * Tn + q) * Tn + k] = -1e30f;
            }
        return;
    }

    __shared__ float Qs[64][65];
    __shared__ float Ks[64][65];
    const int lr = tid >> 2;
    const int lc = (tid & 3) * 16;
    const int kvh = h >> 2;
#pragma unroll
    for (int ch = 0; ch < 4; ch++) {
        float4 qv = *(const float4*)(g_qkv + (size_t)(qt * 64 + lr) * QKVn + h * 64 + lc + ch * 4);
        Qs[lr][lc + ch * 4 + 0] = qv.x; Qs[lr][lc + ch * 4 + 1] = qv.y;
        Qs[lr][lc + ch * 4 + 2] = qv.z; Qs[lr][lc + ch * 4 + 3] = qv.w;
        float4 kv = *(const float4*)(g_qkv + (size_t)(kt * 64 + lr) * QKVn + 2048 + kvh * 64 + lc + ch * 4);
        Ks[lr][lc + ch * 4 + 0] = kv.x; Ks[lr][lc + ch * 4 + 1] = kv.y;
        Ks[lr][lc + ch * 4 + 2] = kv.z; Ks[lr][lc + ch * 4 + 3] = kv.w;
    }
    __syncthreads();

    float acc[4][4];
#pragma unroll
    for (int i = 0; i < 4; i++)
#pragma unroll
        for (int j = 0; j < 4; j++) acc[i][j] = 0.f;

#pragma unroll 8
    for (int kk = 0; kk < 64; kk++) {
        float ra[4], rb[4];
#pragma unroll
        for (int i = 0; i < 4; i++) ra[i] = Qs[ty * 4 + i][kk];
#pragma unroll
        for (int j = 0; j < 4; j++) rb[j] = Ks[tx * 4 + j][kk];
#pragma unroll
        for (int i = 0; i < 4; i++)
#pragma unroll
            for (int j = 0; j < 4; j++) acc[i][j] += ra[i] * rb[j];
    }

    const float scale = 0.125f;
#pragma unroll
    for (int i = 0; i < 4; i++)
#pragma unroll
        for (int j = 0; j < 4; j++) {
            int q = qt * 64 + ty * 4 + i;
            int k = kt * 64 + tx * 4 + j;
            float v = (k <= q) ? acc[i][j] * scale : -1e30f;
            g_scores[((size_t)h * Tn + q) * Tn + k] = v;
        }
}

__global__ void k_softmax() {
    const int row = blockIdx.x;
    float* p = g_scores + (size_t)row * Tn;
    const int tid = threadIdx.x;
    float v[4];
    float mx = -3.4e38f;
#pragma unroll
    for (int j = 0; j < 4; j++) {
        v[j] = p[tid + j * 128];
        mx = fmaxf(mx, v[j]);
    }
#pragma unroll
    for (int o = 16; o > 0; o >>= 1) mx = fmaxf(mx, __shfl_xor_sync(0xffffffffu, mx, o));
    __shared__ float rm[4];
    if ((tid & 31) == 0) rm[tid >> 5] = mx;
    __syncthreads();
    mx = fmaxf(fmaxf(rm[0], rm[1]), fmaxf(rm[2], rm[3]));
    float sum = 0.f;
#pragma unroll
    for (int j = 0; j < 4; j++) {
        v[j] = __expf(v[j] - mx);
        sum += v[j];
    }
#pragma unroll
    for (int o = 16; o > 0; o >>= 1) sum += __shfl_xor_sync(0xffffffffu, sum, o);
    __shared__ float rs[4];
    if ((tid & 31) == 0) rs[tid >> 5] = sum;
    __syncthreads();
    sum = rs[0] + rs[1] + rs[2] + rs[3];
    float inv = 1.f / sum;
#pragma unroll
    for (int j = 0; j < 4; j++) p[tid + j * 128] = v[j] * inv;
}

__global__ void k_attnv() {
    const int qt = blockIdx.x, h = blockIdx.y;
    const int tid = threadIdx.x;
    const int tx = tid & 15, ty = tid >> 4;
    const int lr = tid >> 2;
    const int lc = (tid & 3) * 16;
    const int kvh = h >> 2;

    __shared__ float Ps[64][65];
    __shared__ float Vs[64][65];
    float acc[4][4];
#pragma unroll
    for (int i = 0; i < 4; i++)
#pragma unroll
        for (int j = 0; j < 4; j++) acc[i][j] = 0.f;

    for (int kt = 0; kt <= qt; kt++) {
#pragma unroll
        for (int ch = 0; ch < 4; ch++) {
            float4 pv = *(const float4*)(g_scores + ((size_t)h * Tn + qt * 64 + lr) * Tn + kt * 64 + lc + ch * 4);
            Ps[lr][lc + ch * 4 + 0] = pv.x; Ps[lr][lc + ch * 4 + 1] = pv.y;
            Ps[lr][lc + ch * 4 + 2] = pv.z; Ps[lr][lc + ch * 4 + 3] = pv.w;
            float4 vv = *(const float4*)(g_qkv + (size_t)(kt * 64 + lr) * QKVn + 2560 + kvh * 64 + lc + ch * 4);
            Vs[lr][lc + ch * 4 + 0] = vv.x; Vs[lr][lc + ch * 4 + 1] = vv.y;
            Vs[lr][lc + ch * 4 + 2] = vv.z; Vs[lr][lc + ch * 4 + 3] = vv.w;
        }
        __syncthreads();
#pragma unroll 8
        for (int kk = 0; kk < 64; kk++) {
            float ra[4], rb[4];
#pragma unroll
            for (int i = 0; i < 4; i++) ra[i] = Ps[ty * 4 + i][kk];
#pragma unroll
            for (int j = 0; j < 4; j++) rb[j] = Vs[kk][tx * 4 + j];
#pragma unroll
            for (int i = 0; i < 4; i++)
#pragma unroll
                for (int j = 0; j < 4; j++) acc[i][j] += ra[i] * rb[j];
        }
        __syncthreads();
    }

#pragma unroll
    for (int i = 0; i < 4; i++)
#pragma unroll
        for (int j = 0; j < 4; j++) {
            int q = qt * 64 + ty * 4 + i;
            g_attn[(size_t)q * Dn + h * 64 + tx * 4 + j] = acc[i][j];
        }
}

__global__ void k_gate(const float* __restrict__ gw) {
    const int t = blockIdx.x;
    const int warp = threadIdx.x >> 5, lane = threadIdx.x & 31;
    const float* xr = g_x2 + (size_t)t * Dn;
    const float* wr = gw + (size_t)warp * Dn;
    float s = 0.f;
    for (int c = lane; c < Dn; c += 32) s += xr[c] * wr[c];
#pragma unroll
    for (int o = 16; o > 0; o >>= 1) s += __shfl_xor_sync(0xffffffffu, s, o);
    __shared__ float lg[En];
    if (lane == 0) lg[warp] = s;
    __syncthreads();
    if (threadIdx.x == 0) {
        int i0 = 0;
        for (int e = 1; e < En; e++) if (lg[e] > lg[i0]) i0 = e;
        int i1 = (i0 == 0) ? 1 : 0;
        for (int e = 0; e < En; e++) if (e != i0 && lg[e] > lg[i1]) i1 = e;
        float w1v = __expf(lg[i1] - lg[i0]);
        float inv = 1.f / (1.f + w1v);
        float w0 = inv, w1n = w1v * inv;
        int p0 = atomicAdd(&g_cnt[i0], 1);
        g_tok[i0 * Tn + p0] = t; g_wgt[i0 * Tn + p0] = w0; g_slot[i0 * Tn + p0] = 0;
        int p1 = atomicAdd(&g_cnt[i1], 1);
        g_tok[i1 * Tn + p1] = t; g_wgt[i1 * Tn + p1] = w1n; g_slot[i1 * Tn + p1] = 1;
    }
}

__global__ void k_act() {
    const int e = blockIdx.y >> 9;
    const int pos = blockIdx.y & 511;
    if (pos >= g_cnt[e]) return;
    const int col = blockIdx.x * 256 + threadIdx.x;
    const size_t idx = (size_t)blockIdx.y * In + col;
    float a = g_h1[idx];
    float b = g_h3[idx];
    g_h1[idx] = (a / (1.f + __expf(-a))) * b;
}

// moe_out = sum of 4 eo slots (2 experts x 2 K-halves)
__global__ void k_combine(float* __restrict__ out) {
    int i = blockIdx.x * 256 + threadIdx.x;
    if (i >= Tn * Dn) return;
    int t = i / Dn;
    int d = i - t * Dn;
    const float* base = g_eo + (size_t)t * 4 * Dn + d;
    out[i] = base[0] + base[Dn] + base[2 * Dn] + base[3 * Dn];
}

// ---------------- launch ----------------
extern "C" void kernel_launch(void* const* d_in, const int* in_sizes, int n_in,
                              void* d_out, int out_size) {
    const float* hs   = (const float*)d_in[0];
    const float* resi = (const float*)d_in[1];
    const float* cosb = (const float*)d_in[2];
    const float* sinb = (const float*)d_in[3];
    const float* ln1  = (const float*)d_in[4];
    const float* ln2  = (const float*)d_in[5];
    const float* wqkv = (const float*)d_in[6];
    const float* wo   = (const float*)d_in[7];
    const float* gw   = (const float*)d_in[8];
    const float* w1   = (const float*)d_in[9];
    const float* w3   = (const float*)d_in[10];
    const float* w2   = (const float*)d_in[11];

    float* out = (float*)d_out;
    float* moe_out = out;
    float* res2 = out + Tn * Dn;

    void *px, *pattn, *px2, *ph1, *ph3, *peo;
    cudaGetSymbolAddress(&px, g_x);
    cudaGetSymbolAddress(&pattn, g_attn);
    cudaGetSymbolAddress(&px2, g_x2);
    cudaGetSymbolAddress(&ph1, g_h1);
    cudaGetSymbolAddress(&ph3, g_h3);
    cudaGetSymbolAddress(&peo, g_eo);

    constexpr int SMEM128 = 3 * (128 * PAD + 128 * PAD) * 4;  // 110592
    constexpr int SMEM256 = 3 * (128 * PAD + 256 * PAD) * 4;  // 165888
    cudaFuncSetAttribute(k_gemm<0, 128, 2>, cudaFuncAttributeMaxDynamicSharedMemorySize, SMEM128);
    cudaFuncSetAttribute(k_gemm<1, 256, 1>, cudaFuncAttributeMaxDynamicSharedMemorySize, SMEM256);
    cudaFuncSetAttribute(k_gemm<2, 256, 2>, cudaFuncAttributeMaxDynamicSharedMemorySize, SMEM256);

    k_zero_cnt<<<1, 32>>>();
    k_add_rmsnorm<<<Tn, 256>>>(hs, resi, ln1);

    // qkv partials: [2][512][3072] into g_eo, then sum + rope
    k_gemm<0, 128, 2><<<dim3(QKVn / 128, Tn / 128, 2), 512, SMEM128>>>(
        (const float*)px, wqkv, nullptr, (float*)peo, nullptr, Tn, QKVn, Dn);
    k_addqkv<<<(Tn * QKVn) / 256, 256>>>((const float*)peo);
    k_rope<<<(Tn * 40 * 32) / 256, 256>>>(cosb, sinb);

    k_scores<<<dim3(Tn / 64, Tn / 64, Hn), 256>>>();
    k_softmax<<<Hn * Tn, 128>>>();
    k_attnv<<<dim3(Tn / 64, Hn), 256>>>();

    // attn @ wo^T partials: [2][512][2048] into g_eo; fused add + rmsnorm
    k_gemm<0, 128, 2><<<dim3(Dn / 128, Tn / 128, 2), 512, SMEM128>>>(
        (const float*)pattn, wo, nullptr, (float*)peo, nullptr, Tn, Dn, Dn);
    k_add2_rmsnorm<<<Tn, 256>>>((const float*)peo, (const float*)peo + Tn * Dn, ln2, res2);
    k_gate<<<Tn, 256>>>(gw);

    // fused w1/w3 grouped GEMM: x grid covers [w1 | w3]
    k_gemm<1, 256, 1><<<dim3(2 * In / 256, Tn / 128, En), 512, SMEM256>>>(
        (const float*)px2, w1, w3, (float*)ph1, (float*)ph3, Tn, In, Dn);
    k_act<<<dim3(In / 256, En * Tn), 256>>>();
    // w2 grouped GEMM, split-K2, scatter into 4-slot eo
    k_gemm<2, 256, 2><<<dim3(Dn / 256, Tn / 128, En * 2), 512, SMEM256>>>(
        (const float*)ph1, w2, nullptr, (float*)peo, nullptr, Tn, Dn, In);
    k_combine<<<(Tn * Dn) / 256, 256>>>(moe_out);
}

// round 7
// speedup vs baseline: 7.8486x; 1.5774x over previous
#include <cuda_runtime.h>
#include <cuda_fp16.h>
#include <math.h>
#include <stdint.h>

#define Tn 512
#define Dn 2048
#define Hn 32
#define KVn 8
#define DHn 64
#define In 7168
#define En 8
#define QKVn 3072   // (H + 2*KV) * DH
#define PAD 40      // smem row stride in 32-bit words (conflict-free fragment loads)

// ---------------- scratch (device globals; no allocation allowed) ----------------
__device__ __align__(16) float g_res1[Tn * Dn];
__device__ __align__(16) float g_x[Tn * Dn];
__device__ __align__(16) float g_qkv[Tn * QKVn];
__device__ __align__(16) float g_scores[Hn * Tn * Tn];
__device__ __align__(16) float g_attn[Tn * Dn];
__device__ __align__(16) float g_x2[Tn * Dn];
__device__ __align__(16) float g_h1[En * Tn * In];
__device__ __align__(16) float g_h3[En * Tn * In];
__device__ __align__(16) float g_eo[Tn * 4 * Dn];   // partial/scatter scratch (16 MB)
__device__ int   g_tok[En * Tn];
__device__ float g_wgt[En * Tn];
__device__ int   g_slot[En * Tn];
__device__ int   g_cnt[En];

// ================= helpers (sm_80-level features only) =================
__device__ __forceinline__ uint32_t smem_u32(const void* p) {
    uint32_t a;
    asm("{ .reg .u64 t; cvta.to.shared.u64 t, %1; cvt.u32.u64 %0, t; }" : "=r"(a) : "l"(p));
    return a;
}
__device__ __forceinline__ uint32_t pack_h2(float2 v) {
    __half2 h = __floats2half2_rn(v.x, v.y);
    return *reinterpret_cast<uint32_t*>(&h);
}
__device__ __forceinline__ void mma_f16(float* c, const uint32_t* a, const uint32_t* b) {
    asm volatile(
        "mma.sync.aligned.m16n8k16.row.col.f32.f16.f16.f32 "
        "{%0,%1,%2,%3}, {%4,%5,%6,%7}, {%8,%9}, {%0,%1,%2,%3};"
        : "+f"(c[0]), "+f"(c[1]), "+f"(c[2]), "+f"(c[3])
        : "r"(a[0]), "r"(a[1]), "r"(a[2]), "r"(a[3]), "r"(b[0]), "r"(b[1]));
}
__device__ __forceinline__ void cp_async16(uint32_t saddr, const void* gaddr) {
    asm volatile("cp.async.cg.shared.global [%0], [%1], 16;" :: "r"(saddr), "l"(gaddr));
}
#define CP_COMMIT() asm volatile("cp.async.commit_group;" ::: "memory")
#define CP_WAIT1()  asm volatile("cp.async.wait_group 1;" ::: "memory")

// ================= fp16-input tensor-core GEMM: C[M,N] = A[M,K] * B[N,K]^T =================
// Inputs staged fp32 in SMEM via cp.async; converted to fp16 (rn) at fragment load.
// fp32 accumulate. MODE 0: plain split-K partials. MODE 1: MoE gemm1 fused w1/w3
// (row gather). MODE 2: MoE gemm2 split-K2 weighted scatter.
// Tile 128 x NT, BK=32, 512 threads (16 warps of 32 x NT/4), 3-stage cp.async.
template <int MODE, int NT, int KSPLIT>
__global__ void __launch_bounds__(512, 1) k_gemm(const float* __restrict__ A,
                                                 const float* __restrict__ B,
                                                 const float* __restrict__ B2,
                                                 float* __restrict__ C,
                                                 float* __restrict__ C2,
                                                 int M, int N, int Kstride) {
    constexpr int BNT = NT / 32;                 // warp n-subtiles (8 cols each)
    constexpr int WN = NT / 4;                   // warp n extent
    constexpr int A_WORDS = 128 * PAD;
    constexpr int B_WORDS = NT * PAD;
    constexpr int STAGE_WORDS = A_WORDS + B_WORDS;
    constexpr int BCH = NT / 64;                 // B 16B-chunks per thread per stage

    const int kh = (MODE == 2) ? (int)(blockIdx.z & 1) : ((MODE == 0) ? (int)blockIdx.z : 0);
    const int e  = (MODE == 0) ? 0 : ((MODE == 2) ? (int)(blockIdx.z >> 1) : (int)blockIdx.z);
    const int cnt = (MODE == 0) ? M : g_cnt[e];
    const int bm = blockIdx.y * 128;
    if (bm >= cnt) return;
    int bn = blockIdx.x * NT;

    const float* Bp = B;
    float* Cp = C;
    if (MODE == 1 && bn >= N) { Bp = B2; Cp = C2; bn -= N; }
    if (MODE != 0) Bp += (size_t)e * N * Kstride;

    const int Klen = Kstride / KSPLIT;
    const int koff = kh * Klen;

    const int tid = threadIdx.x;
    const int wid = tid >> 5, lane = tid & 31;
    const int g = lane >> 2, t4 = lane & 3;
    const int wm = (wid & 3) * 32, wn = (wid >> 2) * WN;

    // rows this warp actually needs, in 16-row MMA groups (max 2)
    const int rows_avail = cnt - bm - wm;
    const int mtact = (rows_avail >= 32) ? 2 : ((rows_avail <= 0) ? 0 : ((rows_avail + 15) >> 4));

    extern __shared__ float sm[];
    const uint32_t smBase = smem_u32(sm);

    // ---- A source pointers (2 chunks of 16B per thread per stage) ----
    const float* aSrc[2];
#pragma unroll
    for (int i = 0; i < 2; i++) {
        int chunk = tid + i * 512;
        int row = chunk >> 3, c = chunk & 7;
        if (MODE == 0) {
            int ridx = bm + row; if (ridx >= M) ridx = M - 1;
            aSrc[i] = A + (size_t)ridx * Kstride + c * 4 + koff;
        } else if (MODE == 1) {
            int idx = bm + row;
            int tok = (idx < cnt) ? g_tok[e * Tn + idx] : g_tok[e * Tn];
            aSrc[i] = A + (size_t)tok * Kstride + c * 4 + koff;
        } else {
            int idx = bm + row;
            aSrc[i] = A + ((size_t)e * Tn + idx) * (size_t)Kstride + c * 4 + koff;
        }
    }

#define ISSUE_STAGE(ktn)                                                            \
    do {                                                                            \
        const int k0 = (ktn) * 32;                                                  \
        const uint32_t sb = smBase + ((ktn) % 3) * (uint32_t)(STAGE_WORDS * 4);     \
        _Pragma("unroll")                                                           \
        for (int i = 0; i < 2; i++) {                                               \
            int chunk = tid + i * 512;                                              \
            int row = chunk >> 3, c = chunk & 7;                                    \
            cp_async16(sb + (uint32_t)(row * PAD + c * 4) * 4u, aSrc[i] + k0);      \
        }                                                                           \
        _Pragma("unroll")                                                           \
        for (int i = 0; i < BCH; i++) {                                             \
            int chunk = tid + i * 512;                                              \
            int row = chunk >> 3, c = chunk & 7;                                    \
            const float* gp = Bp + (size_t)(bn + row) * Kstride + c * 4 + koff + k0;\
            cp_async16(sb + (uint32_t)(A_WORDS + row * PAD + c * 4) * 4u, gp);      \
        }                                                                           \
    } while (0)

    float acc[2][BNT][4];
#pragma unroll
    for (int mt = 0; mt < 2; mt++)
#pragma unroll
        for (int nt = 0; nt < BNT; nt++)
#pragma unroll
            for (int q = 0; q < 4; q++) acc[mt][nt][q] = 0.f;

    ISSUE_STAGE(0); CP_COMMIT();
    ISSUE_STAGE(1); CP_COMMIT();

    const int KT = Klen / 32;
    for (int kt = 0; kt < KT; kt++) {
        CP_WAIT1();
        __syncthreads();
        if (kt + 2 < KT) ISSUE_STAGE(kt + 2);
        CP_COMMIT();

        const float* as = sm + (kt % 3) * STAGE_WORDS;
        const float* bs = as + A_WORDS;
#pragma unroll
        for (int ks = 0; ks < 2; ks++) {          // two k16 steps per BK=32
            const int ko = ks * 16 + 2 * t4;
            uint32_t af[2][4], bf[BNT][2];
#pragma unroll
            for (int mt = 0; mt < 2; mt++) {
                if (mt < mtact) {
                    const float* ar0 = &as[(wm + mt * 16 + g) * PAD + ko];
                    const float* ar8 = ar0 + 8 * PAD;
                    float2 a00 = *(const float2*)ar0;          // (g,   k..k+1)
                    float2 a01 = *(const float2*)(ar0 + 8);    // (g,   k+8..k+9)
                    float2 a10 = *(const float2*)ar8;          // (g+8, k..k+1)
                    float2 a11 = *(const float2*)(ar8 + 8);    // (g+8, k+8..k+9)
                    af[mt][0] = pack_h2(a00);
                    af[mt][1] = pack_h2(a10);
                    af[mt][2] = pack_h2(a01);
                    af[mt][3] = pack_h2(a11);
                }
            }
            if (mtact > 0) {
#pragma unroll
                for (int nt = 0; nt < BNT; nt++) {
                    const float* br = &bs[(wn + nt * 8 + g) * PAD + ko];
                    bf[nt][0] = pack_h2(*(const float2*)br);
                    bf[nt][1] = pack_h2(*(const float2*)(br + 8));
                }
#pragma unroll
                for (int mt = 0; mt < 2; mt++) {
                    if (mt < mtact) {
#pragma unroll
                        for (int nt = 0; nt < BNT; nt++)
                            mma_f16(acc[mt][nt], af[mt], bf[nt]);
                    }
                }
            }
        }
        __syncthreads();
    }
#undef ISSUE_STAGE

    // -------- epilogue: registers -> gmem --------
#pragma unroll
    for (int mt = 0; mt < 2; mt++) {
        if (mt >= mtact) continue;
#pragma unroll
        for (int h = 0; h < 2; h++) {
            const int ridx = bm + wm + mt * 16 + g + h * 8;
            bool valid;
            float* dst = nullptr;
            float wg = 1.f;
            if (MODE == 0) {
                valid = ridx < M;
                if (valid) dst = Cp + (size_t)kh * M * N + (size_t)ridx * N;
            } else if (MODE == 1) {
                valid = ridx < cnt;
                if (valid) dst = Cp + ((size_t)e * Tn + ridx) * (size_t)N;
            } else {
                valid = ridx < cnt;
                if (valid) {
                    int idx = e * Tn + ridx;
                    int tok = g_tok[idx];
                    wg = g_wgt[idx];
                    int sl = g_slot[idx];
                    dst = Cp + ((size_t)tok * 4 + sl * 2 + kh) * (size_t)Dn;
                }
            }
            if (!valid) continue;
#pragma unroll
            for (int nt = 0; nt < BNT; nt++) {
                const int col = bn + wn + nt * 8 + 2 * t4;
                float2 v = make_float2(acc[mt][nt][h * 2 + 0], acc[mt][nt][h * 2 + 1]);
                if (MODE == 2) { v.x *= wg; v.y *= wg; }
                *(float2*)(dst + col) = v;
            }
        }
    }
}

// ---------------- small utility kernels ----------------

__global__ void k_zero_cnt() {
    if (threadIdx.x < En) g_cnt[threadIdx.x] = 0;
}

// res1 = h + r;  x = rmsnorm(res1, w)
__global__ void k_add_rmsnorm(const float* __restrict__ h, const float* __restrict__ r,
                              const float* __restrict__ w) {
    int t = blockIdx.x;
    const float* hr = h + t * Dn;
    const float* rr = r + t * Dn;
    float* resr = g_res1 + t * Dn;
    float* xr = g_x + t * Dn;

    float v[8];
    float local = 0.f;
#pragma unroll
    for (int j = 0; j < 8; j++) {
        int c = threadIdx.x + j * 256;
        float s = hr[c] + rr[c];
        v[j] = s;
        resr[c] = s;
        local += s * s;
    }
#pragma unroll
    for (int o = 16; o > 0; o >>= 1) local += __shfl_xor_sync(0xffffffffu, local, o);
    __shared__ float red[8];
    if ((threadIdx.x & 31) == 0) red[threadIdx.x >> 5] = local;
    __syncthreads();
    __shared__ float inv;
    if (threadIdx.x == 0) {
        float s = 0.f;
#pragma unroll
        for (int i = 0; i < 8; i++) s += red[i];
        inv = rsqrtf(s / (float)Dn + 1e-5f);
    }
    __syncthreads();
    float iv = inv;
#pragma unroll
    for (int j = 0; j < 8; j++) {
        int c = threadIdx.x + j * 256;
        xr[c] = v[j] * iv * w[c];
    }
}

// res2 = p0 + p1 + res1 (written to out); x2 = rmsnorm(res2, w)
__global__ void k_add2_rmsnorm(const float* __restrict__ p0, const float* __restrict__ p1,
                               const float* __restrict__ w, float* __restrict__ res2out) {
    int t = blockIdx.x;
    const float* a0 = p0 + t * Dn;
    const float* a1 = p1 + t * Dn;
    const float* rr = g_res1 + t * Dn;
    float* ro = res2out + t * Dn;
    float* xr = g_x2 + t * Dn;
    float v[8];
    float local = 0.f;
#pragma unroll
    for (int j = 0; j < 8; j++) {
        int c = threadIdx.x + j * 256;
        float s = a0[c] + a1[c] + rr[c];
        v[j] = s;
        ro[c] = s;
        local += s * s;
    }
#pragma unroll
    for (int o = 16; o > 0; o >>= 1) local += __shfl_xor_sync(0xffffffffu, local, o);
    __shared__ float red[8];
    if ((threadIdx.x & 31) == 0) red[threadIdx.x >> 5] = local;
    __syncthreads();
    __shared__ float inv;
    if (threadIdx.x == 0) {
        float s = 0.f;
#pragma unroll
        for (int i = 0; i < 8; i++) s += red[i];
        inv = rsqrtf(s / (float)Dn + 1e-5f);
    }
    __syncthreads();
    float iv = inv;
#pragma unroll
    for (int j = 0; j < 8; j++) {
        int c = threadIdx.x + j * 256;
        xr[c] = v[j] * iv * w[c];
    }
}

// qkv = p0 + p1 (split-K partial sum)
__global__ void k_addqkv(const float* __restrict__ p) {
    int i = blockIdx.x * 256 + threadIdx.x;
    if (i >= Tn * QKVn) return;
    g_qkv[i] = p[i] + p[i + Tn * QKVn];
}

__global__ void k_rope(const float* __restrict__ cosb, const float* __restrict__ sinb) {
    int idx = blockIdx.x * 256 + threadIdx.x;
    if (idx >= Tn * 40 * 32) return;
    int d = idx & 31;
    int rest = idx >> 5;
    int hh = rest % 40;
    int t = rest / 40;
    float c = cosb[t * 32 + d];
    float s = sinb[t * 32 + d];
    float* base = g_qkv + (size_t)t * QKVn + hh * 64 + d;
    float x1 = base[0];
    float x2 = base[32];
    base[0] = x1 * c - x2 * s;
    base[32] = x2 * c + x1 * s;
}

__global__ void k_scores() {
    const int kt = blockIdx.x, qt = blockIdx.y, h = blockIdx.z;
    const int tid = threadIdx.x;
    const int tx = tid & 15, ty = tid >> 4;

    if (kt > qt) {
#pragma unroll
        for (int i = 0; i < 4; i++)
#pragma unroll
            for (int j = 0; j < 4; j++) {
                int q = qt * 64 + ty * 4 + i;
                int k = kt * 64 + tx * 4 + j;
                g_scores[((size_t)h * Tn + q) * Tn + k] = -1e30f;
            }
        return;
    }

    __shared__ float Qs[64][65];
    __shared__ float Ks[64][65];
    const int lr = tid >> 2;
    const int lc = (tid & 3) * 16;
    const int kvh = h >> 2;
#pragma unroll
    for (int ch = 0; ch < 4; ch++) {
        float4 qv = *(const float4*)(g_qkv + (size_t)(qt * 64 + lr) * QKVn + h * 64 + lc + ch * 4);
        Qs[lr][lc + ch * 4 + 0] = qv.x; Qs[lr][lc + ch * 4 + 1] = qv.y;
        Qs[lr][lc + ch * 4 + 2] = qv.z; Qs[lr][lc + ch * 4 + 3] = qv.w;
        float4 kv = *(const float4*)(g_qkv + (size_t)(kt * 64 + lr) * QKVn + 2048 + kvh * 64 + lc + ch * 4);
        Ks[lr][lc + ch * 4 + 0] = kv.x; Ks[lr][lc + ch * 4 + 1] = kv.y;
        Ks[lr][lc + ch * 4 + 2] = kv.z; Ks[lr][lc + ch * 4 + 3] = kv.w;
    }
    __syncthreads();

    float acc[4][4];
#pragma unroll
    for (int i = 0; i < 4; i++)
#pragma unroll
        for (int j = 0; j < 4; j++) acc[i][j] = 0.f;

#pragma unroll 8
    for (int kk = 0; kk < 64; kk++) {
        float ra[4], rb[4];
#pragma unroll
        for (int i = 0; i < 4; i++) ra[i] = Qs[ty * 4 + i][kk];
#pragma unroll
        for (int j = 0; j < 4; j++) rb[j] = Ks[tx * 4 + j][kk];
#pragma unroll
        for (int i = 0; i < 4; i++)
#pragma unroll
            for (int j = 0; j < 4; j++) acc[i][j] += ra[i] * rb[j];
    }

    const float scale = 0.125f;
#pragma unroll
    for (int i = 0; i < 4; i++)
#pragma unroll
        for (int j = 0; j < 4; j++) {
            int q = qt * 64 + ty * 4 + i;
            int k = kt * 64 + tx * 4 + j;
            float v = (k <= q) ? acc[i][j] * scale : -1e30f;
            g_scores[((size_t)h * Tn + q) * Tn + k] = v;
        }
}

__global__ void k_softmax() {
    const int row = blockIdx.x;
    float* p = g_scores + (size_t)row * Tn;
    const int tid = threadIdx.x;
    float v[4];
    float mx = -3.4e38f;
#pragma unroll
    for (int j = 0; j < 4; j++) {
        v[j] = p[tid + j * 128];
        mx = fmaxf(mx, v[j]);
    }
#pragma unroll
    for (int o = 16; o > 0; o >>= 1) mx = fmaxf(mx, __shfl_xor_sync(0xffffffffu, mx, o));
    __shared__ float rm[4];
    if ((tid & 31) == 0) rm[tid >> 5] = mx;
    __syncthreads();
    mx = fmaxf(fmaxf(rm[0], rm[1]), fmaxf(rm[2], rm[3]));
    float sum = 0.f;
#pragma unroll
    for (int j = 0; j < 4; j++) {
        v[j] = __expf(v[j] - mx);
        sum += v[j];
    }
#pragma unroll
    for (int o = 16; o > 0; o >>= 1) sum += __shfl_xor_sync(0xffffffffu, sum, o);
    __shared__ float rs[4];
    if ((tid & 31) == 0) rs[tid >> 5] = sum;
    __syncthreads();
    sum = rs[0] + rs[1] + rs[2] + rs[3];
    float inv = 1.f / sum;
#pragma unroll
    for (int j = 0; j < 4; j++) p[tid + j * 128] = v[j] * inv;
}

__global__ void k_attnv() {
    const int qt = blockIdx.x, h = blockIdx.y;
    const int tid = threadIdx.x;
    const int tx = tid & 15, ty = tid >> 4;
    const int lr = tid >> 2;
    const int lc = (tid & 3) * 16;
    const int kvh = h >> 2;

    __shared__ float Ps[64][65];
    __shared__ float Vs[64][65];
    float acc[4][4];
#pragma unroll
    for (int i = 0; i < 4; i++)
#pragma unroll
        for (int j = 0; j < 4; j++) acc[i][j] = 0.f;

    for (int kt = 0; kt <= qt; kt++) {
#pragma unroll
        for (int ch = 0; ch < 4; ch++) {
            float4 pv = *(const float4*)(g_scores + ((size_t)h * Tn + qt * 64 + lr) * Tn + kt * 64 + lc + ch * 4);
            Ps[lr][lc + ch * 4 + 0] = pv.x; Ps[lr][lc + ch * 4 + 1] = pv.y;
            Ps[lr][lc + ch * 4 + 2] = pv.z; Ps[lr][lc + ch * 4 + 3] = pv.w;
            float4 vv = *(const float4*)(g_qkv + (size_t)(kt * 64 + lr) * QKVn + 2560 + kvh * 64 + lc + ch * 4);
            Vs[lr][lc + ch * 4 + 0] = vv.x; Vs[lr][lc + ch * 4 + 1] = vv.y;
            Vs[lr][lc + ch * 4 + 2] = vv.z; Vs[lr][lc + ch * 4 + 3] = vv.w;
        }
        __syncthreads();
#pragma unroll 8
        for (int kk = 0; kk < 64; kk++) {
            float ra[4], rb[4];
#pragma unroll
            for (int i = 0; i < 4; i++) ra[i] = Ps[ty * 4 + i][kk];
#pragma unroll
            for (int j = 0; j < 4; j++) rb[j] = Vs[kk][tx * 4 + j];
#pragma unroll
            for (int i = 0; i < 4; i++)
#pragma unroll
                for (int j = 0; j < 4; j++) acc[i][j] += ra[i] * rb[j];
        }
        __syncthreads();
    }

#pragma unroll
    for (int i = 0; i < 4; i++)
#pragma unroll
        for (int j = 0; j < 4; j++) {
            int q = qt * 64 + ty * 4 + i;
            g_attn[(size_t)q * Dn + h * 64 + tx * 4 + j] = acc[i][j];
        }
}

__global__ void k_gate(const float* __restrict__ gw) {
    const int t = blockIdx.x;
    const int warp = threadIdx.x >> 5, lane = threadIdx.x & 31;
    const float* xr = g_x2 + (size_t)t * Dn;
    const float* wr = gw + (size_t)warp * Dn;
    float s = 0.f;
    for (int c = lane; c < Dn; c += 32) s += xr[c] * wr[c];
#pragma unroll
    for (int o = 16; o > 0; o >>= 1) s += __shfl_xor_sync(0xffffffffu, s, o);
    __shared__ float lg[En];
    if (lane == 0) lg[warp] = s;
    __syncthreads();
    if (threadIdx.x == 0) {
        int i0 = 0;
        for (int e = 1; e < En; e++) if (lg[e] > lg[i0]) i0 = e;
        int i1 = (i0 == 0) ? 1 : 0;
        for (int e = 0; e < En; e++) if (e != i0 && lg[e] > lg[i1]) i1 = e;
        float w1v = __expf(lg[i1] - lg[i0]);
        float inv = 1.f / (1.f + w1v);
        float w0 = inv, w1n = w1v * inv;
        int p0 = atomicAdd(&g_cnt[i0], 1);
        g_tok[i0 * Tn + p0] = t; g_wgt[i0 * Tn + p0] = w0; g_slot[i0 * Tn + p0] = 0;
        int p1 = atomicAdd(&g_cnt[i1], 1);
        g_tok[i1 * Tn + p1] = t; g_wgt[i1 * Tn + p1] = w1n; g_slot[i1 * Tn + p1] = 1;
    }
}

__global__ void k_act() {
    const int e = blockIdx.y >> 9;
    const int pos = blockIdx.y & 511;
    if (pos >= g_cnt[e]) return;
    const int col = blockIdx.x * 256 + threadIdx.x;
    const size_t idx = (size_t)blockIdx.y * In + col;
    float a = g_h1[idx];
    float b = g_h3[idx];
    g_h1[idx] = (a / (1.f + __expf(-a))) * b;
}

// moe_out = sum of 4 eo slots (2 experts x 2 K-halves)
__global__ void k_combine(float* __restrict__ out) {
    int i = blockIdx.x * 256 + threadIdx.x;
    if (i >= Tn * Dn) return;
    int t = i / Dn;
    int d = i - t * Dn;
    const float* base = g_eo + (size_t)t * 4 * Dn + d;
    out[i] = base[0] + base[Dn] + base[2 * Dn] + base[3 * Dn];
}

// ---------------- launch ----------------
extern "C" void kernel_launch(void* const* d_in, const int* in_sizes, int n_in,
                              void* d_out, int out_size) {
    const float* hs   = (const float*)d_in[0];
    const float* resi = (const float*)d_in[1];
    const float* cosb = (const float*)d_in[2];
    const float* sinb = (const float*)d_in[3];
    const float* ln1  = (const float*)d_in[4];
    const float* ln2  = (const float*)d_in[5];
    const float* wqkv = (const float*)d_in[6];
    const float* wo   = (const float*)d_in[7];
    const float* gw   = (const float*)d_in[8];
    const float* w1   = (const float*)d_in[9];
    const float* w3   = (const float*)d_in[10];
    const float* w2   = (const float*)d_in[11];

    float* out = (float*)d_out;
    float* moe_out = out;
    float* res2 = out + Tn * Dn;

    void *px, *pattn, *px2, *ph1, *ph3, *peo;
    cudaGetSymbolAddress(&px, g_x);
    cudaGetSymbolAddress(&pattn, g_attn);
    cudaGetSymbolAddress(&px2, g_x2);
    cudaGetSymbolAddress(&ph1, g_h1);
    cudaGetSymbolAddress(&ph3, g_h3);
    cudaGetSymbolAddress(&peo, g_eo);

    constexpr int SMEM128 = 3 * (128 * PAD + 128 * PAD) * 4;  // 122880
    constexpr int SMEM256 = 3 * (128 * PAD + 256 * PAD) * 4;  // 184320
    cudaFuncSetAttribute(k_gemm<0, 128, 2>, cudaFuncAttributeMaxDynamicSharedMemorySize, SMEM128);
    cudaFuncSetAttribute(k_gemm<1, 256, 1>, cudaFuncAttributeMaxDynamicSharedMemorySize, SMEM256);
    cudaFuncSetAttribute(k_gemm<2, 256, 2>, cudaFuncAttributeMaxDynamicSharedMemorySize, SMEM256);

    k_zero_cnt<<<1, 32>>>();
    k_add_rmsnorm<<<Tn, 256>>>(hs, resi, ln1);

    // qkv partials: [2][512][3072] into g_eo, then sum + rope
    k_gemm<0, 128, 2><<<dim3(QKVn / 128, Tn / 128, 2), 512, SMEM128>>>(
        (const float*)px, wqkv, nullptr, (float*)peo, nullptr, Tn, QKVn, Dn);
    k_addqkv<<<(Tn * QKVn) / 256, 256>>>((const float*)peo);
    k_rope<<<(Tn * 40 * 32) / 256, 256>>>(cosb, sinb);

    k_scores<<<dim3(Tn / 64, Tn / 64, Hn), 256>>>();
    k_softmax<<<Hn * Tn, 128>>>();
    k_attnv<<<dim3(Tn / 64, Hn), 256>>>();

    // attn @ wo^T partials: [2][512][2048] into g_eo; fused add + rmsnorm
    k_gemm<0, 128, 2><<<dim3(Dn / 128, Tn / 128, 2), 512, SMEM128>>>(
        (const float*)pattn, wo, nullptr, (float*)peo, nullptr, Tn, Dn, Dn);
    k_add2_rmsnorm<<<Tn, 256>>>((const float*)peo, (const float*)peo + Tn * Dn, ln2, res2);
    k_gate<<<Tn, 256>>>(gw);

    // fused w1/w3 grouped GEMM: x grid covers [w1 | w3]
    k_gemm<1, 256, 1><<<dim3(2 * In / 256, Tn / 128, En), 512, SMEM256>>>(
        (const float*)px2, w1, w3, (float*)ph1, (float*)ph3, Tn, In, Dn);
    k_act<<<dim3(In / 256, En * Tn), 256>>>();
    // w2 grouped GEMM, split-K2, scatter into 4-slot eo
    k_gemm<2, 256, 2><<<dim3(Dn / 256, Tn / 128, En * 2), 512, SMEM256>>>(
        (const float*)ph1, w2, nullptr, (float*)peo, nullptr, Tn, Dn, In);
    k_combine<<<(Tn * Dn) / 256, 256>>>(moe_out);
}

// round 8
// speedup vs baseline: 8.8056x; 1.1219x over previous
#include <cuda_runtime.h>
#include <cuda_fp16.h>
#include <math.h>
#include <stdint.h>

#define Tn 512
#define Dn 2048
#define Hn 32
#define KVn 8
#define DHn 64
#define In 7168
#define En 8
#define QKVn 3072   // (H + 2*KV) * DH
#define PAD 48      // smem row stride in words: conflict-free LDS.128 fragments

// ---------------- scratch (device globals; no allocation allowed) ----------------
__device__ __align__(16) float g_res1[Tn * Dn];
__device__ __align__(16) float g_x[Tn * Dn];
__device__ __align__(16) float g_qkv[Tn * QKVn];
__device__ __align__(16) float g_scores[Hn * Tn * Tn];
__device__ __align__(16) float g_attn[Tn * Dn];
__device__ __align__(16) float g_x2[Tn * Dn];
__device__ __align__(16) float g_h1[En * Tn * In];
__device__ __align__(16) float g_eo[Tn * 4 * Dn];   // partial/scatter scratch (16 MB)
__device__ int   g_tok[En * Tn];
__device__ float g_wgt[En * Tn];
__device__ int   g_slot[En * Tn];
__device__ int   g_cnt[En];

// ================= helpers (sm_80-level features only) =================
__device__ __forceinline__ uint32_t smem_u32(const void* p) {
    uint32_t a;
    asm("{ .reg .u64 t; cvta.to.shared.u64 t, %1; cvt.u32.u64 %0, t; }" : "=r"(a) : "l"(p));
    return a;
}
__device__ __forceinline__ uint32_t pack_h2(float x, float y) {
    __half2 h = __floats2half2_rn(x, y);
    return *reinterpret_cast<uint32_t*>(&h);
}
__device__ __forceinline__ void mma_f16(float* c, const uint32_t* a, const uint32_t* b) {
    asm volatile(
        "mma.sync.aligned.m16n8k16.row.col.f32.f16.f16.f32 "
        "{%0,%1,%2,%3}, {%4,%5,%6,%7}, {%8,%9}, {%0,%1,%2,%3};"
        : "+f"(c[0]), "+f"(c[1]), "+f"(c[2]), "+f"(c[3])
        : "r"(a[0]), "r"(a[1]), "r"(a[2]), "r"(a[3]), "r"(b[0]), "r"(b[1]));
}
__device__ __forceinline__ void cp_async16(uint32_t saddr, const void* gaddr) {
    asm volatile("cp.async.cg.shared.global [%0], [%1], 16;" :: "r"(saddr), "l"(gaddr));
}
#define CP_COMMIT() asm volatile("cp.async.commit_group;" ::: "memory")
#define CP_WAIT1()  asm volatile("cp.async.wait_group 1;" ::: "memory")

// ================= fp16-input tensor-core GEMM: C[M,N] = A[M,K] * B[N,K]^T =================
// Grid: blockIdx.x = m-tile (FASTEST -> consecutive CTAs share B tile in L2),
//       blockIdx.y = n-tile, blockIdx.z = expert / split-K.
// MODE 0: plain split-K partials.
// MODE 1: dual-B fused w1/w3 (row gather via g_tok); epilogue silu(h1)*h3 -> C.
// MODE 2: MoE gemm2 split-K2 weighted scatter to g_eo 4-slot.
// Fragments: k-slots permuted (thread t4 <-> k 4t4..4t4+3 consistently for A and B)
// so each fragment load is one LDS.128; result bit-identical to canonical order.
template <int MODE, int NT, int KSPLIT>
__global__ void __launch_bounds__(512, 1) k_gemm(const float* __restrict__ A,
                                                 const float* __restrict__ B,
                                                 const float* __restrict__ B2,
                                                 float* __restrict__ C,
                                                 float* __restrict__ C2,
                                                 int M, int N, int Kstride) {
    constexpr int BNT = NT / 32;                 // warp n-subtiles (8 cols each)
    constexpr int WN = NT / 4;                   // warp n extent
    constexpr int NB = (MODE == 1) ? 2 : 1;      // number of B matrices staged
    constexpr int A_WORDS = 128 * PAD;
    constexpr int B_WORDS = NT * PAD;            // per B matrix
    constexpr int STAGE_WORDS = A_WORDS + NB * B_WORDS;
    constexpr int BCH = NT / 64;                 // B 16B-chunks per thread per B matrix

    const int kh = (MODE == 2) ? (int)(blockIdx.z & 1) : ((MODE == 0) ? (int)blockIdx.z : 0);
    const int e  = (MODE == 0) ? 0 : ((MODE == 2) ? (int)(blockIdx.z >> 1) : (int)blockIdx.z);
    const int cnt = (MODE == 0) ? M : g_cnt[e];
    const int bm = blockIdx.x * 128;
    if (bm >= cnt) return;
    const int bn = blockIdx.y * NT;

    const float* Bp  = (MODE == 0) ? B  : B  + (size_t)e * N * Kstride;
    const float* Bp2 = (MODE == 1) ? B2 + (size_t)e * N * Kstride : nullptr;
    float* Cp = C;

    const int Klen = Kstride / KSPLIT;
    const int koff = kh * Klen;

    const int tid = threadIdx.x;
    const int wid = tid >> 5, lane = tid & 31;
    const int g = lane >> 2, t4 = lane & 3;
    const int wm = (wid & 3) * 32, wn = (wid >> 2) * WN;

    // rows this warp actually needs, in 16-row MMA groups (max 2)
    const int rows_avail = cnt - bm - wm;
    const int mtact = (rows_avail >= 32) ? 2 : ((rows_avail <= 0) ? 0 : ((rows_avail + 15) >> 4));

    extern __shared__ float sm[];
    const uint32_t smBase = smem_u32(sm);

    // ---- A source pointers (2 chunks of 16B per thread per stage) ----
    const float* aSrc[2];
#pragma unroll
    for (int i = 0; i < 2; i++) {
        int chunk = tid + i * 512;
        int row = chunk >> 3, c = chunk & 7;
        if (MODE == 0) {
            int ridx = bm + row; if (ridx >= M) ridx = M - 1;
            aSrc[i] = A + (size_t)ridx * Kstride + c * 4 + koff;
        } else if (MODE == 1) {
            int idx = bm + row;
            int tok = (idx < cnt) ? g_tok[e * Tn + idx] : g_tok[e * Tn];
            aSrc[i] = A + (size_t)tok * Kstride + c * 4 + koff;
        } else {
            int idx = bm + row;
            aSrc[i] = A + ((size_t)e * Tn + idx) * (size_t)Kstride + c * 4 + koff;
        }
    }

#define ISSUE_STAGE(ktn)                                                             \
    do {                                                                             \
        const int k0 = (ktn) * 32;                                                   \
        const uint32_t sb = smBase + ((ktn) % 3) * (uint32_t)(STAGE_WORDS * 4);      \
        _Pragma("unroll")                                                            \
        for (int i = 0; i < 2; i++) {                                                \
            int chunk = tid + i * 512;                                               \
            int row = chunk >> 3, c = chunk & 7;                                     \
            cp_async16(sb + (uint32_t)(row * PAD + c * 4) * 4u, aSrc[i] + k0);       \
        }                                                                            \
        _Pragma("unroll")                                                            \
        for (int i = 0; i < BCH; i++) {                                              \
            int chunk = tid + i * 512;                                               \
            int row = chunk >> 3, c = chunk & 7;                                     \
            const float* gp = Bp + (size_t)(bn + row) * Kstride + c * 4 + koff + k0; \
            cp_async16(sb + (uint32_t)(A_WORDS + row * PAD + c * 4) * 4u, gp);       \
        }                                                                            \
        if (MODE == 1) {                                                             \
            _Pragma("unroll")                                                        \
            for (int i = 0; i < BCH; i++) {                                          \
                int chunk = tid + i * 512;                                           \
                int row = chunk >> 3, c = chunk & 7;                                 \
                const float* gp = Bp2 + (size_t)(bn + row) * Kstride + c * 4 + koff + k0; \
                cp_async16(sb + (uint32_t)(A_WORDS + B_WORDS + row * PAD + c * 4) * 4u, gp); \
            }                                                                        \
        }                                                                            \
    } while (0)

    float acc[2][BNT][4];
    float acc2[MODE == 1 ? 2 : 1][MODE == 1 ? BNT : 1][4];
#pragma unroll
    for (int mt = 0; mt < 2; mt++)
#pragma unroll
        for (int nt = 0; nt < BNT; nt++)
#pragma unroll
            for (int q = 0; q < 4; q++) acc[mt][nt][q] = 0.f;
    if (MODE == 1) {
#pragma unroll
        for (int mt = 0; mt < 2; mt++)
#pragma unroll
            for (int nt = 0; nt < BNT; nt++)
#pragma unroll
                for (int q = 0; q < 4; q++) acc2[mt][nt][q] = 0.f;
    }

    ISSUE_STAGE(0); CP_COMMIT();
    ISSUE_STAGE(1); CP_COMMIT();

    const int KT = Klen / 32;
    for (int kt = 0; kt < KT; kt++) {
        CP_WAIT1();
        __syncthreads();
        if (kt + 2 < KT) ISSUE_STAGE(kt + 2);
        CP_COMMIT();

        const float* as = sm + (kt % 3) * STAGE_WORDS;
        const float* bs = as + A_WORDS;
        const float* bs2 = bs + B_WORDS;
#pragma unroll
        for (int ks = 0; ks < 2; ks++) {          // two k16 steps per BK=32
            const int ko = ks * 16 + 4 * t4;      // permuted k-slot base
            uint32_t af[2][4], bf[BNT][2];
#pragma unroll
            for (int mt = 0; mt < 2; mt++) {
                if (mt < mtact) {
                    float4 va0 = *(const float4*)&as[(wm + mt * 16 + g) * PAD + ko];
                    float4 va1 = *(const float4*)&as[(wm + mt * 16 + g + 8) * PAD + ko];
                    af[mt][0] = pack_h2(va0.x, va0.y);
                    af[mt][1] = pack_h2(va1.x, va1.y);
                    af[mt][2] = pack_h2(va0.z, va0.w);
                    af[mt][3] = pack_h2(va1.z, va1.w);
                }
            }
            if (mtact > 0) {
#pragma unroll
                for (int nt = 0; nt < BNT; nt++) {
                    float4 vb = *(const float4*)&bs[(wn + nt * 8 + g) * PAD + ko];
                    bf[nt][0] = pack_h2(vb.x, vb.y);
                    bf[nt][1] = pack_h2(vb.z, vb.w);
                }
#pragma unroll
                for (int mt = 0; mt < 2; mt++) {
                    if (mt < mtact) {
#pragma unroll
                        for (int nt = 0; nt < BNT; nt++)
                            mma_f16(acc[mt][nt], af[mt], bf[nt]);
                    }
                }
                if (MODE == 1) {
                    uint32_t bg[BNT][2];
#pragma unroll
                    for (int nt = 0; nt < BNT; nt++) {
                        float4 vb = *(const float4*)&bs2[(wn + nt * 8 + g) * PAD + ko];
                        bg[nt][0] = pack_h2(vb.x, vb.y);
                        bg[nt][1] = pack_h2(vb.z, vb.w);
                    }
#pragma unroll
                    for (int mt = 0; mt < 2; mt++) {
                        if (mt < mtact) {
#pragma unroll
                            for (int nt = 0; nt < BNT; nt++)
                                mma_f16(acc2[mt][nt], af[mt], bg[nt]);
                        }
                    }
                }
            }
        }
        __syncthreads();
    }
#undef ISSUE_STAGE

    // -------- epilogue: registers -> gmem --------
#pragma unroll
    for (int mt = 0; mt < 2; mt++) {
        if (mt >= mtact) continue;
#pragma unroll
        for (int h = 0; h < 2; h++) {
            const int ridx = bm + wm + mt * 16 + g + h * 8;
            bool valid;
            float* dst = nullptr;
            float wg = 1.f;
            if (MODE == 0) {
                valid = ridx < M;
                if (valid) dst = Cp + (size_t)kh * M * N + (size_t)ridx * N;
            } else if (MODE == 1) {
                valid = ridx < cnt;
                if (valid) dst = Cp + ((size_t)e * Tn + ridx) * (size_t)N;
            } else {
                valid = ridx < cnt;
                if (valid) {
                    int idx = e * Tn + ridx;
                    int tok = g_tok[idx];
                    wg = g_wgt[idx];
                    int sl = g_slot[idx];
                    dst = Cp + ((size_t)tok * 4 + sl * 2 + kh) * (size_t)Dn;
                }
            }
            if (!valid) continue;
#pragma unroll
            for (int nt = 0; nt < BNT; nt++) {
                const int col = bn + wn + nt * 8 + 2 * t4;
                float2 v = make_float2(acc[mt][nt][h * 2 + 0], acc[mt][nt][h * 2 + 1]);
                if (MODE == 1) {
                    float b0 = acc2[mt][nt][h * 2 + 0];
                    float b1 = acc2[mt][nt][h * 2 + 1];
                    v.x = (v.x / (1.f + __expf(-v.x))) * b0;
                    v.y = (v.y / (1.f + __expf(-v.y))) * b1;
                } else if (MODE == 2) {
                    v.x *= wg; v.y *= wg;
                }
                *(float2*)(dst + col) = v;
            }
        }
    }
}

// ---------------- small utility kernels ----------------

__global__ void k_zero_cnt() {
    if (threadIdx.x < En) g_cnt[threadIdx.x] = 0;
}

// res1 = h + r;  x = rmsnorm(res1, w)
__global__ void k_add_rmsnorm(const float* __restrict__ h, const float* __restrict__ r,
                              const float* __restrict__ w) {
    int t = blockIdx.x;
    const float* hr = h + t * Dn;
    const float* rr = r + t * Dn;
    float* resr = g_res1 + t * Dn;
    float* xr = g_x + t * Dn;

    float v[8];
    float local = 0.f;
#pragma unroll
    for (int j = 0; j < 8; j++) {
        int c = threadIdx.x + j * 256;
        float s = hr[c] + rr[c];
        v[j] = s;
        resr[c] = s;
        local += s * s;
    }
#pragma unroll
    for (int o = 16; o > 0; o >>= 1) local += __shfl_xor_sync(0xffffffffu, local, o);
    __shared__ float red[8];
    if ((threadIdx.x & 31) == 0) red[threadIdx.x >> 5] = local;
    __syncthreads();
    __shared__ float inv;
    if (threadIdx.x == 0) {
        float s = 0.f;
#pragma unroll
        for (int i = 0; i < 8; i++) s += red[i];
        inv = rsqrtf(s / (float)Dn + 1e-5f);
    }
    __syncthreads();
    float iv = inv;
#pragma unroll
    for (int j = 0; j < 8; j++) {
        int c = threadIdx.x + j * 256;
        xr[c] = v[j] * iv * w[c];
    }
}

// res2 = p0 + p1 + res1 (written to out); x2 = rmsnorm(res2, w)
__global__ void k_add2_rmsnorm(const float* __restrict__ p0, const float* __restrict__ p1,
                               const float* __restrict__ w, float* __restrict__ res2out) {
    int t = blockIdx.x;
    const float* a0 = p0 + t * Dn;
    const float* a1 = p1 + t * Dn;
    const float* rr = g_res1 + t * Dn;
    float* ro = res2out + t * Dn;
    float* xr = g_x2 + t * Dn;
    float v[8];
    float local = 0.f;
#pragma unroll
    for (int j = 0; j < 8; j++) {
        int c = threadIdx.x + j * 256;
        float s = a0[c] + a1[c] + rr[c];
        v[j] = s;
        ro[c] = s;
        local += s * s;
    }
#pragma unroll
    for (int o = 16; o > 0; o >>= 1) local += __shfl_xor_sync(0xffffffffu, local, o);
    __shared__ float red[8];
    if ((threadIdx.x & 31) == 0) red[threadIdx.x >> 5] = local;
    __syncthreads();
    __shared__ float inv;
    if (threadIdx.x == 0) {
        float s = 0.f;
#pragma unroll
        for (int i = 0; i < 8; i++) s += red[i];
        inv = rsqrtf(s / (float)Dn + 1e-5f);
    }
    __syncthreads();
    float iv = inv;
#pragma unroll
    for (int j = 0; j < 8; j++) {
        int c = threadIdx.x + j * 256;
        xr[c] = v[j] * iv * w[c];
    }
}

// qkv = p0 + p1 (split-K partial sum)
__global__ void k_addqkv(const float* __restrict__ p) {
    int i = blockIdx.x * 256 + threadIdx.x;
    if (i >= Tn * QKVn) return;
    g_qkv[i] = p[i] + p[i + Tn * QKVn];
}

__global__ void k_rope(const float* __restrict__ cosb, const float* __restrict__ sinb) {
    int idx = blockIdx.x * 256 + threadIdx.x;
    if (idx >= Tn * 40 * 32) return;
    int d = idx & 31;
    int rest = idx >> 5;
    int hh = rest % 40;
    int t = rest / 40;
    float c = cosb[t * 32 + d];
    float s = sinb[t * 32 + d];
    float* base = g_qkv + (size_t)t * QKVn + hh * 64 + d;
    float x1 = base[0];
    float x2 = base[32];
    base[0] = x1 * c - x2 * s;
    base[32] = x2 * c + x1 * s;
}

__global__ void k_scores() {
    const int kt = blockIdx.x, qt = blockIdx.y, h = blockIdx.z;
    const int tid = threadIdx.x;
    const int tx = tid & 15, ty = tid >> 4;

    if (kt > qt) {
#pragma unroll
        for (int i = 0; i < 4; i++)
#pragma unroll
            for (int j = 0; j < 4; j++) {
                int q = qt * 64 + ty * 4 + i;
                int k = kt * 64 + tx * 4 + j;
                g_scores[((size_t)h * Tn + q) * Tn + k] = -1e30f;
            }
        return;
    }

    __shared__ float Qs[64][65];
    __shared__ float Ks[64][65];
    const int lr = tid >> 2;
    const int lc = (tid & 3) * 16;
    const int kvh = h >> 2;
#pragma unroll
    for (int ch = 0; ch < 4; ch++) {
        float4 qv = *(const float4*)(g_qkv + (size_t)(qt * 64 + lr) * QKVn + h * 64 + lc + ch * 4);
        Qs[lr][lc + ch * 4 + 0] = qv.x; Qs[lr][lc + ch * 4 + 1] = qv.y;
        Qs[lr][lc + ch * 4 + 2] = qv.z; Qs[lr][lc + ch * 4 + 3] = qv.w;
        float4 kv = *(const float4*)(g_qkv + (size_t)(kt * 64 + lr) * QKVn + 2048 + kvh * 64 + lc + ch * 4);
        Ks[lr][lc + ch * 4 + 0] = kv.x; Ks[lr][lc + ch * 4 + 1] = kv.y;
        Ks[lr][lc + ch * 4 + 2] = kv.z; Ks[lr][lc + ch * 4 + 3] = kv.w;
    }
    __syncthreads();

    float acc[4][4];
#pragma unroll
    for (int i = 0; i < 4; i++)
#pragma unroll
        for (int j = 0; j < 4; j++) acc[i][j] = 0.f;

#pragma unroll 8
    for (int kk = 0; kk < 64; kk++) {
        float ra[4], rb[4];
#pragma unroll
        for (int i = 0; i < 4; i++) ra[i] = Qs[ty * 4 + i][kk];
#pragma unroll
        for (int j = 0; j < 4; j++) rb[j] = Ks[tx * 4 + j][kk];
#pragma unroll
        for (int i = 0; i < 4; i++)
#pragma unroll
            for (int j = 0; j < 4; j++) acc[i][j] += ra[i] * rb[j];
    }

    const float scale = 0.125f;
#pragma unroll
    for (int i = 0; i < 4; i++)
#pragma unroll
        for (int j = 0; j < 4; j++) {
            int q = qt * 64 + ty * 4 + i;
            int k = kt * 64 + tx * 4 + j;
            float v = (k <= q) ? acc[i][j] * scale : -1e30f;
            g_scores[((size_t)h * Tn + q) * Tn + k] = v;
        }
}

__global__ void k_softmax() {
    const int row = blockIdx.x;
    float* p = g_scores + (size_t)row * Tn;
    const int tid = threadIdx.x;
    float v[4];
    float mx = -3.4e38f;
#pragma unroll
    for (int j = 0; j < 4; j++) {
        v[j] = p[tid + j * 128];
        mx = fmaxf(mx, v[j]);
    }
#pragma unroll
    for (int o = 16; o > 0; o >>= 1) mx = fmaxf(mx, __shfl_xor_sync(0xffffffffu, mx, o));
    __shared__ float rm[4];
    if ((tid & 31) == 0) rm[tid >> 5] = mx;
    __syncthreads();
    mx = fmaxf(fmaxf(rm[0], rm[1]), fmaxf(rm[2], rm[3]));
    float sum = 0.f;
#pragma unroll
    for (int j = 0; j < 4; j++) {
        v[j] = __expf(v[j] - mx);
        sum += v[j];
    }
#pragma unroll
    for (int o = 16; o > 0; o >>= 1) sum += __shfl_xor_sync(0xffffffffu, sum, o);
    __shared__ float rs[4];
    if ((tid & 31) == 0) rs[tid >> 5] = sum;
    __syncthreads();
    sum = rs[0] + rs[1] + rs[2] + rs[3];
    float inv = 1.f / sum;
#pragma unroll
    for (int j = 0; j < 4; j++) p[tid + j * 128] = v[j] * inv;
}

__global__ void k_attnv() {
    const int qt = blockIdx.x, h = blockIdx.y;
    const int tid = threadIdx.x;
    const int tx = tid & 15, ty = tid >> 4;
    const int lr = tid >> 2;
    const int lc = (tid & 3) * 16;
    const int kvh = h >> 2;

    __shared__ float Ps[64][65];
    __shared__ float Vs[64][65];
    float acc[4][4];
#pragma unroll
    for (int i = 0; i < 4; i++)
#pragma unroll
        for (int j = 0; j < 4; j++) acc[i][j] = 0.f;

    for (int kt = 0; kt <= qt; kt++) {
#pragma unroll
        for (int ch = 0; ch < 4; ch++) {
            float4 pv = *(const float4*)(g_scores + ((size_t)h * Tn + qt * 64 + lr) * Tn + kt * 64 + lc + ch * 4);
            Ps[lr][lc + ch * 4 + 0] = pv.x; Ps[lr][lc + ch * 4 + 1] = pv.y;
            Ps[lr][lc + ch * 4 + 2] = pv.z; Ps[lr][lc + ch * 4 + 3] = pv.w;
            float4 vv = *(const float4*)(g_qkv + (size_t)(kt * 64 + lr) * QKVn + 2560 + kvh * 64 + lc + ch * 4);
            Vs[lr][lc + ch * 4 + 0] = vv.x; Vs[lr][lc + ch * 4 + 1] = vv.y;
            Vs[lr][lc + ch * 4 + 2] = vv.z; Vs[lr][lc + ch * 4 + 3] = vv.w;
        }
        __syncthreads();
#pragma unroll 8
        for (int kk = 0; kk < 64; kk++) {
            float ra[4], rb[4];
#pragma unroll
            for (int i = 0; i < 4; i++) ra[i] = Ps[ty * 4 + i][kk];
#pragma unroll
            for (int j = 0; j < 4; j++) rb[j] = Vs[kk][tx * 4 + j];
#pragma unroll
            for (int i = 0; i < 4; i++)
#pragma unroll
                for (int j = 0; j < 4; j++) acc[i][j] += ra[i] * rb[j];
        }
        __syncthreads();
    }

#pragma unroll
    for (int i = 0; i < 4; i++)
#pragma unroll
        for (int j = 0; j < 4; j++) {
            int q = qt * 64 + ty * 4 + i;
            g_attn[(size_t)q * Dn + h * 64 + tx * 4 + j] = acc[i][j];
        }
}

__global__ void k_gate(const float* __restrict__ gw) {
    const int t = blockIdx.x;
    const int warp = threadIdx.x >> 5, lane = threadIdx.x & 31;
    const float* xr = g_x2 + (size_t)t * Dn;
    const float* wr = gw + (size_t)warp * Dn;
    float s = 0.f;
    for (int c = lane; c < Dn; c += 32) s += xr[c] * wr[c];
#pragma unroll
    for (int o = 16; o > 0; o >>= 1) s += __shfl_xor_sync(0xffffffffu, s, o);
    __shared__ float lg[En];
    if (lane == 0) lg[warp] = s;
    __syncthreads();
    if (threadIdx.x == 0) {
        int i0 = 0;
        for (int e = 1; e < En; e++) if (lg[e] > lg[i0]) i0 = e;
        int i1 = (i0 == 0) ? 1 : 0;
        for (int e = 0; e < En; e++) if (e != i0 && lg[e] > lg[i1]) i1 = e;
        float w1v = __expf(lg[i1] - lg[i0]);
        float inv = 1.f / (1.f + w1v);
        float w0 = inv, w1n = w1v * inv;
        int p0 = atomicAdd(&g_cnt[i0], 1);
        g_tok[i0 * Tn + p0] = t; g_wgt[i0 * Tn + p0] = w0; g_slot[i0 * Tn + p0] = 0;
        int p1 = atomicAdd(&g_cnt[i1], 1);
        g_tok[i1 * Tn + p1] = t; g_wgt[i1 * Tn + p1] = w1n; g_slot[i1 * Tn + p1] = 1;
    }
}

// moe_out = sum of 4 eo slots (2 experts x 2 K-halves)
__global__ void k_combine(float* __restrict__ out) {
    int i = blockIdx.x * 256 + threadIdx.x;
    if (i >= Tn * Dn) return;
    int t = i / Dn;
    int d = i - t * Dn;
    const float* base = g_eo + (size_t)t * 4 * Dn + d;
    out[i] = base[0] + base[Dn] + base[2 * Dn] + base[3 * Dn];
}

// ---------------- launch ----------------
extern "C" void kernel_launch(void* const* d_in, const int* in_sizes, int n_in,
                              void* d_out, int out_size) {
    const float* hs   = (const float*)d_in[0];
    const float* resi = (const float*)d_in[1];
    const float* cosb = (const float*)d_in[2];
    const float* sinb = (const float*)d_in[3];
    const float* ln1  = (const float*)d_in[4];
    const float* ln2  = (const float*)d_in[5];
    const float* wqkv = (const float*)d_in[6];
    const float* wo   = (const float*)d_in[7];
    const float* gw   = (const float*)d_in[8];
    const float* w1   = (const float*)d_in[9];
    const float* w3   = (const float*)d_in[10];
    const float* w2   = (const float*)d_in[11];

    float* out = (float*)d_out;
    float* moe_out = out;
    float* res2 = out + Tn * Dn;

    void *px, *pattn, *px2, *ph1, *peo;
    cudaGetSymbolAddress(&px, g_x);
    cudaGetSymbolAddress(&pattn, g_attn);
    cudaGetSymbolAddress(&px2, g_x2);
    cudaGetSymbolAddress(&ph1, g_h1);
    cudaGetSymbolAddress(&peo, g_eo);

    constexpr int SMEM0 = 3 * (128 * PAD + 128 * PAD) * 4;            // MODE0 NT=128: 147456
    constexpr int SMEM1 = 3 * (128 * PAD + 2 * 128 * PAD) * 4;        // MODE1 dual-B: 221184
    constexpr int SMEM2 = 3 * (128 * PAD + 256 * PAD) * 4;            // MODE2 NT=256: 221184
    cudaFuncSetAttribute(k_gemm<0, 128, 2>, cudaFuncAttributeMaxDynamicSharedMemorySize, SMEM0);
    cudaFuncSetAttribute(k_gemm<1, 128, 1>, cudaFuncAttributeMaxDynamicSharedMemorySize, SMEM1);
    cudaFuncSetAttribute(k_gemm<2, 256, 2>, cudaFuncAttributeMaxDynamicSharedMemorySize, SMEM2);

    k_zero_cnt<<<1, 32>>>();
    k_add_rmsnorm<<<Tn, 256>>>(hs, resi, ln1);

    // qkv partials: [2][512][3072] into g_eo, then sum + rope   (grid: m fastest)
    k_gemm<0, 128, 2><<<dim3(Tn / 128, QKVn / 128, 2), 512, SMEM0>>>(
        (const float*)px, wqkv, nullptr, (float*)peo, nullptr, Tn, QKVn, Dn);
    k_addqkv<<<(Tn * QKVn) / 256, 256>>>((const float*)peo);
    k_rope<<<(Tn * 40 * 32) / 256, 256>>>(cosb, sinb);

    k_scores<<<dim3(Tn / 64, Tn / 64, Hn), 256>>>();
    k_softmax<<<Hn * Tn, 128>>>();
    k_attnv<<<dim3(Tn / 64, Hn), 256>>>();

    // attn @ wo^T partials: [2][512][2048] into g_eo; fused add + rmsnorm
    k_gemm<0, 128, 2><<<dim3(Tn / 128, Dn / 128, 2), 512, SMEM0>>>(
        (const float*)pattn, wo, nullptr, (float*)peo, nullptr, Tn, Dn, Dn);
    k_add2_rmsnorm<<<Tn, 256>>>((const float*)peo, (const float*)peo + Tn * Dn, ln2, res2);
    k_gate<<<Tn, 256>>>(gw);

    // fused dual-B grouped GEMM1: h1 = silu(x@w1^T) * (x@w3^T), no separate act pass
    k_gemm<1, 128, 1><<<dim3(Tn / 128, In / 128, En), 512, SMEM1>>>(
        (const float*)px2, w1, w3, (float*)ph1, nullptr, Tn, In, Dn);
    // w2 grouped GEMM, split-K2, scatter into 4-slot eo
    k_gemm<2, 256, 2><<<dim3(Tn / 128, Dn / 256, En * 2), 512, SMEM2>>>(
        (const float*)ph1, w2, nullptr, (float*)peo, nullptr, Tn, Dn, In);
    k_combine<<<(Tn * Dn) / 256, 256>>>(moe_out);
}

// round 9
// speedup vs baseline: 10.7026x; 1.2154x over previous
#include <cuda_runtime.h>
#include <cuda_fp16.h>
#include <math.h>
#include <stdint.h>

#define Tn 512
#define Dn 2048
#define Hn 32
#define KVn 8
#define DHn 64
#define In 7168
#define En 8
#define QKVn 3072   // (H + 2*KV) * DH
#define PADH 40     // smem row stride in halfs (32 data + 8 pad): ldmatrix conflict-free

// ---------------- scratch (device globals; no allocation allowed) ----------------
__device__ __align__(16) float g_res1[Tn * Dn];
__device__ __align__(16) float g_x[Tn * Dn];
__device__ __align__(16) float g_qkv[Tn * QKVn];
__device__ __align__(16) float g_scores[Hn * Tn * Tn];
__device__ __align__(16) float g_attn[Tn * Dn];
__device__ __align__(16) float g_x2[Tn * Dn];
__device__ __align__(16) float g_h1[En * Tn * In];
__device__ __align__(16) float g_eo[Tn * 4 * Dn];   // partial/scatter scratch (16 MB)
__device__ int   g_tok[En * Tn];
__device__ float g_wgt[En * Tn];
__device__ int   g_slot[En * Tn];
__device__ int   g_cnt[En];

// ================= helpers (sm_80-level features only) =================
__device__ __forceinline__ uint32_t smem_u32(const void* p) {
    uint32_t a;
    asm("{ .reg .u64 t; cvta.to.shared.u64 t, %1; cvt.u32.u64 %0, t; }" : "=r"(a) : "l"(p));
    return a;
}
__device__ __forceinline__ uint32_t pack_h2(float x, float y) {
    __half2 h = __floats2half2_rn(x, y);
    return *reinterpret_cast<uint32_t*>(&h);
}
__device__ __forceinline__ uint4 cvt8(float4 a, float4 b) {
    uint4 u;
    u.x = pack_h2(a.x, a.y); u.y = pack_h2(a.z, a.w);
    u.z = pack_h2(b.x, b.y); u.w = pack_h2(b.z, b.w);
    return u;
}
__device__ __forceinline__ void mma_f16(float* c, const uint32_t* a, const uint32_t* b) {
    asm volatile(
        "mma.sync.aligned.m16n8k16.row.col.f32.f16.f16.f32 "
        "{%0,%1,%2,%3}, {%4,%5,%6,%7}, {%8,%9}, {%0,%1,%2,%3};"
        : "+f"(c[0]), "+f"(c[1]), "+f"(c[2]), "+f"(c[3])
        : "r"(a[0]), "r"(a[1]), "r"(a[2]), "r"(a[3]), "r"(b[0]), "r"(b[1]));
}
__device__ __forceinline__ void ldsm_x4(uint32_t& r0, uint32_t& r1, uint32_t& r2, uint32_t& r3,
                                        uint32_t addr) {
    asm volatile("ldmatrix.sync.aligned.m8n8.x4.shared.b16 {%0,%1,%2,%3}, [%4];"
                 : "=r"(r0), "=r"(r1), "=r"(r2), "=r"(r3) : "r"(addr));
}

// ================= fp16 tensor-core GEMM: C[M,N] = A[M,K] * B[N,K]^T =================
// fp32 sources converted to fp16 ONCE at staging (LDG->cvt->STS.128), smem fp16,
// fragments via ldmatrix. Register-prefetch double-buffered pipeline.
// Grid: blockIdx.x = m-tile (fastest: consecutive CTAs share B tile in L2).
// MODE 0: plain split-K partials. MODE 1: dual-B fused w1/w3 (gather; silu epilogue).
// MODE 2: MoE gemm2 split-K2 weighted scatter to g_eo 4-slot.
template <int MODE, int NT, int KSPLIT>
__global__ void __launch_bounds__(512, 1) k_gemm(const float* __restrict__ A,
                                                 const float* __restrict__ B,
                                                 const float* __restrict__ B2,
                                                 float* __restrict__ C,
                                                 float* __restrict__ C2,
                                                 int M, int N, int Kstride) {
    constexpr int BNT = NT / 32;                  // warp n-subtiles (8 cols each)
    constexpr int NPAIR = BNT / 2;                // ldmatrix x4 covers 2 subtiles
    constexpr int WN = NT / 4;                    // warp n extent
    constexpr int NB = (MODE == 1) ? 2 : 1;       // B matrices staged
    constexpr int NBB = (MODE == 1) ? 2 : (NT / 128);  // B chunks per thread
    constexpr int A_HALFS = 128 * PADH;
    constexpr int B_HALFS = NT * PADH;            // per B matrix
    constexpr int STAGE_HALFS = A_HALFS + NB * B_HALFS;
    constexpr int STAGE_BYTES = STAGE_HALFS * 2;

    const int kh = (MODE == 2) ? (int)(blockIdx.z & 1) : ((MODE == 0) ? (int)blockIdx.z : 0);
    const int e  = (MODE == 0) ? 0 : ((MODE == 2) ? (int)(blockIdx.z >> 1) : (int)blockIdx.z);
    const int cnt = (MODE == 0) ? M : g_cnt[e];
    const int bm = blockIdx.x * 128;
    if (bm >= cnt) return;
    const int bn = blockIdx.y * NT;

    const float* Bp  = (MODE == 0) ? B  : B  + (size_t)e * N * Kstride;
    const float* Bp2 = (MODE == 1) ? B2 + (size_t)e * N * Kstride : nullptr;

    const int Klen = Kstride / KSPLIT;
    const int koff = kh * Klen;

    const int tid = threadIdx.x;
    const int wid = tid >> 5, lane = tid & 31;
    const int g = lane >> 2, t4 = lane & 3;
    const int wm = (wid & 3) * 32, wn = (wid >> 2) * WN;

    const int rows_avail = cnt - bm - wm;
    const int mtact = (rows_avail >= 32) ? 2 : ((rows_avail <= 0) ? 0 : ((rows_avail + 15) >> 4));

    extern __shared__ char smc[];
    const uint32_t smU = smem_u32(smc);

    // ---- staging geometry: chunk = 8 floats; 4 chunks per 32-float row ----
    const int arow = tid >> 2;
    const int acol = (tid & 3) * 8;

    const float* aSrc;
    {
        if (MODE == 0) {
            int ridx = bm + arow; if (ridx >= M) ridx = M - 1;
            aSrc = A + (size_t)ridx * Kstride + acol + koff;
        } else if (MODE == 1) {
            int idx = bm + arow;
            int tok = (idx < cnt) ? g_tok[e * Tn + idx] : g_tok[e * Tn];
            aSrc = A + (size_t)tok * Kstride + acol + koff;
        } else {
            int idx = bm + arow;
            aSrc = A + ((size_t)e * Tn + idx) * (size_t)Kstride + acol + koff;
        }
    }
    const uint32_t aSts = (uint32_t)(arow * PADH + acol) * 2u;

    const float* bSrc[NBB];
    uint32_t bSts[NBB];
#pragma unroll
    for (int j = 0; j < NBB; j++) {
        const int rowoff = (MODE == 2) ? j * 128 : 0;
        const float* base = (MODE == 1 && j == 1) ? Bp2 : Bp;
        const int moff = (MODE == 1 && j == 1) ? 1 : 0;
        bSrc[j] = base + (size_t)(bn + rowoff + arow) * Kstride + acol + koff;
        bSts[j] = (uint32_t)(A_HALFS + moff * B_HALFS + (rowoff + arow) * PADH + acol) * 2u;
    }

    // ---- ldmatrix fragment addresses (stage 0, ks 0); add stage/ks offsets at use ----
    const int l4 = lane >> 3, lr = lane & 7;
    uint32_t aAddr[2];
#pragma unroll
    for (int mt = 0; mt < 2; mt++) {
        int m_local = wm + mt * 16 + (l4 & 1) * 8 + lr;
        aAddr[mt] = smU + (uint32_t)(m_local * PADH) * 2u + (uint32_t)(l4 >> 1) * 16u;
    }
    uint32_t bAddr[NPAIR];
#pragma unroll
    for (int p = 0; p < NPAIR; p++) {
        int n_local = wn + p * 16 + (l4 >> 1) * 8 + lr;
        bAddr[p] = smU + (uint32_t)(A_HALFS + n_local * PADH) * 2u + (uint32_t)(l4 & 1) * 16u;
    }

    float acc[2][BNT][4];
    float acc2[MODE == 1 ? 2 : 1][MODE == 1 ? BNT : 1][4];
#pragma unroll
    for (int mt = 0; mt < 2; mt++)
#pragma unroll
        for (int nt = 0; nt < BNT; nt++)
#pragma unroll
            for (int q = 0; q < 4; q++) acc[mt][nt][q] = 0.f;
    if (MODE == 1) {
#pragma unroll
        for (int mt = 0; mt < 2; mt++)
#pragma unroll
            for (int nt = 0; nt < BNT; nt++)
#pragma unroll
                for (int q = 0; q < 4; q++) acc2[mt][nt][q] = 0.f;
    }

    float4 ra0, ra1;
    float4 rb0[NBB], rb1[NBB];

#define LDG_STAGE(ktn)                                                   \
    do {                                                                 \
        const int k0 = (ktn) * 32;                                       \
        ra0 = *(const float4*)(aSrc + k0);                               \
        ra1 = *(const float4*)(aSrc + k0 + 4);                           \
        _Pragma("unroll")                                                \
        for (int j = 0; j < NBB; j++) {                                  \
            rb0[j] = *(const float4*)(bSrc[j] + k0);                     \
            rb1[j] = *(const float4*)(bSrc[j] + k0 + 4);                 \
        }                                                                \
    } while (0)

#define STS_STAGE(ktn)                                                   \
    do {                                                                 \
        char* sb = smc + ((ktn) & 1) * STAGE_BYTES;                      \
        *(uint4*)(sb + aSts) = cvt8(ra0, ra1);                           \
        _Pragma("unroll")                                                \
        for (int j = 0; j < NBB; j++)                                    \
            *(uint4*)(sb + bSts[j]) = cvt8(rb0[j], rb1[j]);              \
    } while (0)

    const int KT = Klen / 32;

    LDG_STAGE(0);
    STS_STAGE(0);
    __syncthreads();
    LDG_STAGE(1);

    for (int kt = 0; kt < KT; kt++) {
        const uint32_t so = (uint32_t)(kt & 1) * STAGE_BYTES;
#pragma unroll
        for (int ks = 0; ks < 2; ks++) {
            const uint32_t kso = so + (uint32_t)ks * 32u;
            uint32_t af[2][4];
#pragma unroll
            for (int mt = 0; mt < 2; mt++)
                if (mt < mtact)
                    ldsm_x4(af[mt][0], af[mt][1], af[mt][2], af[mt][3], aAddr[mt] + kso);
            if (mtact > 0) {
                uint32_t bf[BNT][2];
#pragma unroll
                for (int p = 0; p < NPAIR; p++)
                    ldsm_x4(bf[2 * p][0], bf[2 * p][1], bf[2 * p + 1][0], bf[2 * p + 1][1],
                            bAddr[p] + kso);
#pragma unroll
                for (int mt = 0; mt < 2; mt++)
                    if (mt < mtact)
#pragma unroll
                        for (int nt = 0; nt < BNT; nt++)
                            mma_f16(acc[mt][nt], af[mt], bf[nt]);
                if (MODE == 1) {
                    uint32_t bg[BNT][2];
#pragma unroll
                    for (int p = 0; p < NPAIR; p++)
                        ldsm_x4(bg[2 * p][0], bg[2 * p][1], bg[2 * p + 1][0], bg[2 * p + 1][1],
                                bAddr[p] + (uint32_t)(B_HALFS * 2) + kso);
#pragma unroll
                    for (int mt = 0; mt < 2; mt++)
                        if (mt < mtact)
#pragma unroll
                            for (int nt = 0; nt < BNT; nt++)
                                mma_f16(acc2[mt][nt], af[mt], bg[nt]);
                }
            }
        }
        if (kt + 1 < KT) {
            STS_STAGE(kt + 1);
            if (kt + 2 < KT) LDG_STAGE(kt + 2);
            __syncthreads();
        }
    }
#undef LDG_STAGE
#undef STS_STAGE

    // -------- epilogue: registers -> gmem --------
#pragma unroll
    for (int mt = 0; mt < 2; mt++) {
        if (mt >= mtact) continue;
#pragma unroll
        for (int h = 0; h < 2; h++) {
            const int ridx = bm + wm + mt * 16 + g + h * 8;
            bool valid;
            float* dst = nullptr;
            float wg = 1.f;
            if (MODE == 0) {
                valid = ridx < M;
                if (valid) dst = C + (size_t)kh * M * N + (size_t)ridx * N;
            } else if (MODE == 1) {
                valid = ridx < cnt;
                if (valid) dst = C + ((size_t)e * Tn + ridx) * (size_t)N;
            } else {
                valid = ridx < cnt;
                if (valid) {
                    int idx = e * Tn + ridx;
                    int tok = g_tok[idx];
                    wg = g_wgt[idx];
                    int sl = g_slot[idx];
                    dst = C + ((size_t)tok * 4 + sl * 2 + kh) * (size_t)Dn;
                }
            }
            if (!valid) continue;
#pragma unroll
            for (int nt = 0; nt < BNT; nt++) {
                const int col = bn + wn + nt * 8 + 2 * t4;
                float2 v = make_float2(acc[mt][nt][h * 2 + 0], acc[mt][nt][h * 2 + 1]);
                if (MODE == 1) {
                    float b0 = acc2[mt][nt][h * 2 + 0];
                    float b1 = acc2[mt][nt][h * 2 + 1];
                    v.x = (v.x / (1.f + __expf(-v.x))) * b0;
                    v.y = (v.y / (1.f + __expf(-v.y))) * b1;
                } else if (MODE == 2) {
                    v.x *= wg; v.y *= wg;
                }
                *(float2*)(dst + col) = v;
            }
        }
    }
}

// ---------------- small utility kernels ----------------

__global__ void k_zero_cnt() {
    if (threadIdx.x < En) g_cnt[threadIdx.x] = 0;
}

// res1 = h + r;  x = rmsnorm(res1, w)
__global__ void k_add_rmsnorm(const float* __restrict__ h, const float* __restrict__ r,
                              const float* __restrict__ w) {
    int t = blockIdx.x;
    const float* hr = h + t * Dn;
    const float* rr = r + t * Dn;
    float* resr = g_res1 + t * Dn;
    float* xr = g_x + t * Dn;

    float v[8];
    float local = 0.f;
#pragma unroll
    for (int j = 0; j < 8; j++) {
        int c = threadIdx.x + j * 256;
        float s = hr[c] + rr[c];
        v[j] = s;
        resr[c] = s;
        local += s * s;
    }
#pragma unroll
    for (int o = 16; o > 0; o >>= 1) local += __shfl_xor_sync(0xffffffffu, local, o);
    __shared__ float red[8];
    if ((threadIdx.x & 31) == 0) red[threadIdx.x >> 5] = local;
    __syncthreads();
    __shared__ float inv;
    if (threadIdx.x == 0) {
        float s = 0.f;
#pragma unroll
        for (int i = 0; i < 8; i++) s += red[i];
        inv = rsqrtf(s / (float)Dn + 1e-5f);
    }
    __syncthreads();
    float iv = inv;
#pragma unroll
    for (int j = 0; j < 8; j++) {
        int c = threadIdx.x + j * 256;
        xr[c] = v[j] * iv * w[c];
    }
}

// res2 = p0 + p1 + res1 (written to out); x2 = rmsnorm(res2, w)
__global__ void k_add2_rmsnorm(const float* __restrict__ p0, const float* __restrict__ p1,
                               const float* __restrict__ w, float* __restrict__ res2out) {
    int t = blockIdx.x;
    const float* a0 = p0 + t * Dn;
    const float* a1 = p1 + t * Dn;
    const float* rr = g_res1 + t * Dn;
    float* ro = res2out + t * Dn;
    float* xr = g_x2 + t * Dn;
    float v[8];
    float local = 0.f;
#pragma unroll
    for (int j = 0; j < 8; j++) {
        int c = threadIdx.x + j * 256;
        float s = a0[c] + a1[c] + rr[c];
        v[j] = s;
        ro[c] = s;
        local += s * s;
    }
#pragma unroll
    for (int o = 16; o > 0; o >>= 1) local += __shfl_xor_sync(0xffffffffu, local, o);
    __shared__ float red[8];
    if ((threadIdx.x & 31) == 0) red[threadIdx.x >> 5] = local;
    __syncthreads();
    __shared__ float inv;
    if (threadIdx.x == 0) {
        float s = 0.f;
#pragma unroll
        for (int i = 0; i < 8; i++) s += red[i];
        inv = rsqrtf(s / (float)Dn + 1e-5f);
    }
    __syncthreads();
    float iv = inv;
#pragma unroll
    for (int j = 0; j < 8; j++) {
        int c = threadIdx.x + j * 256;
        xr[c] = v[j] * iv * w[c];
    }
}

// qkv = p0 + p1 (split-K partial sum)
__global__ void k_addqkv(const float* __restrict__ p) {
    int i = blockIdx.x * 256 + threadIdx.x;
    if (i >= Tn * QKVn) return;
    g_qkv[i] = p[i] + p[i + Tn * QKVn];
}

__global__ void k_rope(const float* __restrict__ cosb, const float* __restrict__ sinb) {
    int idx = blockIdx.x * 256 + threadIdx.x;
    if (idx >= Tn * 40 * 32) return;
    int d = idx & 31;
    int rest = idx >> 5;
    int hh = rest % 40;
    int t = rest / 40;
    float c = cosb[t * 32 + d];
    float s = sinb[t * 32 + d];
    float* base = g_qkv + (size_t)t * QKVn + hh * 64 + d;
    float x1 = base[0];
    float x2 = base[32];
    base[0] = x1 * c - x2 * s;
    base[32] = x2 * c + x1 * s;
}

__global__ void k_scores() {
    const int kt = blockIdx.x, qt = blockIdx.y, h = blockIdx.z;
    const int tid = threadIdx.x;
    const int tx = tid & 15, ty = tid >> 4;

    if (kt > qt) {
#pragma unroll
        for (int i = 0; i < 4; i++)
#pragma unroll
            for (int j = 0; j < 4; j++) {
                int q = qt * 64 + ty * 4 + i;
                int k = kt * 64 + tx * 4 + j;
                g_scores[((size_t)h * Tn + q) * Tn + k] = -1e30f;
            }
        return;
    }

    __shared__ float Qs[64][65];
    __shared__ float Ks[64][65];
    const int lr = tid >> 2;
    const int lc = (tid & 3) * 16;
    const int kvh = h >> 2;
#pragma unroll
    for (int ch = 0; ch < 4; ch++) {
        float4 qv = *(const float4*)(g_qkv + (size_t)(qt * 64 + lr) * QKVn + h * 64 + lc + ch * 4);
        Qs[lr][lc + ch * 4 + 0] = qv.x; Qs[lr][lc + ch * 4 + 1] = qv.y;
        Qs[lr][lc + ch * 4 + 2] = qv.z; Qs[lr][lc + ch * 4 + 3] = qv.w;
        float4 kv = *(const float4*)(g_qkv + (size_t)(kt * 64 + lr) * QKVn + 2048 + kvh * 64 + lc + ch * 4);
        Ks[lr][lc + ch * 4 + 0] = kv.x; Ks[lr][lc + ch * 4 + 1] = kv.y;
        Ks[lr][lc + ch * 4 + 2] = kv.z; Ks[lr][lc + ch * 4 + 3] = kv.w;
    }
    __syncthreads();

    float acc[4][4];
#pragma unroll
    for (int i = 0; i < 4; i++)
#pragma unroll
        for (int j = 0; j < 4; j++) acc[i][j] = 0.f;

#pragma unroll 8
    for (int kk = 0; kk < 64; kk++) {
        float ra[4], rb[4];
#pragma unroll
        for (int i = 0; i < 4; i++) ra[i] = Qs[ty * 4 + i][kk];
#pragma unroll
        for (int j = 0; j < 4; j++) rb[j] = Ks[tx * 4 + j][kk];
#pragma unroll
        for (int i = 0; i < 4; i++)
#pragma unroll
            for (int j = 0; j < 4; j++) acc[i][j] += ra[i] * rb[j];
    }

    const float scale = 0.125f;
#pragma unroll
    for (int i = 0; i < 4; i++)
#pragma unroll
        for (int j = 0; j < 4; j++) {
            int q = qt * 64 + ty * 4 + i;
            int k = kt * 64 + tx * 4 + j;
            float v = (k <= q) ? acc[i][j] * scale : -1e30f;
            g_scores[((size_t)h * Tn + q) * Tn + k] = v;
        }
}

__global__ void k_softmax() {
    const int row = blockIdx.x;
    float* p = g_scores + (size_t)row * Tn;
    const int tid = threadIdx.x;
    float v[4];
    float mx = -3.4e38f;
#pragma unroll
    for (int j = 0; j < 4; j++) {
        v[j] = p[tid + j * 128];
        mx = fmaxf(mx, v[j]);
    }
#pragma unroll
    for (int o = 16; o > 0; o >>= 1) mx = fmaxf(mx, __shfl_xor_sync(0xffffffffu, mx, o));
    __shared__ float rm[4];
    if ((tid & 31) == 0) rm[tid >> 5] = mx;
    __syncthreads();
    mx = fmaxf(fmaxf(rm[0], rm[1]), fmaxf(rm[2], rm[3]));
    float sum = 0.f;
#pragma unroll
    for (int j = 0; j < 4; j++) {
        v[j] = __expf(v[j] - mx);
        sum += v[j];
    }
#pragma unroll
    for (int o = 16; o > 0; o >>= 1) sum += __shfl_xor_sync(0xffffffffu, sum, o);
    __shared__ float rs[4];
    if ((tid & 31) == 0) rs[tid >> 5] = sum;
    __syncthreads();
    sum = rs[0] + rs[1] + rs[2] + rs[3];
    float inv = 1.f / sum;
#pragma unroll
    for (int j = 0; j < 4; j++) p[tid + j * 128] = v[j] * inv;
}

__global__ void k_attnv() {
    const int qt = blockIdx.x, h = blockIdx.y;
    const int tid = threadIdx.x;
    const int tx = tid & 15, ty = tid >> 4;
    const int lr = tid >> 2;
    const int lc = (tid & 3) * 16;
    const int kvh = h >> 2;

    __shared__ float Ps[64][65];
    __shared__ float Vs[64][65];
    float acc[4][4];
#pragma unroll
    for (int i = 0; i < 4; i++)
#pragma unroll
        for (int j = 0; j < 4; j++) acc[i][j] = 0.f;

    for (int kt = 0; kt <= qt; kt++) {
#pragma unroll
        for (int ch = 0; ch < 4; ch++) {
            float4 pv = *(const float4*)(g_scores + ((size_t)h * Tn + qt * 64 + lr) * Tn + kt * 64 + lc + ch * 4);
            Ps[lr][lc + ch * 4 + 0] = pv.x; Ps[lr][lc + ch * 4 + 1] = pv.y;
            Ps[lr][lc + ch * 4 + 2] = pv.z; Ps[lr][lc + ch * 4 + 3] = pv.w;
            float4 vv = *(const float4*)(g_qkv + (size_t)(kt * 64 + lr) * QKVn + 2560 + kvh * 64 + lc + ch * 4);
            Vs[lr][lc + ch * 4 + 0] = vv.x; Vs[lr][lc + ch * 4 + 1] = vv.y;
            Vs[lr][lc + ch * 4 + 2] = vv.z; Vs[lr][lc + ch * 4 + 3] = vv.w;
        }
        __syncthreads();
#pragma unroll 8
        for (int kk = 0; kk < 64; kk++) {
            float ra[4], rb[4];
#pragma unroll
            for (int i = 0; i < 4; i++) ra[i] = Ps[ty * 4 + i][kk];
#pragma unroll
            for (int j = 0; j < 4; j++) rb[j] = Vs[kk][tx * 4 + j];
#pragma unroll
            for (int i = 0; i < 4; i++)
#pragma unroll
                for (int j = 0; j < 4; j++) acc[i][j] += ra[i] * rb[j];
        }
        __syncthreads();
    }

#pragma unroll
    for (int i = 0; i < 4; i++)
#pragma unroll
        for (int j = 0; j < 4; j++) {
            int q = qt * 64 + ty * 4 + i;
            g_attn[(size_t)q * Dn + h * 64 + tx * 4 + j] = acc[i][j];
        }
}

__global__ void k_gate(const float* __restrict__ gw) {
    const int t = blockIdx.x;
    const int warp = threadIdx.x >> 5, lane = threadIdx.x & 31;
    const float* xr = g_x2 + (size_t)t * Dn;
    const float* wr = gw + (size_t)warp * Dn;
    float s = 0.f;
    for (int c = lane; c < Dn; c += 32) s += xr[c] * wr[c];
#pragma unroll
    for (int o = 16; o > 0; o >>= 1) s += __shfl_xor_sync(0xffffffffu, s, o);
    __shared__ float lg[En];
    if (lane == 0) lg[warp] = s;
    __syncthreads();
    if (threadIdx.x == 0) {
        int i0 = 0;
        for (int e = 1; e < En; e++) if (lg[e] > lg[i0]) i0 = e;
        int i1 = (i0 == 0) ? 1 : 0;
        for (int e = 0; e < En; e++) if (e != i0 && lg[e] > lg[i1]) i1 = e;
        float w1v = __expf(lg[i1] - lg[i0]);
        float inv = 1.f / (1.f + w1v);
        float w0 = inv, w1n = w1v * inv;
        int p0 = atomicAdd(&g_cnt[i0], 1);
        g_tok[i0 * Tn + p0] = t; g_wgt[i0 * Tn + p0] = w0; g_slot[i0 * Tn + p0] = 0;
        int p1 = atomicAdd(&g_cnt[i1], 1);
        g_tok[i1 * Tn + p1] = t; g_wgt[i1 * Tn + p1] = w1n; g_slot[i1 * Tn + p1] = 1;
    }
}

// moe_out = sum of 4 eo slots (2 experts x 2 K-halves)
__global__ void k_combine(float* __restrict__ out) {
    int i = blockIdx.x * 256 + threadIdx.x;
    if (i >= Tn * Dn) return;
    int t = i / Dn;
    int d = i - t * Dn;
    const float* base = g_eo + (size_t)t * 4 * Dn + d;
    out[i] = base[0] + base[Dn] + base[2 * Dn] + base[3 * Dn];
}

// ---------------- launch ----------------
extern "C" void kernel_launch(void* const* d_in, const int* in_sizes, int n_in,
                              void* d_out, int out_size) {
    const float* hs   = (const float*)d_in[0];
    const float* resi = (const float*)d_in[1];
    const float* cosb = (const float*)d_in[2];
    const float* sinb = (const float*)d_in[3];
    const float* ln1  = (const float*)d_in[4];
    const float* ln2  = (const float*)d_in[5];
    const float* wqkv = (const float*)d_in[6];
    const float* wo   = (const float*)d_in[7];
    const float* gw   = (const float*)d_in[8];
    const float* w1   = (const float*)d_in[9];
    const float* w3   = (const float*)d_in[10];
    const float* w2   = (const float*)d_in[11];

    float* out = (float*)d_out;
    float* moe_out = out;
    float* res2 = out + Tn * Dn;

    void *px, *pattn, *px2, *ph1, *peo;
    cudaGetSymbolAddress(&px, g_x);
    cudaGetSymbolAddress(&pattn, g_attn);
    cudaGetSymbolAddress(&px2, g_x2);
    cudaGetSymbolAddress(&ph1, g_h1);
    cudaGetSymbolAddress(&peo, g_eo);

    // fp16 staging: 2 stages x (A + NB*B) halfs x 2B
    constexpr int SMEM0 = 2 * (128 * PADH + 128 * PADH) * 2;       // 40960
    constexpr int SMEM1 = 2 * (128 * PADH + 2 * 128 * PADH) * 2;   // 61440
    constexpr int SMEM2 = 2 * (128 * PADH + 256 * PADH) * 2;       // 61440
    cudaFuncSetAttribute(k_gemm<0, 128, 2>, cudaFuncAttributeMaxDynamicSharedMemorySize, SMEM0);
    cudaFuncSetAttribute(k_gemm<1, 128, 1>, cudaFuncAttributeMaxDynamicSharedMemorySize, SMEM1);
    cudaFuncSetAttribute(k_gemm<2, 256, 2>, cudaFuncAttributeMaxDynamicSharedMemorySize, SMEM2);

    k_zero_cnt<<<1, 32>>>();
    k_add_rmsnorm<<<Tn, 256>>>(hs, resi, ln1);

    // qkv partials: [2][512][3072] into g_eo, then sum + rope   (grid: m fastest)
    k_gemm<0, 128, 2><<<dim3(Tn / 128, QKVn / 128, 2), 512, SMEM0>>>(
        (const float*)px, wqkv, nullptr, (float*)peo, nullptr, Tn, QKVn, Dn);
    k_addqkv<<<(Tn * QKVn) / 256, 256>>>((const float*)peo);
    k_rope<<<(Tn * 40 * 32) / 256, 256>>>(cosb, sinb);

    k_scores<<<dim3(Tn / 64, Tn / 64, Hn), 256>>>();
    k_softmax<<<Hn * Tn, 128>>>();
    k_attnv<<<dim3(Tn / 64, Hn), 256>>>();

    // attn @ wo^T partials: [2][512][2048] into g_eo; fused add + rmsnorm
    k_gemm<0, 128, 2><<<dim3(Tn / 128, Dn / 128, 2), 512, SMEM0>>>(
        (const float*)pattn, wo, nullptr, (float*)peo, nullptr, Tn, Dn, Dn);
    k_add2_rmsnorm<<<Tn, 256>>>((const float*)peo, (const float*)peo + Tn * Dn, ln2, res2);
    k_gate<<<Tn, 256>>>(gw);

    // fused dual-B grouped GEMM1: h1 = silu(x@w1^T) * (x@w3^T)
    k_gemm<1, 128, 1><<<dim3(Tn / 128, In / 128, En), 512, SMEM1>>>(
        (const float*)px2, w1, w3, (float*)ph1, nullptr, Tn, In, Dn);
    // w2 grouped GEMM, split-K2, scatter into 4-slot eo
    k_gemm<2, 256, 2><<<dim3(Tn / 128, Dn / 256, En * 2), 512, SMEM2>>>(
        (const float*)ph1, w2, nullptr, (float*)peo, nullptr, Tn, Dn, In);
    k_combine<<<(Tn * Dn) / 256, 256>>>(moe_out);
}

// round 10
// speedup vs baseline: 11.5293x; 1.0772x over previous
#include <cuda_runtime.h>
#include <cuda_fp16.h>
#include <math.h>
#include <stdint.h>

#define Tn 512
#define Dn 2048
#define Hn 32
#define KVn 8
#define DHn 64
#define In 7168
#define En 8
#define QKVn 3072   // (H + 2*KV) * DH
#define PADH 40     // GEMM smem row stride in halfs
#define PADA 72     // attention smem row stride in halfs (64 data + 8 pad)

// ---------------- scratch (device globals; no allocation allowed) ----------------
__device__ __align__(16) float g_res1[Tn * Dn];
__device__ __align__(16) float g_x[Tn * Dn];
__device__ __align__(16) float g_qkv[Tn * QKVn];
__device__ __align__(16) float g_scores[Hn * Tn * Tn];
__device__ __align__(16) float g_attn[Tn * Dn];
__device__ __align__(16) float g_x2[Tn * Dn];
__device__ __align__(16) float g_h1[En * Tn * In];
__device__ __align__(16) float g_eo[Tn * 4 * Dn];
__device__ int   g_tok[En * Tn];
__device__ float g_wgt[En * Tn];
__device__ int   g_slot[En * Tn];
__device__ int   g_cnt[En];

// ================= helpers (sm_80-level features only) =================
__device__ __forceinline__ uint32_t smem_u32(const void* p) {
    uint32_t a;
    asm("{ .reg .u64 t; cvta.to.shared.u64 t, %1; cvt.u32.u64 %0, t; }" : "=r"(a) : "l"(p));
    return a;
}
__device__ __forceinline__ uint32_t pack_h2(float x, float y) {
    __half2 h = __floats2half2_rn(x, y);
    return *reinterpret_cast<uint32_t*>(&h);
}
__device__ __forceinline__ uint4 cvt8(float4 a, float4 b) {
    uint4 u;
    u.x = pack_h2(a.x, a.y); u.y = pack_h2(a.z, a.w);
    u.z = pack_h2(b.x, b.y); u.w = pack_h2(b.z, b.w);
    return u;
}
__device__ __forceinline__ void mma_f16(float* c, const uint32_t* a, const uint32_t* b) {
    asm volatile(
        "mma.sync.aligned.m16n8k16.row.col.f32.f16.f16.f32 "
        "{%0,%1,%2,%3}, {%4,%5,%6,%7}, {%8,%9}, {%0,%1,%2,%3};"
        : "+f"(c[0]), "+f"(c[1]), "+f"(c[2]), "+f"(c[3])
        : "r"(a[0]), "r"(a[1]), "r"(a[2]), "r"(a[3]), "r"(b[0]), "r"(b[1]));
}
__device__ __forceinline__ void ldsm_x4(uint32_t& r0, uint32_t& r1, uint32_t& r2, uint32_t& r3,
                                        uint32_t addr) {
    asm volatile("ldmatrix.sync.aligned.m8n8.x4.shared.b16 {%0,%1,%2,%3}, [%4];"
                 : "=r"(r0), "=r"(r1), "=r"(r2), "=r"(r3) : "r"(addr));
}
__device__ __forceinline__ void ldsm_x4_t(uint32_t& r0, uint32_t& r1, uint32_t& r2, uint32_t& r3,
                                          uint32_t addr) {
    asm volatile("ldmatrix.sync.aligned.m8n8.x4.trans.shared.b16 {%0,%1,%2,%3}, [%4];"
                 : "=r"(r0), "=r"(r1), "=r"(r2), "=r"(r3) : "r"(addr));
}

// ================= fp16 tensor-core GEMM (unchanged core from R9) =================
template <int MODE, int NT, int KSPLIT>
__global__ void __launch_bounds__(512, 1) k_gemm(const float* __restrict__ A,
                                                 const float* __restrict__ B,
                                                 const float* __restrict__ B2,
                                                 float* __restrict__ C,
                                                 float* __restrict__ C2,
                                                 int M, int N, int Kstride) {
    constexpr int BNT = NT / 32;
    constexpr int NPAIR = BNT / 2;
    constexpr int WN = NT / 4;
    constexpr int NB = (MODE == 1) ? 2 : 1;
    constexpr int NBB = (MODE == 1) ? 2 : (NT / 128);
    constexpr int A_HALFS = 128 * PADH;
    constexpr int B_HALFS = NT * PADH;
    constexpr int STAGE_HALFS = A_HALFS + NB * B_HALFS;
    constexpr int STAGE_BYTES = STAGE_HALFS * 2;

    const int kh = (MODE == 2) ? (int)(blockIdx.z & 1) : ((MODE == 0) ? (int)blockIdx.z : 0);
    const int e  = (MODE == 0) ? 0 : ((MODE == 2) ? (int)(blockIdx.z >> 1) : (int)blockIdx.z);
    const int cnt = (MODE == 0) ? M : g_cnt[e];
    const int bm = blockIdx.x * 128;
    if (bm >= cnt) return;
    const int bn = blockIdx.y * NT;

    const float* Bp  = (MODE == 0) ? B  : B  + (size_t)e * N * Kstride;
    const float* Bp2 = (MODE == 1) ? B2 + (size_t)e * N * Kstride : nullptr;

    const int Klen = Kstride / KSPLIT;
    const int koff = kh * Klen;

    const int tid = threadIdx.x;
    const int wid = tid >> 5, lane = tid & 31;
    const int g = lane >> 2, t4 = lane & 3;
    const int wm = (wid & 3) * 32, wn = (wid >> 2) * WN;

    const int rows_avail = cnt - bm - wm;
    const int mtact = (rows_avail >= 32) ? 2 : ((rows_avail <= 0) ? 0 : ((rows_avail + 15) >> 4));

    extern __shared__ char smc[];
    const uint32_t smU = smem_u32(smc);

    const int arow = tid >> 2;
    const int acol = (tid & 3) * 8;

    const float* aSrc;
    {
        if (MODE == 0) {
            int ridx = bm + arow; if (ridx >= M) ridx = M - 1;
            aSrc = A + (size_t)ridx * Kstride + acol + koff;
        } else if (MODE == 1) {
            int idx = bm + arow;
            int tok = (idx < cnt) ? g_tok[e * Tn + idx] : g_tok[e * Tn];
            aSrc = A + (size_t)tok * Kstride + acol + koff;
        } else {
            int idx = bm + arow;
            aSrc = A + ((size_t)e * Tn + idx) * (size_t)Kstride + acol + koff;
        }
    }
    const uint32_t aSts = (uint32_t)(arow * PADH + acol) * 2u;

    const float* bSrc[NBB];
    uint32_t bSts[NBB];
#pragma unroll
    for (int j = 0; j < NBB; j++) {
        const int rowoff = (MODE == 2) ? j * 128 : 0;
        const float* base = (MODE == 1 && j == 1) ? Bp2 : Bp;
        const int moff = (MODE == 1 && j == 1) ? 1 : 0;
        bSrc[j] = base + (size_t)(bn + rowoff + arow) * Kstride + acol + koff;
        bSts[j] = (uint32_t)(A_HALFS + moff * B_HALFS + (rowoff + arow) * PADH + acol) * 2u;
    }

    const int l4 = lane >> 3, lr = lane & 7;
    uint32_t aAddr[2];
#pragma unroll
    for (int mt = 0; mt < 2; mt++) {
        int m_local = wm + mt * 16 + (l4 & 1) * 8 + lr;
        aAddr[mt] = smU + (uint32_t)(m_local * PADH) * 2u + (uint32_t)(l4 >> 1) * 16u;
    }
    uint32_t bAddr[NPAIR];
#pragma unroll
    for (int p = 0; p < NPAIR; p++) {
        int n_local = wn + p * 16 + (l4 >> 1) * 8 + lr;
        bAddr[p] = smU + (uint32_t)(A_HALFS + n_local * PADH) * 2u + (uint32_t)(l4 & 1) * 16u;
    }

    float acc[2][BNT][4];
    float acc2[MODE == 1 ? 2 : 1][MODE == 1 ? BNT : 1][4];
#pragma unroll
    for (int mt = 0; mt < 2; mt++)
#pragma unroll
        for (int nt = 0; nt < BNT; nt++)
#pragma unroll
            for (int q = 0; q < 4; q++) acc[mt][nt][q] = 0.f;
    if (MODE == 1) {
#pragma unroll
        for (int mt = 0; mt < 2; mt++)
#pragma unroll
            for (int nt = 0; nt < BNT; nt++)
#pragma unroll
                for (int q = 0; q < 4; q++) acc2[mt][nt][q] = 0.f;
    }

    float4 ra0, ra1;
    float4 rb0[NBB], rb1[NBB];

#define LDG_STAGE(ktn)                                                   \
    do {                                                                 \
        const int k0 = (ktn) * 32;                                       \
        ra0 = *(const float4*)(aSrc + k0);                               \
        ra1 = *(const float4*)(aSrc + k0 + 4);                           \
        _Pragma("unroll")                                                \
        for (int j = 0; j < NBB; j++) {                                  \
            rb0[j] = *(const float4*)(bSrc[j] + k0);                     \
            rb1[j] = *(const float4*)(bSrc[j] + k0 + 4);                 \
        }                                                                \
    } while (0)

#define STS_STAGE(ktn)                                                   \
    do {                                                                 \
        char* sb = smc + ((ktn) & 1) * STAGE_BYTES;                      \
        *(uint4*)(sb + aSts) = cvt8(ra0, ra1);                           \
        _Pragma("unroll")                                                \
        for (int j = 0; j < NBB; j++)                                    \
            *(uint4*)(sb + bSts[j]) = cvt8(rb0[j], rb1[j]);              \
    } while (0)

    const int KT = Klen / 32;

    LDG_STAGE(0);
    STS_STAGE(0);
    __syncthreads();
    LDG_STAGE(1);

    for (int kt = 0; kt < KT; kt++) {
        const uint32_t so = (uint32_t)(kt & 1) * STAGE_BYTES;
#pragma unroll
        for (int ks = 0; ks < 2; ks++) {
            const uint32_t kso = so + (uint32_t)ks * 32u;
            uint32_t af[2][4];
#pragma unroll
            for (int mt = 0; mt < 2; mt++)
                if (mt < mtact)
                    ldsm_x4(af[mt][0], af[mt][1], af[mt][2], af[mt][3], aAddr[mt] + kso);
            if (mtact > 0) {
                uint32_t bf[BNT][2];
#pragma unroll
                for (int p = 0; p < NPAIR; p++)
                    ldsm_x4(bf[2 * p][0], bf[2 * p][1], bf[2 * p + 1][0], bf[2 * p + 1][1],
                            bAddr[p] + kso);
#pragma unroll
                for (int mt = 0; mt < 2; mt++)
                    if (mt < mtact)
#pragma unroll
                        for (int nt = 0; nt < BNT; nt++)
                            mma_f16(acc[mt][nt], af[mt], bf[nt]);
                if (MODE == 1) {
                    uint32_t bg[BNT][2];
#pragma unroll
                    for (int p = 0; p < NPAIR; p++)
                        ldsm_x4(bg[2 * p][0], bg[2 * p][1], bg[2 * p + 1][0], bg[2 * p + 1][1],
                                bAddr[p] + (uint32_t)(B_HALFS * 2) + kso);
#pragma unroll
                    for (int mt = 0; mt < 2; mt++)
                        if (mt < mtact)
#pragma unroll
                            for (int nt = 0; nt < BNT; nt++)
                                mma_f16(acc2[mt][nt], af[mt], bg[nt]);
                }
            }
        }
        if (kt + 1 < KT) {
            STS_STAGE(kt + 1);
            if (kt + 2 < KT) LDG_STAGE(kt + 2);
            __syncthreads();
        }
    }
#undef LDG_STAGE
#undef STS_STAGE

#pragma unroll
    for (int mt = 0; mt < 2; mt++) {
        if (mt >= mtact) continue;
#pragma unroll
        for (int h = 0; h < 2; h++) {
            const int ridx = bm + wm + mt * 16 + g + h * 8;
            bool valid;
            float* dst = nullptr;
            float wg = 1.f;
            if (MODE == 0) {
                valid = ridx < M;
                if (valid) dst = C + (size_t)kh * M * N + (size_t)ridx * N;
            } else if (MODE == 1) {
                valid = ridx < cnt;
                if (valid) dst = C + ((size_t)e * Tn + ridx) * (size_t)N;
            } else {
                valid = ridx < cnt;
                if (valid) {
                    int idx = e * Tn + ridx;
                    int tok = g_tok[idx];
                    wg = g_wgt[idx];
                    int sl = g_slot[idx];
                    dst = C + ((size_t)tok * 4 + sl * 2 + kh) * (size_t)Dn;
                }
            }
            if (!valid) continue;
#pragma unroll
            for (int nt = 0; nt < BNT; nt++) {
                const int col = bn + wn + nt * 8 + 2 * t4;
                float2 v = make_float2(acc[mt][nt][h * 2 + 0], acc[mt][nt][h * 2 + 1]);
                if (MODE == 1) {
                    float b0 = acc2[mt][nt][h * 2 + 0];
                    float b1 = acc2[mt][nt][h * 2 + 1];
                    v.x = (v.x / (1.f + __expf(-v.x))) * b0;
                    v.y = (v.y / (1.f + __expf(-v.y))) * b1;
                } else if (MODE == 2) {
                    v.x *= wg; v.y *= wg;
                }
                *(float2*)(dst + col) = v;
            }
        }
    }
}

// ================= attention: scores via fp16 MMA =================
// Tile: 128 q-rows x 64 k-cols per CTA. grid = (kt 8, qt 4, h 32), 256 threads.
__global__ void __launch_bounds__(256, 1) k_scores_mma() {
    const int kt = blockIdx.x, qt = blockIdx.y, h = blockIdx.z;
    const int tid = threadIdx.x;
    const int wid = tid >> 5, lane = tid & 31;
    const int g = lane >> 2, t4 = lane & 3;
    const int wm = (wid & 3) * 32;           // q offset within 128
    const int wn = (wid >> 2) * 32;          // k offset within 64

    // fully masked tile: fill -1e30 and exit
    if (kt * 64 > qt * 128 + 127) {
#pragma unroll
        for (int mt = 0; mt < 2; mt++)
#pragma unroll
            for (int hh = 0; hh < 2; hh++) {
                int row = qt * 128 + wm + mt * 16 + g + hh * 8;
#pragma unroll
                for (int nt = 0; nt < 4; nt++) {
                    int col = kt * 64 + wn + nt * 8 + 2 * t4;
                    float* p = &g_scores[((size_t)h * Tn + row) * Tn + col];
                    p[0] = -1e30f; p[1] = -1e30f;
                }
            }
        return;
    }

    __shared__ __align__(16) __half Qs[128 * PADA];
    __shared__ __align__(16) __half Ks[64 * PADA];
    const uint32_t qU = smem_u32(Qs);
    const uint32_t kU = smem_u32(Ks);
    const int kvh = h >> 2;

    // stage Q (128x64) and K (64x64) as fp16
    for (int idx = tid; idx < 128 * 8; idx += 256) {
        int row = idx >> 3, c8 = (idx & 7) * 8;
        const float* src = g_qkv + (size_t)(qt * 128 + row) * QKVn + h * 64 + c8;
        *(uint4*)((char*)Qs + (row * PADA + c8) * 2) =
            cvt8(*(const float4*)src, *(const float4*)(src + 4));
    }
    for (int idx = tid; idx < 64 * 8; idx += 256) {
        int row = idx >> 3, c8 = (idx & 7) * 8;
        const float* src = g_qkv + (size_t)(kt * 64 + row) * QKVn + 2048 + kvh * 64 + c8;
        *(uint4*)((char*)Ks + (row * PADA + c8) * 2) =
            cvt8(*(const float4*)src, *(const float4*)(src + 4));
    }
    __syncthreads();

    const int l4 = lane >> 3, lr = lane & 7;
    uint32_t aAddr[2], bAddr[2];
#pragma unroll
    for (int mt = 0; mt < 2; mt++) {
        int m_local = wm + mt * 16 + (l4 & 1) * 8 + lr;
        aAddr[mt] = qU + (uint32_t)(m_local * PADA) * 2u + (uint32_t)(l4 >> 1) * 16u;
    }
#pragma unroll
    for (int p = 0; p < 2; p++) {
        int n_local = wn + p * 16 + (l4 >> 1) * 8 + lr;
        bAddr[p] = kU + (uint32_t)(n_local * PADA) * 2u + (uint32_t)(l4 & 1) * 16u;
    }

    float acc[2][4][4];
#pragma unroll
    for (int mt = 0; mt < 2; mt++)
#pragma unroll
        for (int nt = 0; nt < 4; nt++)
#pragma unroll
            for (int q = 0; q < 4; q++) acc[mt][nt][q] = 0.f;

#pragma unroll
    for (int ks = 0; ks < 4; ks++) {
        const uint32_t kso = (uint32_t)ks * 32u;
        uint32_t af[2][4], bf[4][2];
#pragma unroll
        for (int mt = 0; mt < 2; mt++)
            ldsm_x4(af[mt][0], af[mt][1], af[mt][2], af[mt][3], aAddr[mt] + kso);
#pragma unroll
        for (int p = 0; p < 2; p++)
            ldsm_x4(bf[2 * p][0], bf[2 * p][1], bf[2 * p + 1][0], bf[2 * p + 1][1],
                    bAddr[p] + kso);
#pragma unroll
        for (int mt = 0; mt < 2; mt++)
#pragma unroll
            for (int nt = 0; nt < 4; nt++)
                mma_f16(acc[mt][nt], af[mt], bf[nt]);
    }

    const float scale = 0.125f;
#pragma unroll
    for (int mt = 0; mt < 2; mt++)
#pragma unroll
        for (int hh = 0; hh < 2; hh++) {
            int row = qt * 128 + wm + mt * 16 + g + hh * 8;
#pragma unroll
            for (int nt = 0; nt < 4; nt++) {
                int col = kt * 64 + wn + nt * 8 + 2 * t4;
                float v0 = (col     <= row) ? acc[mt][nt][hh * 2 + 0] * scale : -1e30f;
                float v1 = (col + 1 <= row) ? acc[mt][nt][hh * 2 + 1] * scale : -1e30f;
                float* p = &g_scores[((size_t)h * Tn + row) * Tn + col];
                p[0] = v0; p[1] = v1;
            }
        }
}

// ================= attention: P@V via fp16 MMA (V via trans-ldmatrix) =================
// Tile: 128 q-rows x 64 dh per CTA. grid = (qt 4, h 32), 256 threads.
__global__ void __launch_bounds__(256, 1) k_attnv_mma() {
    const int qt = blockIdx.x, h = blockIdx.y;
    const int tid = threadIdx.x;
    const int wid = tid >> 5, lane = tid & 31;
    const int g = lane >> 2, t4 = lane & 3;
    const int wm = (wid & 3) * 32;           // q offset
    const int wn = (wid >> 2) * 32;          // dh offset
    const int kvh = h >> 2;

    __shared__ __align__(16) __half Ps[128 * PADA];
    __shared__ __align__(16) __half Vs[64 * PADA];
    const uint32_t pU = smem_u32(Ps);
    const uint32_t vU = smem_u32(Vs);

    const int l4 = lane >> 3, lr = lane & 7;
    uint32_t aAddr[2];
#pragma unroll
    for (int mt = 0; mt < 2; mt++) {
        int m_local = wm + mt * 16 + (l4 & 1) * 8 + lr;
        aAddr[mt] = pU + (uint32_t)(m_local * PADA) * 2u + (uint32_t)(l4 >> 1) * 16u;
    }
    // trans-ldmatrix addresses into V stored [k][dh]: subtile order (k-low,dh-low),
    // (k-high,dh-low),(k-low,dh-high),(k-high,dh-high) = non-trans order on V^T.
    uint32_t bAddr[2];
#pragma unroll
    for (int p = 0; p < 2; p++) {
        int k_row = (l4 & 1) * 8 + lr;
        int dh_c = wn + p * 16 + (l4 >> 1) * 8;
        bAddr[p] = vU + (uint32_t)(k_row * PADA + dh_c) * 2u;
    }

    float acc[2][4][4];
#pragma unroll
    for (int mt = 0; mt < 2; mt++)
#pragma unroll
        for (int nt = 0; nt < 4; nt++)
#pragma unroll
            for (int q = 0; q < 4; q++) acc[mt][nt][q] = 0.f;

    const int ktmax = 2 * qt + 1;
    for (int kt = 0; kt <= ktmax; kt++) {
        // stage P (128 x 64) fp16 — softmax already zeroed masked cols
        for (int idx = tid; idx < 128 * 8; idx += 256) {
            int row = idx >> 3, c8 = (idx & 7) * 8;
            const float* src = &g_scores[((size_t)h * Tn + qt * 128 + row) * Tn + kt * 64 + c8];
            *(uint4*)((char*)Ps + (row * PADA + c8) * 2) =
                cvt8(*(const float4*)src, *(const float4*)(src + 4));
        }
        // stage V (64 k x 64 dh) fp16
        for (int idx = tid; idx < 64 * 8; idx += 256) {
            int row = idx >> 3, c8 = (idx & 7) * 8;
            const float* src = g_qkv + (size_t)(kt * 64 + row) * QKVn + 2560 + kvh * 64 + c8;
            *(uint4*)((char*)Vs + (row * PADA + c8) * 2) =
                cvt8(*(const float4*)src, *(const float4*)(src + 4));
        }
        __syncthreads();

#pragma unroll
        for (int ks = 0; ks < 4; ks++) {
            uint32_t af[2][4], bf[4][2];
#pragma unroll
            for (int mt = 0; mt < 2; mt++)
                ldsm_x4(af[mt][0], af[mt][1], af[mt][2], af[mt][3],
                        aAddr[mt] + (uint32_t)ks * 32u);
#pragma unroll
            for (int p = 0; p < 2; p++)
                ldsm_x4_t(bf[2 * p][0], bf[2 * p][1], bf[2 * p + 1][0], bf[2 * p + 1][1],
                          bAddr[p] + (uint32_t)(ks * 16 * PADA) * 2u);
#pragma unroll
            for (int mt = 0; mt < 2; mt++)
#pragma unroll
                for (int nt = 0; nt < 4; nt++)
                    mma_f16(acc[mt][nt], af[mt], bf[nt]);
        }
        __syncthreads();
    }

#pragma unroll
    for (int mt = 0; mt < 2; mt++)
#pragma unroll
        for (int hh = 0; hh < 2; hh++) {
            int row = qt * 128 + wm + mt * 16 + g + hh * 8;
#pragma unroll
            for (int nt = 0; nt < 4; nt++) {
                int col = wn + nt * 8 + 2 * t4;
                float* p = &g_attn[(size_t)row * Dn + h * 64 + col];
                p[0] = acc[mt][nt][hh * 2 + 0];
                p[1] = acc[mt][nt][hh * 2 + 1];
            }
        }
}

// ---------------- small utility kernels ----------------

__global__ void k_zero_cnt() {
    if (threadIdx.x < En) g_cnt[threadIdx.x] = 0;
}

__global__ void k_add_rmsnorm(const float* __restrict__ h, const float* __restrict__ r,
                              const float* __restrict__ w) {
    int t = blockIdx.x;
    const float* hr = h + t * Dn;
    const float* rr = r + t * Dn;
    float* resr = g_res1 + t * Dn;
    float* xr = g_x + t * Dn;

    float v[8];
    float local = 0.f;
#pragma unroll
    for (int j = 0; j < 8; j++) {
        int c = threadIdx.x + j * 256;
        float s = hr[c] + rr[c];
        v[j] = s;
        resr[c] = s;
        local += s * s;
    }
#pragma unroll
    for (int o = 16; o > 0; o >>= 1) local += __shfl_xor_sync(0xffffffffu, local, o);
    __shared__ float red[8];
    if ((threadIdx.x & 31) == 0) red[threadIdx.x >> 5] = local;
    __syncthreads();
    __shared__ float inv;
    if (threadIdx.x == 0) {
        float s = 0.f;
#pragma unroll
        for (int i = 0; i < 8; i++) s += red[i];
        inv = rsqrtf(s / (float)Dn + 1e-5f);
    }
    __syncthreads();
    float iv = inv;
#pragma unroll
    for (int j = 0; j < 8; j++) {
        int c = threadIdx.x + j * 256;
        xr[c] = v[j] * iv * w[c];
    }
}

__global__ void k_add2_rmsnorm(const float* __restrict__ p0, const float* __restrict__ p1,
                               const float* __restrict__ w, float* __restrict__ res2out) {
    int t = blockIdx.x;
    const float* a0 = p0 + t * Dn;
    const float* a1 = p1 + t * Dn;
    const float* rr = g_res1 + t * Dn;
    float* ro = res2out + t * Dn;
    float* xr = g_x2 + t * Dn;
    float v[8];
    float local = 0.f;
#pragma unroll
    for (int j = 0; j < 8; j++) {
        int c = threadIdx.x + j * 256;
        float s = a0[c] + a1[c] + rr[c];
        v[j] = s;
        ro[c] = s;
        local += s * s;
    }
#pragma unroll
    for (int o = 16; o > 0; o >>= 1) local += __shfl_xor_sync(0xffffffffu, local, o);
    __shared__ float red[8];
    if ((threadIdx.x & 31) == 0) red[threadIdx.x >> 5] = local;
    __syncthreads();
    __shared__ float inv;
    if (threadIdx.x == 0) {
        float s = 0.f;
#pragma unroll
        for (int i = 0; i < 8; i++) s += red[i];
        inv = rsqrtf(s / (float)Dn + 1e-5f);
    }
    __syncthreads();
    float iv = inv;
#pragma unroll
    for (int j = 0; j < 8; j++) {
        int c = threadIdx.x + j * 256;
        xr[c] = v[j] * iv * w[c];
    }
}

__global__ void k_rope(const float* __restrict__ cosb, const float* __restrict__ sinb) {
    int idx = blockIdx.x * 256 + threadIdx.x;
    if (idx >= Tn * 40 * 32) return;
    int d = idx & 31;
    int rest = idx >> 5;
    int hh = rest % 40;
    int t = rest / 40;
    float c = cosb[t * 32 + d];
    float s = sinb[t * 32 + d];
    float* base = g_qkv + (size_t)t * QKVn + hh * 64 + d;
    float x1 = base[0];
    float x2 = base[32];
    base[0] = x1 * c - x2 * s;
    base[32] = x2 * c + x1 * s;
}

__global__ void k_softmax() {
    const int row = blockIdx.x;
    float* p = g_scores + (size_t)row * Tn;
    const int tid = threadIdx.x;
    float v[4];
    float mx = -3.4e38f;
#pragma unroll
    for (int j = 0; j < 4; j++) {
        v[j] = p[tid + j * 128];
        mx = fmaxf(mx, v[j]);
    }
#pragma unroll
    for (int o = 16; o > 0; o >>= 1) mx = fmaxf(mx, __shfl_xor_sync(0xffffffffu, mx, o));
    __shared__ float rm[4];
    if ((tid & 31) == 0) rm[tid >> 5] = mx;
    __syncthreads();
    mx = fmaxf(fmaxf(rm[0], rm[1]), fmaxf(rm[2], rm[3]));
    float sum = 0.f;
#pragma unroll
    for (int j = 0; j < 4; j++) {
        v[j] = __expf(v[j] - mx);
        sum += v[j];
    }
#pragma unroll
    for (int o = 16; o > 0; o >>= 1) sum += __shfl_xor_sync(0xffffffffu, sum, o);
    __shared__ float rs[4];
    if ((tid & 31) == 0) rs[tid >> 5] = sum;
    __syncthreads();
    sum = rs[0] + rs[1] + rs[2] + rs[3];
    float inv = 1.f / sum;
#pragma unroll
    for (int j = 0; j < 4; j++) p[tid + j * 128] = v[j] * inv;
}

__global__ void k_gate(const float* __restrict__ gw) {
    const int t = blockIdx.x;
    const int warp = threadIdx.x >> 5, lane = threadIdx.x & 31;
    const float* xr = g_x2 + (size_t)t * Dn;
    const float* wr = gw + (size_t)warp * Dn;
    float s = 0.f;
    for (int c = lane; c < Dn; c += 32) s += xr[c] * wr[c];
#pragma unroll
    for (int o = 16; o > 0; o >>= 1) s += __shfl_xor_sync(0xffffffffu, s, o);
    __shared__ float lg[En];
    if (lane == 0) lg[warp] = s;
    __syncthreads();
    if (threadIdx.x == 0) {
        int i0 = 0;
        for (int e = 1; e < En; e++) if (lg[e] > lg[i0]) i0 = e;
        int i1 = (i0 == 0) ? 1 : 0;
        for (int e = 0; e < En; e++) if (e != i0 && lg[e] > lg[i1]) i1 = e;
        float w1v = __expf(lg[i1] - lg[i0]);
        float inv = 1.f / (1.f + w1v);
        float w0 = inv, w1n = w1v * inv;
        int p0 = atomicAdd(&g_cnt[i0], 1);
        g_tok[i0 * Tn + p0] = t; g_wgt[i0 * Tn + p0] = w0; g_slot[i0 * Tn + p0] = 0;
        int p1 = atomicAdd(&g_cnt[i1], 1);
        g_tok[i1 * Tn + p1] = t; g_wgt[i1 * Tn + p1] = w1n; g_slot[i1 * Tn + p1] = 1;
    }
}

__global__ void k_combine(float* __restrict__ out) {
    int i = blockIdx.x * 256 + threadIdx.x;
    if (i >= Tn * Dn) return;
    int t = i / Dn;
    int d = i - t * Dn;
    const float* base = g_eo + (size_t)t * 4 * Dn + d;
    out[i] = base[0] + base[Dn] + base[2 * Dn] + base[3 * Dn];
}

// ---------------- launch ----------------
extern "C" void kernel_launch(void* const* d_in, const int* in_sizes, int n_in,
                              void* d_out, int out_size) {
    const float* hs   = (const float*)d_in[0];
    const float* resi = (const float*)d_in[1];
    const float* cosb = (const float*)d_in[2];
    const float* sinb = (const float*)d_in[3];
    const float* ln1  = (const float*)d_in[4];
    const float* ln2  = (const float*)d_in[5];
    const float* wqkv = (const float*)d_in[6];
    const float* wo   = (const float*)d_in[7];
    const float* gw   = (const float*)d_in[8];
    const float* w1   = (const float*)d_in[9];
    const float* w3   = (const float*)d_in[10];
    const float* w2   = (const float*)d_in[11];

    float* out = (float*)d_out;
    float* moe_out = out;
    float* res2 = out + Tn * Dn;

    void *px, *pqkv, *pattn, *px2, *ph1, *peo;
    cudaGetSymbolAddress(&px, g_x);
    cudaGetSymbolAddress(&pqkv, g_qkv);
    cudaGetSymbolAddress(&pattn, g_attn);
    cudaGetSymbolAddress(&px2, g_x2);
    cudaGetSymbolAddress(&ph1, g_h1);
    cudaGetSymbolAddress(&peo, g_eo);

    constexpr int SMEM0 = 2 * (128 * PADH + 128 * PADH) * 2;       // 40960
    constexpr int SMEM1 = 2 * (128 * PADH + 2 * 128 * PADH) * 2;   // 61440
    constexpr int SMEM2 = 2 * (128 * PADH + 256 * PADH) * 2;       // 61440
    cudaFuncSetAttribute(k_gemm<0, 128, 1>, cudaFuncAttributeMaxDynamicSharedMemorySize, SMEM0);
    cudaFuncSetAttribute(k_gemm<0, 128, 2>, cudaFuncAttributeMaxDynamicSharedMemorySize, SMEM0);
    cudaFuncSetAttribute(k_gemm<1, 128, 1>, cudaFuncAttributeMaxDynamicSharedMemorySize, SMEM1);
    cudaFuncSetAttribute(k_gemm<2, 256, 2>, cudaFuncAttributeMaxDynamicSharedMemorySize, SMEM2);

    k_zero_cnt<<<1, 32>>>();
    k_add_rmsnorm<<<Tn, 256>>>(hs, resi, ln1);

    // qkv direct (no split-K): [512][3072] into g_qkv, then rope
    k_gemm<0, 128, 1><<<dim3(Tn / 128, QKVn / 128, 1), 512, SMEM0>>>(
        (const float*)px, wqkv, nullptr, (float*)pqkv, nullptr, Tn, QKVn, Dn);
    k_rope<<<(Tn * 40 * 32) / 256, 256>>>(cosb, sinb);

    k_scores_mma<<<dim3(Tn / 64, Tn / 128, Hn), 256>>>();
    k_softmax<<<Hn * Tn, 128>>>();
    k_attnv_mma<<<dim3(Tn / 128, Hn), 256>>>();

    // attn @ wo^T partials: [2][512][2048] into g_eo; fused add + rmsnorm
    k_gemm<0, 128, 2><<<dim3(Tn / 128, Dn / 128, 2), 512, SMEM0>>>(
        (const float*)pattn, wo, nullptr, (float*)peo, nullptr, Tn, Dn, Dn);
    k_add2_rmsnorm<<<Tn, 256>>>((const float*)peo, (const float*)peo + Tn * Dn, ln2, res2);
    k_gate<<<Tn, 256>>>(gw);

    // fused dual-B grouped GEMM1: h1 = silu(x@w1^T) * (x@w3^T)
    k_gemm<1, 128, 1><<<dim3(Tn / 128, In / 128, En), 512, SMEM1>>>(
        (const float*)px2, w1, w3, (float*)ph1, nullptr, Tn, In, Dn);
    // w2 grouped GEMM, split-K2, scatter into 4-slot eo
    k_gemm<2, 256, 2><<<dim3(Tn / 128, Dn / 256, En * 2), 512, SMEM2>>>(
        (const float*)ph1, w2, nullptr, (float*)peo, nullptr, Tn, Dn, In);
    k_combine<<<(Tn * Dn) / 256, 256>>>(moe_out);
}

// round 11
// speedup vs baseline: 11.8782x; 1.0303x over previous
#include <cuda_runtime.h>
#include <cuda_fp16.h>
#include <math.h>
#include <stdint.h>

#define Tn 512
#define Dn 2048
#define Hn 32
#define KVn 8
#define DHn 64
#define In 7168
#define En 8
#define QKVn 3072   // (H + 2*KV) * DH
#define PADH 40     // GEMM smem row stride in halfs
#define PADA 72     // attention smem row stride in halfs (64 data + 8 pad)

// ---------------- scratch (device globals; no allocation allowed) ----------------
__device__ __align__(16) float g_res1[Tn * Dn];
__device__ __align__(16) float g_x[Tn * Dn];
__device__ __align__(16) float g_qkv[Tn * QKVn];
__device__ __align__(16) __half g_scoresh[Hn * Tn * Tn];
__device__ __align__(16) float g_attn[Tn * Dn];
__device__ __align__(16) float g_x2[Tn * Dn];
__device__ __align__(16) __half g_h1h[En * Tn * In];
__device__ __align__(16) float g_eo[Tn * 4 * Dn];
__device__ int   g_tok[En * Tn];
__device__ float g_wgt[En * Tn];
__device__ int   g_slot[En * Tn];
__device__ int   g_cnt[En];

// ================= helpers (sm_80-level features only) =================
__device__ __forceinline__ uint32_t smem_u32(const void* p) {
    uint32_t a;
    asm("{ .reg .u64 t; cvta.to.shared.u64 t, %1; cvt.u32.u64 %0, t; }" : "=r"(a) : "l"(p));
    return a;
}
__device__ __forceinline__ uint32_t pack_h2(float x, float y) {
    __half2 h = __floats2half2_rn(x, y);
    return *reinterpret_cast<uint32_t*>(&h);
}
__device__ __forceinline__ uint4 cvt8(float4 a, float4 b) {
    uint4 u;
    u.x = pack_h2(a.x, a.y); u.y = pack_h2(a.z, a.w);
    u.z = pack_h2(b.x, b.y); u.w = pack_h2(b.z, b.w);
    return u;
}
__device__ __forceinline__ void mma_f16(float* c, const uint32_t* a, const uint32_t* b) {
    asm volatile(
        "mma.sync.aligned.m16n8k16.row.col.f32.f16.f16.f32 "
        "{%0,%1,%2,%3}, {%4,%5,%6,%7}, {%8,%9}, {%0,%1,%2,%3};"
        : "+f"(c[0]), "+f"(c[1]), "+f"(c[2]), "+f"(c[3])
        : "r"(a[0]), "r"(a[1]), "r"(a[2]), "r"(a[3]), "r"(b[0]), "r"(b[1]));
}
__device__ __forceinline__ void ldsm_x4(uint32_t& r0, uint32_t& r1, uint32_t& r2, uint32_t& r3,
                                        uint32_t addr) {
    asm volatile("ldmatrix.sync.aligned.m8n8.x4.shared.b16 {%0,%1,%2,%3}, [%4];"
                 : "=r"(r0), "=r"(r1), "=r"(r2), "=r"(r3) : "r"(addr));
}
__device__ __forceinline__ void ldsm_x4_t(uint32_t& r0, uint32_t& r1, uint32_t& r2, uint32_t& r3,
                                          uint32_t addr) {
    asm volatile("ldmatrix.sync.aligned.m8n8.x4.trans.shared.b16 {%0,%1,%2,%3}, [%4];"
                 : "=r"(r0), "=r"(r1), "=r"(r2), "=r"(r3) : "r"(addr));
}

// ================= fp16 tensor-core GEMM =================
// MODE 0: plain split-K partials (fp32 A).
// MODE 1: dual-B fused w1/w3 (gather; silu epilogue -> fp16 C).
// MODE 2: MoE gemm2 split-K2 (fp16 A = g_h1h), weighted scatter to g_eo 4-slot.
template <int MODE, int NT, int KSPLIT>
__global__ void __launch_bounds__(512, 1) k_gemm(const float* __restrict__ A,
                                                 const float* __restrict__ B,
                                                 const float* __restrict__ B2,
                                                 float* __restrict__ C,
                                                 float* __restrict__ C2,
                                                 int M, int N, int Kstride) {
    constexpr int BNT = NT / 32;
    constexpr int NPAIR = BNT / 2;
    constexpr int WN = NT / 4;
    constexpr int NB = (MODE == 1) ? 2 : 1;
    constexpr int NBB = (MODE == 1) ? 2 : (NT / 128);
    constexpr int A_HALFS = 128 * PADH;
    constexpr int B_HALFS = NT * PADH;
    constexpr int STAGE_HALFS = A_HALFS + NB * B_HALFS;
    constexpr int STAGE_BYTES = STAGE_HALFS * 2;

    const int kh = (MODE == 2) ? (int)(blockIdx.z & 1) : ((MODE == 0) ? (int)blockIdx.z : 0);
    const int e  = (MODE == 0) ? 0 : ((MODE == 2) ? (int)(blockIdx.z >> 1) : (int)blockIdx.z);
    const int cnt = (MODE == 0) ? M : g_cnt[e];
    const int bm = blockIdx.x * 128;
    if (bm >= cnt) return;
    const int bn = blockIdx.y * NT;

    const float* Bp  = (MODE == 0) ? B  : B  + (size_t)e * N * Kstride;
    const float* Bp2 = (MODE == 1) ? B2 + (size_t)e * N * Kstride : nullptr;

    const int Klen = Kstride / KSPLIT;
    const int koff = kh * Klen;

    const int tid = threadIdx.x;
    const int wid = tid >> 5, lane = tid & 31;
    const int g = lane >> 2, t4 = lane & 3;
    const int wm = (wid & 3) * 32, wn = (wid >> 2) * WN;

    const int rows_avail = cnt - bm - wm;
    const int mtact = (rows_avail >= 32) ? 2 : ((rows_avail <= 0) ? 0 : ((rows_avail + 15) >> 4));

    extern __shared__ char smc[];
    const uint32_t smU = smem_u32(smc);

    const int arow = tid >> 2;
    const int acol = (tid & 3) * 8;

    const float* aSrc = nullptr;
    const __half* aSrcH = nullptr;
    {
        if (MODE == 0) {
            int ridx = bm + arow; if (ridx >= M) ridx = M - 1;
            aSrc = A + (size_t)ridx * Kstride + acol + koff;
        } else if (MODE == 1) {
            int idx = bm + arow;
            int tok = (idx < cnt) ? g_tok[e * Tn + idx] : g_tok[e * Tn];
            aSrc = A + (size_t)tok * Kstride + acol + koff;
        } else {
            int idx = bm + arow;
            aSrcH = (const __half*)A + ((size_t)e * Tn + idx) * (size_t)Kstride + acol + koff;
        }
    }
    const uint32_t aSts = (uint32_t)(arow * PADH + acol) * 2u;

    const float* bSrc[NBB];
    uint32_t bSts[NBB];
#pragma unroll
    for (int j = 0; j < NBB; j++) {
        const int rowoff = (MODE == 2) ? j * 128 : 0;
        const float* base = (MODE == 1 && j == 1) ? Bp2 : Bp;
        const int moff = (MODE == 1 && j == 1) ? 1 : 0;
        bSrc[j] = base + (size_t)(bn + rowoff + arow) * Kstride + acol + koff;
        bSts[j] = (uint32_t)(A_HALFS + moff * B_HALFS + (rowoff + arow) * PADH + acol) * 2u;
    }

    const int l4 = lane >> 3, lr = lane & 7;
    uint32_t aAddr[2];
#pragma unroll
    for (int mt = 0; mt < 2; mt++) {
        int m_local = wm + mt * 16 + (l4 & 1) * 8 + lr;
        aAddr[mt] = smU + (uint32_t)(m_local * PADH) * 2u + (uint32_t)(l4 >> 1) * 16u;
    }
    uint32_t bAddr[NPAIR];
#pragma unroll
    for (int p = 0; p < NPAIR; p++) {
        int n_local = wn + p * 16 + (l4 >> 1) * 8 + lr;
        bAddr[p] = smU + (uint32_t)(A_HALFS + n_local * PADH) * 2u + (uint32_t)(l4 & 1) * 16u;
    }

    float acc[2][BNT][4];
    float acc2[MODE == 1 ? 2 : 1][MODE == 1 ? BNT : 1][4];
#pragma unroll
    for (int mt = 0; mt < 2; mt++)
#pragma unroll
        for (int nt = 0; nt < BNT; nt++)
#pragma unroll
            for (int q = 0; q < 4; q++) acc[mt][nt][q] = 0.f;
    if (MODE == 1) {
#pragma unroll
        for (int mt = 0; mt < 2; mt++)
#pragma unroll
            for (int nt = 0; nt < BNT; nt++)
#pragma unroll
                for (int q = 0; q < 4; q++) acc2[mt][nt][q] = 0.f;
    }

    float4 ra0, ra1;
    uint4 raH;
    float4 rb0[NBB], rb1[NBB];

#define LDG_STAGE(ktn)                                                   \
    do {                                                                 \
        const int k0 = (ktn) * 32;                                       \
        if (MODE == 2) {                                                 \
            raH = *(const uint4*)(aSrcH + k0);                           \
        } else {                                                         \
            ra0 = *(const float4*)(aSrc + k0);                           \
            ra1 = *(const float4*)(aSrc + k0 + 4);                       \
        }                                                                \
        _Pragma("unroll")                                                \
        for (int j = 0; j < NBB; j++) {                                  \
            rb0[j] = *(const float4*)(bSrc[j] + k0);                     \
            rb1[j] = *(const float4*)(bSrc[j] + k0 + 4);                 \
        }                                                                \
    } while (0)

#define STS_STAGE(ktn)                                                   \
    do {                                                                 \
        char* sb = smc + ((ktn) & 1) * STAGE_BYTES;                      \
        if (MODE == 2) *(uint4*)(sb + aSts) = raH;                       \
        else           *(uint4*)(sb + aSts) = cvt8(ra0, ra1);            \
        _Pragma("unroll")                                                \
        for (int j = 0; j < NBB; j++)                                    \
            *(uint4*)(sb + bSts[j]) = cvt8(rb0[j], rb1[j]);              \
    } while (0)

    const int KT = Klen / 32;

    LDG_STAGE(0);
    STS_STAGE(0);
    __syncthreads();
    LDG_STAGE(1);

    for (int kt = 0; kt < KT; kt++) {
        const uint32_t so = (uint32_t)(kt & 1) * STAGE_BYTES;
#pragma unroll
        for (int ks = 0; ks < 2; ks++) {
            const uint32_t kso = so + (uint32_t)ks * 32u;
            uint32_t af[2][4];
#pragma unroll
            for (int mt = 0; mt < 2; mt++)
                if (mt < mtact)
                    ldsm_x4(af[mt][0], af[mt][1], af[mt][2], af[mt][3], aAddr[mt] + kso);
            if (mtact > 0) {
                uint32_t bf[BNT][2];
#pragma unroll
                for (int p = 0; p < NPAIR; p++)
                    ldsm_x4(bf[2 * p][0], bf[2 * p][1], bf[2 * p + 1][0], bf[2 * p + 1][1],
                            bAddr[p] + kso);
#pragma unroll
                for (int mt = 0; mt < 2; mt++)
                    if (mt < mtact)
#pragma unroll
                        for (int nt = 0; nt < BNT; nt++)
                            mma_f16(acc[mt][nt], af[mt], bf[nt]);
                if (MODE == 1) {
                    uint32_t bg[BNT][2];
#pragma unroll
                    for (int p = 0; p < NPAIR; p++)
                        ldsm_x4(bg[2 * p][0], bg[2 * p][1], bg[2 * p + 1][0], bg[2 * p + 1][1],
                                bAddr[p] + (uint32_t)(B_HALFS * 2) + kso);
#pragma unroll
                    for (int mt = 0; mt < 2; mt++)
                        if (mt < mtact)
#pragma unroll
                            for (int nt = 0; nt < BNT; nt++)
                                mma_f16(acc2[mt][nt], af[mt], bg[nt]);
                }
            }
        }
        if (kt + 1 < KT) {
            STS_STAGE(kt + 1);
            if (kt + 2 < KT) LDG_STAGE(kt + 2);
            __syncthreads();
        }
    }
#undef LDG_STAGE
#undef STS_STAGE

#pragma unroll
    for (int mt = 0; mt < 2; mt++) {
        if (mt >= mtact) continue;
#pragma unroll
        for (int h = 0; h < 2; h++) {
            const int ridx = bm + wm + mt * 16 + g + h * 8;
            bool valid;
            float* dst = nullptr;
            __half* dsth = nullptr;
            float wg = 1.f;
            if (MODE == 0) {
                valid = ridx < M;
                if (valid) dst = C + (size_t)kh * M * N + (size_t)ridx * N;
            } else if (MODE == 1) {
                valid = ridx < cnt;
                if (valid) dsth = (__half*)C + ((size_t)e * Tn + ridx) * (size_t)N;
            } else {
                valid = ridx < cnt;
                if (valid) {
                    int idx = e * Tn + ridx;
                    int tok = g_tok[idx];
                    wg = g_wgt[idx];
                    int sl = g_slot[idx];
                    dst = C + ((size_t)tok * 4 + sl * 2 + kh) * (size_t)Dn;
                }
            }
            if (!valid) continue;
#pragma unroll
            for (int nt = 0; nt < BNT; nt++) {
                const int col = bn + wn + nt * 8 + 2 * t4;
                float2 v = make_float2(acc[mt][nt][h * 2 + 0], acc[mt][nt][h * 2 + 1]);
                if (MODE == 1) {
                    float b0 = acc2[mt][nt][h * 2 + 0];
                    float b1 = acc2[mt][nt][h * 2 + 1];
                    v.x = (v.x / (1.f + __expf(-v.x))) * b0;
                    v.y = (v.y / (1.f + __expf(-v.y))) * b1;
                    *(__half2*)(dsth + col) = __floats2half2_rn(v.x, v.y);
                } else {
                    if (MODE == 2) { v.x *= wg; v.y *= wg; }
                    *(float2*)(dst + col) = v;
                }
            }
        }
    }
}

// ================= attention: scores via fp16 MMA (fp16 output) =================
__global__ void __launch_bounds__(256, 1) k_scores_mma() {
    const int kt = blockIdx.x, qt = blockIdx.y, h = blockIdx.z;
    const int tid = threadIdx.x;
    const int wid = tid >> 5, lane = tid & 31;
    const int g = lane >> 2, t4 = lane & 3;
    const int wm = (wid & 3) * 32;
    const int wn = (wid >> 2) * 32;

    if (kt * 64 > qt * 128 + 127) {
        const __half2 neg = __floats2half2_rn(-60000.f, -60000.f);
#pragma unroll
        for (int mt = 0; mt < 2; mt++)
#pragma unroll
            for (int hh = 0; hh < 2; hh++) {
                int row = qt * 128 + wm + mt * 16 + g + hh * 8;
#pragma unroll
                for (int nt = 0; nt < 4; nt++) {
                    int col = kt * 64 + wn + nt * 8 + 2 * t4;
                    *(__half2*)&g_scoresh[((size_t)h * Tn + row) * Tn + col] = neg;
                }
            }
        return;
    }

    __shared__ __align__(16) __half Qs[128 * PADA];
    __shared__ __align__(16) __half Ks[64 * PADA];
    const uint32_t qU = smem_u32(Qs);
    const uint32_t kU = smem_u32(Ks);
    const int kvh = h >> 2;

    for (int idx = tid; idx < 128 * 8; idx += 256) {
        int row = idx >> 3, c8 = (idx & 7) * 8;
        const float* src = g_qkv + (size_t)(qt * 128 + row) * QKVn + h * 64 + c8;
        *(uint4*)((char*)Qs + (row * PADA + c8) * 2) =
            cvt8(*(const float4*)src, *(const float4*)(src + 4));
    }
    for (int idx = tid; idx < 64 * 8; idx += 256) {
        int row = idx >> 3, c8 = (idx & 7) * 8;
        const float* src = g_qkv + (size_t)(kt * 64 + row) * QKVn + 2048 + kvh * 64 + c8;
        *(uint4*)((char*)Ks + (row * PADA + c8) * 2) =
            cvt8(*(const float4*)src, *(const float4*)(src + 4));
    }
    __syncthreads();

    const int l4 = lane >> 3, lr = lane & 7;
    uint32_t aAddr[2], bAddr[2];
#pragma unroll
    for (int mt = 0; mt < 2; mt++) {
        int m_local = wm + mt * 16 + (l4 & 1) * 8 + lr;
        aAddr[mt] = qU + (uint32_t)(m_local * PADA) * 2u + (uint32_t)(l4 >> 1) * 16u;
    }
#pragma unroll
    for (int p = 0; p < 2; p++) {
        int n_local = wn + p * 16 + (l4 >> 1) * 8 + lr;
        bAddr[p] = kU + (uint32_t)(n_local * PADA) * 2u + (uint32_t)(l4 & 1) * 16u;
    }

    float acc[2][4][4];
#pragma unroll
    for (int mt = 0; mt < 2; mt++)
#pragma unroll
        for (int nt = 0; nt < 4; nt++)
#pragma unroll
            for (int q = 0; q < 4; q++) acc[mt][nt][q] = 0.f;

#pragma unroll
    for (int ks = 0; ks < 4; ks++) {
        const uint32_t kso = (uint32_t)ks * 32u;
        uint32_t af[2][4], bf[4][2];
#pragma unroll
        for (int mt = 0; mt < 2; mt++)
            ldsm_x4(af[mt][0], af[mt][1], af[mt][2], af[mt][3], aAddr[mt] + kso);
#pragma unroll
        for (int p = 0; p < 2; p++)
            ldsm_x4(bf[2 * p][0], bf[2 * p][1], bf[2 * p + 1][0], bf[2 * p + 1][1],
                    bAddr[p] + kso);
#pragma unroll
        for (int mt = 0; mt < 2; mt++)
#pragma unroll
            for (int nt = 0; nt < 4; nt++)
                mma_f16(acc[mt][nt], af[mt], bf[nt]);
    }

    const float scale = 0.125f;
#pragma unroll
    for (int mt = 0; mt < 2; mt++)
#pragma unroll
        for (int hh = 0; hh < 2; hh++) {
            int row = qt * 128 + wm + mt * 16 + g + hh * 8;
#pragma unroll
            for (int nt = 0; nt < 4; nt++) {
                int col = kt * 64 + wn + nt * 8 + 2 * t4;
                float v0 = (col     <= row) ? acc[mt][nt][hh * 2 + 0] * scale : -60000.f;
                float v1 = (col + 1 <= row) ? acc[mt][nt][hh * 2 + 1] * scale : -60000.f;
                *(__half2*)&g_scoresh[((size_t)h * Tn + row) * Tn + col] =
                    __floats2half2_rn(v0, v1);
            }
        }
}

// ================= attention: P@V via fp16 MMA =================
__global__ void __launch_bounds__(256, 1) k_attnv_mma() {
    const int qt = blockIdx.x, h = blockIdx.y;
    const int tid = threadIdx.x;
    const int wid = tid >> 5, lane = tid & 31;
    const int g = lane >> 2, t4 = lane & 3;
    const int wm = (wid & 3) * 32;
    const int wn = (wid >> 2) * 32;
    const int kvh = h >> 2;

    __shared__ __align__(16) __half Ps[128 * PADA];
    __shared__ __align__(16) __half Vs[64 * PADA];
    const uint32_t pU = smem_u32(Ps);
    const uint32_t vU = smem_u32(Vs);

    const int l4 = lane >> 3, lr = lane & 7;
    uint32_t aAddr[2];
#pragma unroll
    for (int mt = 0; mt < 2; mt++) {
        int m_local = wm + mt * 16 + (l4 & 1) * 8 + lr;
        aAddr[mt] = pU + (uint32_t)(m_local * PADA) * 2u + (uint32_t)(l4 >> 1) * 16u;
    }
    uint32_t bAddr[2];
#pragma unroll
    for (int p = 0; p < 2; p++) {
        int k_row = (l4 & 1) * 8 + lr;
        int dh_c = wn + p * 16 + (l4 >> 1) * 8;
        bAddr[p] = vU + (uint32_t)(k_row * PADA + dh_c) * 2u;
    }

    float acc[2][4][4];
#pragma unroll
    for (int mt = 0; mt < 2; mt++)
#pragma unroll
        for (int nt = 0; nt < 4; nt++)
#pragma unroll
            for (int q = 0; q < 4; q++) acc[mt][nt][q] = 0.f;

    const int ktmax = 2 * qt + 1;
    for (int kt = 0; kt <= ktmax; kt++) {
        // stage P (128 x 64) — already fp16, raw copy
        for (int idx = tid; idx < 128 * 8; idx += 256) {
            int row = idx >> 3, c8 = (idx & 7) * 8;
            const __half* src = &g_scoresh[((size_t)h * Tn + qt * 128 + row) * Tn + kt * 64 + c8];
            *(uint4*)((char*)Ps + (row * PADA + c8) * 2) = *(const uint4*)src;
        }
        // stage V (64 k x 64 dh) fp16
        for (int idx = tid; idx < 64 * 8; idx += 256) {
            int row = idx >> 3, c8 = (idx & 7) * 8;
            const float* src = g_qkv + (size_t)(kt * 64 + row) * QKVn + 2560 + kvh * 64 + c8;
            *(uint4*)((char*)Vs + (row * PADA + c8) * 2) =
                cvt8(*(const float4*)src, *(const float4*)(src + 4));
        }
        __syncthreads();

#pragma unroll
        for (int ks = 0; ks < 4; ks++) {
            uint32_t af[2][4], bf[4][2];
#pragma unroll
            for (int mt = 0; mt < 2; mt++)
                ldsm_x4(af[mt][0], af[mt][1], af[mt][2], af[mt][3],
                        aAddr[mt] + (uint32_t)ks * 32u);
#pragma unroll
            for (int p = 0; p < 2; p++)
                ldsm_x4_t(bf[2 * p][0], bf[2 * p][1], bf[2 * p + 1][0], bf[2 * p + 1][1],
                          bAddr[p] + (uint32_t)(ks * 16 * PADA) * 2u);
#pragma unroll
            for (int mt = 0; mt < 2; mt++)
#pragma unroll
                for (int nt = 0; nt < 4; nt++)
                    mma_f16(acc[mt][nt], af[mt], bf[nt]);
        }
        __syncthreads();
    }

#pragma unroll
    for (int mt = 0; mt < 2; mt++)
#pragma unroll
        for (int hh = 0; hh < 2; hh++) {
            int row = qt * 128 + wm + mt * 16 + g + hh * 8;
#pragma unroll
            for (int nt = 0; nt < 4; nt++) {
                int col = wn + nt * 8 + 2 * t4;
                float* p = &g_attn[(size_t)row * Dn + h * 64 + col];
                p[0] = acc[mt][nt][hh * 2 + 0];
                p[1] = acc[mt][nt][hh * 2 + 1];
            }
        }
}

// ---------------- small utility kernels ----------------

// res1 = h + r;  x = rmsnorm(res1, w); block 0 also zeroes g_cnt
__global__ void k_add_rmsnorm(const float* __restrict__ h, const float* __restrict__ r,
                              const float* __restrict__ w) {
    int t = blockIdx.x;
    if (t == 0 && threadIdx.x < En) g_cnt[threadIdx.x] = 0;
    const float* hr = h + t * Dn;
    const float* rr = r + t * Dn;
    float* resr = g_res1 + t * Dn;
    float* xr = g_x + t * Dn;

    float v[8];
    float local = 0.f;
#pragma unroll
    for (int j = 0; j < 8; j++) {
        int c = threadIdx.x + j * 256;
        float s = hr[c] + rr[c];
        v[j] = s;
        resr[c] = s;
        local += s * s;
    }
#pragma unroll
    for (int o = 16; o > 0; o >>= 1) local += __shfl_xor_sync(0xffffffffu, local, o);
    __shared__ float red[8];
    if ((threadIdx.x & 31) == 0) red[threadIdx.x >> 5] = local;
    __syncthreads();
    __shared__ float inv;
    if (threadIdx.x == 0) {
        float s = 0.f;
#pragma unroll
        for (int i = 0; i < 8; i++) s += red[i];
        inv = rsqrtf(s / (float)Dn + 1e-5f);
    }
    __syncthreads();
    float iv = inv;
#pragma unroll
    for (int j = 0; j < 8; j++) {
        int c = threadIdx.x + j * 256;
        xr[c] = v[j] * iv * w[c];
    }
}

// res2 = p0+p1+res1 -> out; x2 = rmsnorm(res2, ln2); gate top-2 routing (fused)
__global__ void k_add2_rmsnorm_gate(const float* __restrict__ p0, const float* __restrict__ p1,
                                    const float* __restrict__ w, float* __restrict__ res2out,
                                    const float* __restrict__ gw) {
    int t = blockIdx.x;
    const float* a0 = p0 + t * Dn;
    const float* a1 = p1 + t * Dn;
    const float* rr = g_res1 + t * Dn;
    float* ro = res2out + t * Dn;
    float* xr = g_x2 + t * Dn;
    __shared__ float xs[Dn];
    float v[8];
    float local = 0.f;
#pragma unroll
    for (int j = 0; j < 8; j++) {
        int c = threadIdx.x + j * 256;
        float s = a0[c] + a1[c] + rr[c];
        v[j] = s;
        ro[c] = s;
        local += s * s;
    }
#pragma unroll
    for (int o = 16; o > 0; o >>= 1) local += __shfl_xor_sync(0xffffffffu, local, o);
    __shared__ float red[8];
    if ((threadIdx.x & 31) == 0) red[threadIdx.x >> 5] = local;
    __syncthreads();
    __shared__ float inv;
    if (threadIdx.x == 0) {
        float s = 0.f;
#pragma unroll
        for (int i = 0; i < 8; i++) s += red[i];
        inv = rsqrtf(s / (float)Dn + 1e-5f);
    }
    __syncthreads();
    float iv = inv;
#pragma unroll
    for (int j = 0; j < 8; j++) {
        int c = threadIdx.x + j * 256;
        float xv = v[j] * iv * w[c];
        xr[c] = xv;
        xs[c] = xv;
    }
    __syncthreads();

    // gate: warp e computes logit e
    const int warp = threadIdx.x >> 5, lane = threadIdx.x & 31;
    const float* wr = gw + (size_t)warp * Dn;
    float s = 0.f;
    for (int c = lane; c < Dn; c += 32) s += xs[c] * wr[c];
#pragma unroll
    for (int o = 16; o > 0; o >>= 1) s += __shfl_xor_sync(0xffffffffu, s, o);
    __shared__ float lg[En];
    if (lane == 0) lg[warp] = s;
    __syncthreads();
    if (threadIdx.x == 0) {
        int i0 = 0;
        for (int e = 1; e < En; e++) if (lg[e] > lg[i0]) i0 = e;
        int i1 = (i0 == 0) ? 1 : 0;
        for (int e = 0; e < En; e++) if (e != i0 && lg[e] > lg[i1]) i1 = e;
        float w1v = __expf(lg[i1] - lg[i0]);
        float invw = 1.f / (1.f + w1v);
        float w0 = invw, w1n = w1v * invw;
        int pp0 = atomicAdd(&g_cnt[i0], 1);
        g_tok[i0 * Tn + pp0] = t; g_wgt[i0 * Tn + pp0] = w0; g_slot[i0 * Tn + pp0] = 0;
        int pp1 = atomicAdd(&g_cnt[i1], 1);
        g_tok[i1 * Tn + pp1] = t; g_wgt[i1 * Tn + pp1] = w1n; g_slot[i1 * Tn + pp1] = 1;
    }
}

__global__ void k_rope(const float* __restrict__ cosb, const float* __restrict__ sinb) {
    int idx = blockIdx.x * 256 + threadIdx.x;
    if (idx >= Tn * 40 * 32) return;
    int d = idx & 31;
    int rest = idx >> 5;
    int hh = rest % 40;
    int t = rest / 40;
    float c = cosb[t * 32 + d];
    float s = sinb[t * 32 + d];
    float* base = g_qkv + (size_t)t * QKVn + hh * 64 + d;
    float x1 = base[0];
    float x2 = base[32];
    base[0] = x1 * c - x2 * s;
    base[32] = x2 * c + x1 * s;
}

// softmax over fp16 scores row (512)
__global__ void k_softmax() {
    const int row = blockIdx.x;
    __half* p = g_scoresh + (size_t)row * Tn;
    const int tid = threadIdx.x;  // 128
    float v[4];
    float mx = -3.4e38f;
#pragma unroll
    for (int j = 0; j < 4; j++) {
        v[j] = __half2float(p[tid + j * 128]);
        mx = fmaxf(mx, v[j]);
    }
#pragma unroll
    for (int o = 16; o > 0; o >>= 1) mx = fmaxf(mx, __shfl_xor_sync(0xffffffffu, mx, o));
    __shared__ float rm[4];
    if ((tid & 31) == 0) rm[tid >> 5] = mx;
    __syncthreads();
    mx = fmaxf(fmaxf(rm[0], rm[1]), fmaxf(rm[2], rm[3]));
    float sum = 0.f;
#pragma unroll
    for (int j = 0; j < 4; j++) {
        v[j] = __expf(v[j] - mx);
        sum += v[j];
    }
#pragma unroll
    for (int o = 16; o > 0; o >>= 1) sum += __shfl_xor_sync(0xffffffffu, sum, o);
    __shared__ float rs[4];
    if ((tid & 31) == 0) rs[tid >> 5] = sum;
    __syncthreads();
    sum = rs[0] + rs[1] + rs[2] + rs[3];
    float inv = 1.f / sum;
#pragma unroll
    for (int j = 0; j < 4; j++) p[tid + j * 128] = __float2half(v[j] * inv);
}

// moe_out = sum of 4 eo slots (2 experts x 2 K-halves)
__global__ void k_combine(float* __restrict__ out) {
    int i = blockIdx.x * 256 + threadIdx.x;
    if (i >= Tn * Dn) return;
    int t = i / Dn;
    int d = i - t * Dn;
    const float* base = g_eo + (size_t)t * 4 * Dn + d;
    out[i] = base[0] + base[Dn] + base[2 * Dn] + base[3 * Dn];
}

// ---------------- launch ----------------
extern "C" void kernel_launch(void* const* d_in, const int* in_sizes, int n_in,
                              void* d_out, int out_size) {
    const float* hs   = (const float*)d_in[0];
    const float* resi = (const float*)d_in[1];
    const float* cosb = (const float*)d_in[2];
    const float* sinb = (const float*)d_in[3];
    const float* ln1  = (const float*)d_in[4];
    const float* ln2  = (const float*)d_in[5];
    const float* wqkv = (const float*)d_in[6];
    const float* wo   = (const float*)d_in[7];
    const float* gw   = (const float*)d_in[8];
    const float* w1   = (const float*)d_in[9];
    const float* w3   = (const float*)d_in[10];
    const float* w2   = (const float*)d_in[11];

    float* out = (float*)d_out;
    float* moe_out = out;
    float* res2 = out + Tn * Dn;

    void *px, *pqkv, *pattn, *px2, *ph1h, *peo;
    cudaGetSymbolAddress(&px, g_x);
    cudaGetSymbolAddress(&pqkv, g_qkv);
    cudaGetSymbolAddress(&pattn, g_attn);
    cudaGetSymbolAddress(&px2, g_x2);
    cudaGetSymbolAddress(&ph1h, g_h1h);
    cudaGetSymbolAddress(&peo, g_eo);

    constexpr int SMEM0 = 2 * (128 * PADH + 128 * PADH) * 2;       // 40960
    constexpr int SMEM1 = 2 * (128 * PADH + 2 * 128 * PADH) * 2;   // 61440
    constexpr int SMEM2 = 2 * (128 * PADH + 256 * PADH) * 2;       // 61440
    cudaFuncSetAttribute(k_gemm<0, 128, 1>, cudaFuncAttributeMaxDynamicSharedMemorySize, SMEM0);
    cudaFuncSetAttribute(k_gemm<0, 128, 2>, cudaFuncAttributeMaxDynamicSharedMemorySize, SMEM0);
    cudaFuncSetAttribute(k_gemm<1, 128, 1>, cudaFuncAttributeMaxDynamicSharedMemorySize, SMEM1);
    cudaFuncSetAttribute(k_gemm<2, 256, 2>, cudaFuncAttributeMaxDynamicSharedMemorySize, SMEM2);

    k_add_rmsnorm<<<Tn, 256>>>(hs, resi, ln1);

    // qkv direct: [512][3072] into g_qkv, then rope
    k_gemm<0, 128, 1><<<dim3(Tn / 128, QKVn / 128, 1), 512, SMEM0>>>(
        (const float*)px, wqkv, nullptr, (float*)pqkv, nullptr, Tn, QKVn, Dn);
    k_rope<<<(Tn * 40 * 32) / 256, 256>>>(cosb, sinb);

    k_scores_mma<<<dim3(Tn / 64, Tn / 128, Hn), 256>>>();
    k_softmax<<<Hn * Tn, 128>>>();
    k_attnv_mma<<<dim3(Tn / 128, Hn), 256>>>();

    // attn @ wo^T partials: [2][512][2048] into g_eo; fused add + rmsnorm + gate
    k_gemm<0, 128, 2><<<dim3(Tn / 128, Dn / 128, 2), 512, SMEM0>>>(
        (const float*)pattn, wo, nullptr, (float*)peo, nullptr, Tn, Dn, Dn);
    k_add2_rmsnorm_gate<<<Tn, 256>>>((const float*)peo, (const float*)peo + Tn * Dn,
                                     ln2, res2, gw);

    // fused dual-B grouped GEMM1: h1h = fp16( silu(x@w1^T) * (x@w3^T) )
    k_gemm<1, 128, 1><<<dim3(Tn / 128, In / 128, En), 512, SMEM1>>>(
        (const float*)px2, w1, w3, (float*)ph1h, nullptr, Tn, In, Dn);
    // w2 grouped GEMM (fp16 A), split-K2, scatter into 4-slot eo
    k_gemm<2, 256, 2><<<dim3(Tn / 128, Dn / 256, En * 2), 512, SMEM2>>>(
        (const float*)ph1h, w2, nullptr, (float*)peo, nullptr, Tn, Dn, In);
    k_combine<<<(Tn * Dn) / 256, 256>>>(moe_out);
}

// round 12
// speedup vs baseline: 12.3168x; 1.0369x over previous
#include <cuda_runtime.h>
#include <cuda_fp16.h>
#include <math.h>
#include <stdint.h>

#define Tn 512
#define Dn 2048
#define Hn 32
#define KVn 8
#define DHn 64
#define In 7168
#define En 8
#define QKVn 3072   // (H + 2*KV) * DH
#define PADH 40     // GEMM smem row stride in halfs
#define PADA 72     // attention smem row stride in halfs (64 data + 8 pad)

// ---------------- scratch (device globals; no allocation allowed) ----------------
__device__ __align__(16) float g_res1[Tn * Dn];
__device__ __align__(16) float g_x[Tn * Dn];
__device__ __align__(16) float g_qkv[Tn * QKVn];
__device__ __align__(16) float g_attn[Tn * Dn];
__device__ __align__(16) float g_x2[Tn * Dn];
__device__ __align__(16) __half g_h1h[En * Tn * In];
__device__ __align__(16) float g_eo[Tn * 4 * Dn];
__device__ int   g_tok[En * Tn];
__device__ float g_wgt[En * Tn];
__device__ int   g_slot[En * Tn];
__device__ int   g_cnt[En];

// ================= helpers (sm_80-level features only) =================
__device__ __forceinline__ uint32_t smem_u32(const void* p) {
    uint32_t a;
    asm("{ .reg .u64 t; cvta.to.shared.u64 t, %1; cvt.u32.u64 %0, t; }" : "=r"(a) : "l"(p));
    return a;
}
__device__ __forceinline__ uint32_t pack_h2(float x, float y) {
    __half2 h = __floats2half2_rn(x, y);
    return *reinterpret_cast<uint32_t*>(&h);
}
__device__ __forceinline__ uint4 cvt8(float4 a, float4 b) {
    uint4 u;
    u.x = pack_h2(a.x, a.y); u.y = pack_h2(a.z, a.w);
    u.z = pack_h2(b.x, b.y); u.w = pack_h2(b.z, b.w);
    return u;
}
__device__ __forceinline__ void mma_f16(float* c, const uint32_t* a, const uint32_t* b) {
    asm volatile(
        "mma.sync.aligned.m16n8k16.row.col.f32.f16.f16.f32 "
        "{%0,%1,%2,%3}, {%4,%5,%6,%7}, {%8,%9}, {%0,%1,%2,%3};"
        : "+f"(c[0]), "+f"(c[1]), "+f"(c[2]), "+f"(c[3])
        : "r"(a[0]), "r"(a[1]), "r"(a[2]), "r"(a[3]), "r"(b[0]), "r"(b[1]));
}
__device__ __forceinline__ void ldsm_x4(uint32_t& r0, uint32_t& r1, uint32_t& r2, uint32_t& r3,
                                        uint32_t addr) {
    asm volatile("ldmatrix.sync.aligned.m8n8.x4.shared.b16 {%0,%1,%2,%3}, [%4];"
                 : "=r"(r0), "=r"(r1), "=r"(r2), "=r"(r3) : "r"(addr));
}
__device__ __forceinline__ void ldsm_x4_t(uint32_t& r0, uint32_t& r1, uint32_t& r2, uint32_t& r3,
                                          uint32_t addr) {
    asm volatile("ldmatrix.sync.aligned.m8n8.x4.trans.shared.b16 {%0,%1,%2,%3}, [%4];"
                 : "=r"(r0), "=r"(r1), "=r"(r2), "=r"(r3) : "r"(addr));
}

// ================= fp16 tensor-core GEMM (unchanged from R11) =================
template <int MODE, int NT, int KSPLIT>
__global__ void __launch_bounds__(512, 1) k_gemm(const float* __restrict__ A,
                                                 const float* __restrict__ B,
                                                 const float* __restrict__ B2,
                                                 float* __restrict__ C,
                                                 float* __restrict__ C2,
                                                 int M, int N, int Kstride) {
    constexpr int BNT = NT / 32;
    constexpr int NPAIR = BNT / 2;
    constexpr int WN = NT / 4;
    constexpr int NB = (MODE == 1) ? 2 : 1;
    constexpr int NBB = (MODE == 1) ? 2 : (NT / 128);
    constexpr int A_HALFS = 128 * PADH;
    constexpr int B_HALFS = NT * PADH;
    constexpr int STAGE_HALFS = A_HALFS + NB * B_HALFS;
    constexpr int STAGE_BYTES = STAGE_HALFS * 2;

    const int kh = (MODE == 2) ? (int)(blockIdx.z & 1) : ((MODE == 0) ? (int)blockIdx.z : 0);
    const int e  = (MODE == 0) ? 0 : ((MODE == 2) ? (int)(blockIdx.z >> 1) : (int)blockIdx.z);
    const int cnt = (MODE == 0) ? M : g_cnt[e];
    const int bm = blockIdx.x * 128;
    if (bm >= cnt) return;
    const int bn = blockIdx.y * NT;

    const float* Bp  = (MODE == 0) ? B  : B  + (size_t)e * N * Kstride;
    const float* Bp2 = (MODE == 1) ? B2 + (size_t)e * N * Kstride : nullptr;

    const int Klen = Kstride / KSPLIT;
    const int koff = kh * Klen;

    const int tid = threadIdx.x;
    const int wid = tid >> 5, lane = tid & 31;
    const int g = lane >> 2, t4 = lane & 3;
    const int wm = (wid & 3) * 32, wn = (wid >> 2) * WN;

    const int rows_avail = cnt - bm - wm;
    const int mtact = (rows_avail >= 32) ? 2 : ((rows_avail <= 0) ? 0 : ((rows_avail + 15) >> 4));

    extern __shared__ char smc[];
    const uint32_t smU = smem_u32(smc);

    const int arow = tid >> 2;
    const int acol = (tid & 3) * 8;

    const float* aSrc = nullptr;
    const __half* aSrcH = nullptr;
    {
        if (MODE == 0) {
            int ridx = bm + arow; if (ridx >= M) ridx = M - 1;
            aSrc = A + (size_t)ridx * Kstride + acol + koff;
        } else if (MODE == 1) {
            int idx = bm + arow;
            int tok = (idx < cnt) ? g_tok[e * Tn + idx] : g_tok[e * Tn];
            aSrc = A + (size_t)tok * Kstride + acol + koff;
        } else {
            int idx = bm + arow;
            aSrcH = (const __half*)A + ((size_t)e * Tn + idx) * (size_t)Kstride + acol + koff;
        }
    }
    const uint32_t aSts = (uint32_t)(arow * PADH + acol) * 2u;

    const float* bSrc[NBB];
    uint32_t bSts[NBB];
#pragma unroll
    for (int j = 0; j < NBB; j++) {
        const int rowoff = (MODE == 2) ? j * 128 : 0;
        const float* base = (MODE == 1 && j == 1) ? Bp2 : Bp;
        const int moff = (MODE == 1 && j == 1) ? 1 : 0;
        bSrc[j] = base + (size_t)(bn + rowoff + arow) * Kstride + acol + koff;
        bSts[j] = (uint32_t)(A_HALFS + moff * B_HALFS + (rowoff + arow) * PADH + acol) * 2u;
    }

    const int l4 = lane >> 3, lr = lane & 7;
    uint32_t aAddr[2];
#pragma unroll
    for (int mt = 0; mt < 2; mt++) {
        int m_local = wm + mt * 16 + (l4 & 1) * 8 + lr;
        aAddr[mt] = smU + (uint32_t)(m_local * PADH) * 2u + (uint32_t)(l4 >> 1) * 16u;
    }
    uint32_t bAddr[NPAIR];
#pragma unroll
    for (int p = 0; p < NPAIR; p++) {
        int n_local = wn + p * 16 + (l4 >> 1) * 8 + lr;
        bAddr[p] = smU + (uint32_t)(A_HALFS + n_local * PADH) * 2u + (uint32_t)(l4 & 1) * 16u;
    }

    float acc[2][BNT][4];
    float acc2[MODE == 1 ? 2 : 1][MODE == 1 ? BNT : 1][4];
#pragma unroll
    for (int mt = 0; mt < 2; mt++)
#pragma unroll
        for (int nt = 0; nt < BNT; nt++)
#pragma unroll
            for (int q = 0; q < 4; q++) acc[mt][nt][q] = 0.f;
    if (MODE == 1) {
#pragma unroll
        for (int mt = 0; mt < 2; mt++)
#pragma unroll
            for (int nt = 0; nt < BNT; nt++)
#pragma unroll
                for (int q = 0; q < 4; q++) acc2[mt][nt][q] = 0.f;
    }

    float4 ra0, ra1;
    uint4 raH;
    float4 rb0[NBB], rb1[NBB];

#define LDG_STAGE(ktn)                                                   \
    do {                                                                 \
        const int k0 = (ktn) * 32;                                       \
        if (MODE == 2) {                                                 \
            raH = *(const uint4*)(aSrcH + k0);                           \
        } else {                                                         \
            ra0 = *(const float4*)(aSrc + k0);                           \
            ra1 = *(const float4*)(aSrc + k0 + 4);                       \
        }                                                                \
        _Pragma("unroll")                                                \
        for (int j = 0; j < NBB; j++) {                                  \
            rb0[j] = *(const float4*)(bSrc[j] + k0);                     \
            rb1[j] = *(const float4*)(bSrc[j] + k0 + 4);                 \
        }                                                                \
    } while (0)

#define STS_STAGE(ktn)                                                   \
    do {                                                                 \
        char* sb = smc + ((ktn) & 1) * STAGE_BYTES;                      \
        if (MODE == 2) *(uint4*)(sb + aSts) = raH;                       \
        else           *(uint4*)(sb + aSts) = cvt8(ra0, ra1);            \
        _Pragma("unroll")                                                \
        for (int j = 0; j < NBB; j++)                                    \
            *(uint4*)(sb + bSts[j]) = cvt8(rb0[j], rb1[j]);              \
    } while (0)

    const int KT = Klen / 32;

    LDG_STAGE(0);
    STS_STAGE(0);
    __syncthreads();
    LDG_STAGE(1);

    for (int kt = 0; kt < KT; kt++) {
        const uint32_t so = (uint32_t)(kt & 1) * STAGE_BYTES;
#pragma unroll
        for (int ks = 0; ks < 2; ks++) {
            const uint32_t kso = so + (uint32_t)ks * 32u;
            uint32_t af[2][4];
#pragma unroll
            for (int mt = 0; mt < 2; mt++)
                if (mt < mtact)
                    ldsm_x4(af[mt][0], af[mt][1], af[mt][2], af[mt][3], aAddr[mt] + kso);
            if (mtact > 0) {
                uint32_t bf[BNT][2];
#pragma unroll
                for (int p = 0; p < NPAIR; p++)
                    ldsm_x4(bf[2 * p][0], bf[2 * p][1], bf[2 * p + 1][0], bf[2 * p + 1][1],
                            bAddr[p] + kso);
#pragma unroll
                for (int mt = 0; mt < 2; mt++)
                    if (mt < mtact)
#pragma unroll
                        for (int nt = 0; nt < BNT; nt++)
                            mma_f16(acc[mt][nt], af[mt], bf[nt]);
                if (MODE == 1) {
                    uint32_t bg[BNT][2];
#pragma unroll
                    for (int p = 0; p < NPAIR; p++)
                        ldsm_x4(bg[2 * p][0], bg[2 * p][1], bg[2 * p + 1][0], bg[2 * p + 1][1],
                                bAddr[p] + (uint32_t)(B_HALFS * 2) + kso);
#pragma unroll
                    for (int mt = 0; mt < 2; mt++)
                        if (mt < mtact)
#pragma unroll
                            for (int nt = 0; nt < BNT; nt++)
                                mma_f16(acc2[mt][nt], af[mt], bg[nt]);
                }
            }
        }
        if (kt + 1 < KT) {
            STS_STAGE(kt + 1);
            if (kt + 2 < KT) LDG_STAGE(kt + 2);
            __syncthreads();
        }
    }
#undef LDG_STAGE
#undef STS_STAGE

#pragma unroll
    for (int mt = 0; mt < 2; mt++) {
        if (mt >= mtact) continue;
#pragma unroll
        for (int h = 0; h < 2; h++) {
            const int ridx = bm + wm + mt * 16 + g + h * 8;
            bool valid;
            float* dst = nullptr;
            __half* dsth = nullptr;
            float wg = 1.f;
            if (MODE == 0) {
                valid = ridx < M;
                if (valid) dst = C + (size_t)kh * M * N + (size_t)ridx * N;
            } else if (MODE == 1) {
                valid = ridx < cnt;
                if (valid) dsth = (__half*)C + ((size_t)e * Tn + ridx) * (size_t)N;
            } else {
                valid = ridx < cnt;
                if (valid) {
                    int idx = e * Tn + ridx;
                    int tok = g_tok[idx];
                    wg = g_wgt[idx];
                    int sl = g_slot[idx];
                    dst = C + ((size_t)tok * 4 + sl * 2 + kh) * (size_t)Dn;
                }
            }
            if (!valid) continue;
#pragma unroll
            for (int nt = 0; nt < BNT; nt++) {
                const int col = bn + wn + nt * 8 + 2 * t4;
                float2 v = make_float2(acc[mt][nt][h * 2 + 0], acc[mt][nt][h * 2 + 1]);
                if (MODE == 1) {
                    float b0 = acc2[mt][nt][h * 2 + 0];
                    float b1 = acc2[mt][nt][h * 2 + 1];
                    v.x = (v.x / (1.f + __expf(-v.x))) * b0;
                    v.y = (v.y / (1.f + __expf(-v.y))) * b1;
                    *(__half2*)(dsth + col) = __floats2half2_rn(v.x, v.y);
                } else {
                    if (MODE == 2) { v.x *= wg; v.y *= wg; }
                    *(float2*)(dst + col) = v;
                }
            }
        }
    }
}

// ================= flash attention: fused scores+softmax+PV =================
// CTA = (128 q-rows, head). 8 warps x 16 q-rows each (warp-local online softmax).
// P fragments come straight from score accumulators (no SMEM roundtrip).
__global__ void __launch_bounds__(256, 1) k_flash() {
    const int qt = blockIdx.x;    // 0..3
    const int h = blockIdx.y;
    const int tid = threadIdx.x;
    const int wid = tid >> 5, lane = tid & 31;
    const int g = lane >> 2, t4 = lane & 3;
    const int kvh = h >> 2;

    __shared__ __align__(16) __half Qs[128 * PADA];
    __shared__ __align__(16) __half Ks[64 * PADA];
    __shared__ __align__(16) __half Vs[64 * PADA];
    const uint32_t qU = smem_u32(Qs);
    const uint32_t kU = smem_u32(Ks);
    const uint32_t vU = smem_u32(Vs);

    // stage Q (128 x 64) fp16
    for (int idx = tid; idx < 128 * 8; idx += 256) {
        int row = idx >> 3, c8 = (idx & 7) * 8;
        const float* src = g_qkv + (size_t)(qt * 128 + row) * QKVn + h * 64 + c8;
        *(uint4*)((char*)Qs + (row * PADA + c8) * 2) =
            cvt8(*(const float4*)src, *(const float4*)(src + 4));
    }
    __syncthreads();

    const int l4 = lane >> 3, lr = lane & 7;
    // Q fragments: rows wid*16 .. wid*16+15, kept in registers for all kv steps
    uint32_t qf[4][4];
    {
        int m_local = wid * 16 + (l4 & 1) * 8 + lr;
        uint32_t qAddr = qU + (uint32_t)(m_local * PADA) * 2u + (uint32_t)(l4 >> 1) * 16u;
#pragma unroll
        for (int kc = 0; kc < 4; kc++)
            ldsm_x4(qf[kc][0], qf[kc][1], qf[kc][2], qf[kc][3], qAddr + (uint32_t)kc * 32u);
    }

    // K fragment addresses (n = kv position, 4 ldsm cover 64 cols)
    uint32_t kA[4];
#pragma unroll
    for (int p = 0; p < 4; p++) {
        int n_local = p * 16 + (l4 >> 1) * 8 + lr;
        kA[p] = kU + (uint32_t)(n_local * PADA) * 2u + (uint32_t)(l4 & 1) * 16u;
    }
    // V trans-ldmatrix addresses (dh 0..63)
    uint32_t vA[4];
#pragma unroll
    for (int p = 0; p < 4; p++) {
        int k_row = (l4 & 1) * 8 + lr;
        int dh_c = p * 16 + (l4 >> 1) * 8;
        vA[p] = vU + (uint32_t)(k_row * PADA + dh_c) * 2u;
    }

    float o[8][4];
#pragma unroll
    for (int dt = 0; dt < 8; dt++)
#pragma unroll
        for (int q = 0; q < 4; q++) o[dt][q] = 0.f;
    float mrow[2] = {-3.4e38f, -3.4e38f};
    float lrow[2] = {0.f, 0.f};

    const int row0 = qt * 128 + wid * 16 + g;   // thread rows: row0, row0+8
    const int ktmax = 2 * qt + 1;

    for (int kt = 0; kt <= ktmax; kt++) {
        // stage K, V tiles (64 x 64 each)
        for (int idx = tid; idx < 64 * 8; idx += 256) {
            int row = idx >> 3, c8 = (idx & 7) * 8;
            const float* srck = g_qkv + (size_t)(kt * 64 + row) * QKVn + 2048 + kvh * 64 + c8;
            *(uint4*)((char*)Ks + (row * PADA + c8) * 2) =
                cvt8(*(const float4*)srck, *(const float4*)(srck + 4));
            const float* srcv = g_qkv + (size_t)(kt * 64 + row) * QKVn + 2560 + kvh * 64 + c8;
            *(uint4*)((char*)Vs + (row * PADA + c8) * 2) =
                cvt8(*(const float4*)srcv, *(const float4*)(srcv + 4));
        }
        __syncthreads();

        // scores: 16 x 64 per warp
        float s[8][4];
#pragma unroll
        for (int nt = 0; nt < 8; nt++)
#pragma unroll
            for (int q = 0; q < 4; q++) s[nt][q] = 0.f;
#pragma unroll
        for (int kc = 0; kc < 4; kc++) {
            uint32_t bf[8][2];
#pragma unroll
            for (int p = 0; p < 4; p++)
                ldsm_x4(bf[2 * p][0], bf[2 * p][1], bf[2 * p + 1][0], bf[2 * p + 1][1],
                        kA[p] + (uint32_t)kc * 32u);
#pragma unroll
            for (int nt = 0; nt < 8; nt++)
                mma_f16(s[nt], qf[kc], bf[nt]);
        }

        // mask + scale + online softmax (rows warp-local; reduce over t4 quad)
        float mnew[2], alpha[2], lsum[2];
#pragma unroll
        for (int r = 0; r < 2; r++) {
            const int rown = row0 + r * 8;
            float mx = mrow[r];
#pragma unroll
            for (int nt = 0; nt < 8; nt++)
#pragma unroll
                for (int q = 0; q < 2; q++) {
                    int col = kt * 64 + nt * 8 + 2 * t4 + q;
                    float val = (col <= rown) ? s[nt][r * 2 + q] * 0.125f : -1e30f;
                    s[nt][r * 2 + q] = val;
                    mx = fmaxf(mx, val);
                }
            mx = fmaxf(mx, __shfl_xor_sync(0xffffffffu, mx, 1));
            mx = fmaxf(mx, __shfl_xor_sync(0xffffffffu, mx, 2));
            mnew[r] = mx;
            alpha[r] = __expf(mrow[r] - mx);
            float ls = 0.f;
#pragma unroll
            for (int nt = 0; nt < 8; nt++)
#pragma unroll
                for (int q = 0; q < 2; q++) {
                    float p = __expf(s[nt][r * 2 + q] - mx);
                    s[nt][r * 2 + q] = p;
                    ls += p;
                }
            ls += __shfl_xor_sync(0xffffffffu, ls, 1);
            ls += __shfl_xor_sync(0xffffffffu, ls, 2);
            lsum[r] = ls;
            lrow[r] = lrow[r] * alpha[r] + ls;
            mrow[r] = mx;
        }
        // rescale output accumulators
#pragma unroll
        for (int dt = 0; dt < 8; dt++) {
            o[dt][0] *= alpha[0]; o[dt][1] *= alpha[0];
            o[dt][2] *= alpha[1]; o[dt][3] *= alpha[1];
        }

        // P fragments directly from score accumulators
        uint32_t pf[4][4];
#pragma unroll
        for (int j = 0; j < 4; j++) {
            pf[j][0] = pack_h2(s[2 * j][0], s[2 * j][1]);
            pf[j][1] = pack_h2(s[2 * j][2], s[2 * j][3]);
            pf[j][2] = pack_h2(s[2 * j + 1][0], s[2 * j + 1][1]);
            pf[j][3] = pack_h2(s[2 * j + 1][2], s[2 * j + 1][3]);
        }
        // P @ V
#pragma unroll
        for (int j = 0; j < 4; j++) {
            uint32_t vf[8][2];
#pragma unroll
            for (int p = 0; p < 4; p++)
                ldsm_x4_t(vf[2 * p][0], vf[2 * p][1], vf[2 * p + 1][0], vf[2 * p + 1][1],
                          vA[p] + (uint32_t)(j * 16 * PADA) * 2u);
#pragma unroll
            for (int dt = 0; dt < 8; dt++)
                mma_f16(o[dt], pf[j], vf[dt]);
        }
        __syncthreads();
    }

    // epilogue: normalize and write
    float inv0 = 1.f / lrow[0];
    float inv1 = 1.f / lrow[1];
#pragma unroll
    for (int r = 0; r < 2; r++) {
        const int row = row0 + r * 8;
        float invr = r ? inv1 : inv0;
#pragma unroll
        for (int dt = 0; dt < 8; dt++) {
            int col = dt * 8 + 2 * t4;
            float* p = &g_attn[(size_t)row * Dn + h * 64 + col];
            p[0] = o[dt][r * 2 + 0] * invr;
            p[1] = o[dt][r * 2 + 1] * invr;
        }
    }
}

// ---------------- small utility kernels ----------------

__global__ void k_add_rmsnorm(const float* __restrict__ h, const float* __restrict__ r,
                              const float* __restrict__ w) {
    int t = blockIdx.x;
    if (t == 0 && threadIdx.x < En) g_cnt[threadIdx.x] = 0;
    const float* hr = h + t * Dn;
    const float* rr = r + t * Dn;
    float* resr = g_res1 + t * Dn;
    float* xr = g_x + t * Dn;

    float v[8];
    float local = 0.f;
#pragma unroll
    for (int j = 0; j < 8; j++) {
        int c = threadIdx.x + j * 256;
        float s = hr[c] + rr[c];
        v[j] = s;
        resr[c] = s;
        local += s * s;
    }
#pragma unroll
    for (int o = 16; o > 0; o >>= 1) local += __shfl_xor_sync(0xffffffffu, local, o);
    __shared__ float red[8];
    if ((threadIdx.x & 31) == 0) red[threadIdx.x >> 5] = local;
    __syncthreads();
    __shared__ float inv;
    if (threadIdx.x == 0) {
        float s = 0.f;
#pragma unroll
        for (int i = 0; i < 8; i++) s += red[i];
        inv = rsqrtf(s / (float)Dn + 1e-5f);
    }
    __syncthreads();
    float iv = inv;
#pragma unroll
    for (int j = 0; j < 8; j++) {
        int c = threadIdx.x + j * 256;
        xr[c] = v[j] * iv * w[c];
    }
}

__global__ void k_add2_rmsnorm_gate(const float* __restrict__ p0, const float* __restrict__ p1,
                                    const float* __restrict__ w, float* __restrict__ res2out,
                                    const float* __restrict__ gw) {
    int t = blockIdx.x;
    const float* a0 = p0 + t * Dn;
    const float* a1 = p1 + t * Dn;
    const float* rr = g_res1 + t * Dn;
    float* ro = res2out + t * Dn;
    float* xr = g_x2 + t * Dn;
    __shared__ float xs[Dn];
    float v[8];
    float local = 0.f;
#pragma unroll
    for (int j = 0; j < 8; j++) {
        int c = threadIdx.x + j * 256;
        float s = a0[c] + a1[c] + rr[c];
        v[j] = s;
        ro[c] = s;
        local += s * s;
    }
#pragma unroll
    for (int o = 16; o > 0; o >>= 1) local += __shfl_xor_sync(0xffffffffu, local, o);
    __shared__ float red[8];
    if ((threadIdx.x & 31) == 0) red[threadIdx.x >> 5] = local;
    __syncthreads();
    __shared__ float inv;
    if (threadIdx.x == 0) {
        float s = 0.f;
#pragma unroll
        for (int i = 0; i < 8; i++) s += red[i];
        inv = rsqrtf(s / (float)Dn + 1e-5f);
    }
    __syncthreads();
    float iv = inv;
#pragma unroll
    for (int j = 0; j < 8; j++) {
        int c = threadIdx.x + j * 256;
        float xv = v[j] * iv * w[c];
        xr[c] = xv;
        xs[c] = xv;
    }
    __syncthreads();

    const int warp = threadIdx.x >> 5, lane = threadIdx.x & 31;
    const float* wr = gw + (size_t)warp * Dn;
    float s = 0.f;
    for (int c = lane; c < Dn; c += 32) s += xs[c] * wr[c];
#pragma unroll
    for (int o = 16; o > 0; o >>= 1) s += __shfl_xor_sync(0xffffffffu, s, o);
    __shared__ float lg[En];
    if (lane == 0) lg[warp] = s;
    __syncthreads();
    if (threadIdx.x == 0) {
        int i0 = 0;
        for (int e = 1; e < En; e++) if (lg[e] > lg[i0]) i0 = e;
        int i1 = (i0 == 0) ? 1 : 0;
        for (int e = 0; e < En; e++) if (e != i0 && lg[e] > lg[i1]) i1 = e;
        float w1v = __expf(lg[i1] - lg[i0]);
        float invw = 1.f / (1.f + w1v);
        float w0 = invw, w1n = w1v * invw;
        int pp0 = atomicAdd(&g_cnt[i0], 1);
        g_tok[i0 * Tn + pp0] = t; g_wgt[i0 * Tn + pp0] = w0; g_slot[i0 * Tn + pp0] = 0;
        int pp1 = atomicAdd(&g_cnt[i1], 1);
        g_tok[i1 * Tn + pp1] = t; g_wgt[i1 * Tn + pp1] = w1n; g_slot[i1 * Tn + pp1] = 1;
    }
}

__global__ void k_rope(const float* __restrict__ cosb, const float* __restrict__ sinb) {
    int idx = blockIdx.x * 256 + threadIdx.x;
    if (idx >= Tn * 40 * 32) return;
    int d = idx & 31;
    int rest = idx >> 5;
    int hh = rest % 40;
    int t = rest / 40;
    float c = cosb[t * 32 + d];
    float s = sinb[t * 32 + d];
    float* base = g_qkv + (size_t)t * QKVn + hh * 64 + d;
    float x1 = base[0];
    float x2 = base[32];
    base[0] = x1 * c - x2 * s;
    base[32] = x2 * c + x1 * s;
}

__global__ void k_combine(float* __restrict__ out) {
    int i = blockIdx.x * 256 + threadIdx.x;
    if (i >= Tn * Dn) return;
    int t = i / Dn;
    int d = i - t * Dn;
    const float* base = g_eo + (size_t)t * 4 * Dn + d;
    out[i] = base[0] + base[Dn] + base[2 * Dn] + base[3 * Dn];
}

// ---------------- launch ----------------
extern "C" void kernel_launch(void* const* d_in, const int* in_sizes, int n_in,
                              void* d_out, int out_size) {
    const float* hs   = (const float*)d_in[0];
    const float* resi = (const float*)d_in[1];
    const float* cosb = (const float*)d_in[2];
    const float* sinb = (const float*)d_in[3];
    const float* ln1  = (const float*)d_in[4];
    const float* ln2  = (const float*)d_in[5];
    const float* wqkv = (const float*)d_in[6];
    const float* wo   = (const float*)d_in[7];
    const float* gw   = (const float*)d_in[8];
    const float* w1   = (const float*)d_in[9];
    const float* w3   = (const float*)d_in[10];
    const float* w2   = (const float*)d_in[11];

    float* out = (float*)d_out;
    float* moe_out = out;
    float* res2 = out + Tn * Dn;

    void *px, *pqkv, *pattn, *px2, *ph1h, *peo;
    cudaGetSymbolAddress(&px, g_x);
    cudaGetSymbolAddress(&pqkv, g_qkv);
    cudaGetSymbolAddress(&pattn, g_attn);
    cudaGetSymbolAddress(&px2, g_x2);
    cudaGetSymbolAddress(&ph1h, g_h1h);
    cudaGetSymbolAddress(&peo, g_eo);

    constexpr int SMEM0 = 2 * (128 * PADH + 128 * PADH) * 2;       // 40960
    constexpr int SMEM1 = 2 * (128 * PADH + 2 * 128 * PADH) * 2;   // 61440
    constexpr int SMEM2 = 2 * (128 * PADH + 256 * PADH) * 2;       // 61440
    cudaFuncSetAttribute(k_gemm<0, 128, 1>, cudaFuncAttributeMaxDynamicSharedMemorySize, SMEM0);
    cudaFuncSetAttribute(k_gemm<0, 128, 2>, cudaFuncAttributeMaxDynamicSharedMemorySize, SMEM0);
    cudaFuncSetAttribute(k_gemm<1, 128, 1>, cudaFuncAttributeMaxDynamicSharedMemorySize, SMEM1);
    cudaFuncSetAttribute(k_gemm<2, 256, 2>, cudaFuncAttributeMaxDynamicSharedMemorySize, SMEM2);

    k_add_rmsnorm<<<Tn, 256>>>(hs, resi, ln1);

    // qkv direct: [512][3072] into g_qkv, then rope
    k_gemm<0, 128, 1><<<dim3(Tn / 128, QKVn / 128, 1), 512, SMEM0>>>(
        (const float*)px, wqkv, nullptr, (float*)pqkv, nullptr, Tn, QKVn, Dn);
    k_rope<<<(Tn * 40 * 32) / 256, 256>>>(cosb, sinb);

    // fused flash attention (scores + softmax + P@V)
    k_flash<<<dim3(Tn / 128, Hn), 256>>>();

    // attn @ wo^T partials: [2][512][2048] into g_eo; fused add + rmsnorm + gate
    k_gemm<0, 128, 2><<<dim3(Tn / 128, Dn / 128, 2), 512, SMEM0>>>(
        (const float*)pattn, wo, nullptr, (float*)peo, nullptr, Tn, Dn, Dn);
    k_add2_rmsnorm_gate<<<Tn, 256>>>((const float*)peo, (const float*)peo + Tn * Dn,
                                     ln2, res2, gw);

    // fused dual-B grouped GEMM1: h1h = fp16( silu(x@w1^T) * (x@w3^T) )
    k_gemm<1, 128, 1><<<dim3(Tn / 128, In / 128, En), 512, SMEM1>>>(
        (const float*)px2, w1, w3, (float*)ph1h, nullptr, Tn, In, Dn);
    // w2 grouped GEMM (fp16 A), split-K2, scatter into 4-slot eo
    k_gemm<2, 256, 2><<<dim3(Tn / 128, Dn / 256, En * 2), 512, SMEM2>>>(
        (const float*)ph1h, w2, nullptr, (float*)peo, nullptr, Tn, Dn, In);
    k_combine<<<(Tn * Dn) / 256, 256>>>(moe_out);
}